// round 9
// baseline (speedup 1.0000x reference)
#include <cuda_runtime.h>
#include <math.h>

#define NN    50000
#define EE    8192
#define INDIM 256
#define HIDD  256
#define TDIM  32
#define MSGD  288   // INDIM + TDIM
#define G3H   768
#define EMBD  512

// ---------------- scratch (static device globals; no runtime allocation) ----
static __device__ __align__(128) float g_msg [EE * MSGD];
static __device__ __align__(128) float g_gi  [EE * G3H];
static __device__ __align__(128) float g_WhhT[HIDD * G3H];
static __device__ __align__(128) float g_mem [NN * HIDD];
static __device__ __align__(128) float g_emb [NN * EMBD];
static __device__ __align__(128) float g_buf0[NN * HIDD];
static __device__ __align__(128) float g_buf1[NN * HIDD];
static __device__ __align__(128) float g_qe  [EE * 512];
static __device__ __align__(128) float g_ke  [EE * 512];
static __device__ __align__(128) float g_ve  [EE * 512];
static __device__ float g_alpha[EE * 2];
static __device__ float g_ex   [EE * 2];
static __device__ float g_m    [NN * 2];
static __device__ float g_denom[NN * 2];
static __device__ int   g_chain_edge[EE];
static __device__ int   g_chain_dst [EE];
static __device__ int   g_is_head   [EE];

// ---------------- sort: single-block bitonic on 64-bit keys -----------------
// key = (dst << 45) | (time_bits << 13) | idx
// time in [0,1) -> float bits < 2^30, idx < 2^13, dst < 2^16: no overlap.
// Per-dst order = (time, original index) == JAX stable argsort restricted to dst.
__global__ void sort_kernel(const float* __restrict__ et, const int* __restrict__ ei) {
    extern __shared__ unsigned long long key[];
    const int n = EE;
    for (int i = threadIdx.x; i < n; i += blockDim.x) {
        unsigned long long tb = (unsigned long long)__float_as_uint(et[i]);
        unsigned long long d  = (unsigned long long)(unsigned)ei[EE + i];
        key[i] = (d << 45) | (tb << 13) | (unsigned long long)i;
    }
    __syncthreads();
    for (int k = 2; k <= n; k <<= 1) {
        for (int j = k >> 1; j > 0; j >>= 1) {
            for (int t = threadIdx.x; t < n; t += blockDim.x) {
                int ixj = t ^ j;
                if (ixj > t) {
                    unsigned long long a = key[t], b = key[ixj];
                    bool up = ((t & k) == 0);
                    if ((a > b) == up) { key[t] = b; key[ixj] = a; }
                }
            }
            __syncthreads();
        }
    }
    for (int i = threadIdx.x; i < n; i += blockDim.x) {
        unsigned long long kv = key[i];
        g_chain_edge[i] = (int)(kv & 0x1FFFULL);
        g_chain_dst[i]  = (int)(kv >> 45);
    }
    __syncthreads();
    for (int i = threadIdx.x; i < n; i += blockDim.x)
        g_is_head[i] = (i == 0) || (g_chain_dst[i] != g_chain_dst[i - 1]);
}

// ---------------- small helpers ---------------------------------------------
__global__ void msg_kernel(const float* __restrict__ x, const int* __restrict__ src,
                           const float* __restrict__ et, const float* __restrict__ tW,
                           const float* __restrict__ tb) {
    int e = blockIdx.x, c = threadIdx.x;
    float v;
    if (c < INDIM) v = x[(size_t)src[e] * INDIM + c];
    else { int cc = c - INDIM; v = fmaxf(fmaf(et[e], tW[cc], tb[cc]), 0.0f); }
    g_msg[(size_t)e * MSGD + c] = v;
}

__global__ void transpose_whh(const float* __restrict__ Whh) {
    int idx = blockIdx.x * 256 + threadIdx.x;
    if (idx < G3H * HIDD) {
        int j = idx / HIDD, i = idx % HIDD;
        g_WhhT[i * G3H + j] = Whh[idx];
    }
}

__global__ void copy_mem_kernel(const float* __restrict__ memin) {
    int idx = blockIdx.x * 256 + threadIdx.x;
    if (idx < NN * HIDD) g_mem[idx] = memin[idx];
}

__global__ void concat_kernel() {
    int idx = blockIdx.x * 256 + threadIdx.x;
    if (idx < NN * HIDD) {
        int n = idx / HIDD, c = idx % HIDD;
        g_emb[(size_t)n * EMBD + HIDD + c] = g_mem[idx];
    }
}

__global__ void init_md_kernel() {
    int idx = blockIdx.x * 256 + threadIdx.x;
    if (idx < NN * 2) {
        g_m[idx] = __int_as_float(0xff800000);  // -inf
        g_denom[idx] = 0.0f;
    }
}

__global__ void relu_kernel(float* __restrict__ buf, int n) {
    int idx = blockIdx.x * 256 + threadIdx.x;
    if (idx < n) buf[idx] = fmaxf(buf[idx], 0.0f);
}

// ---------------- GRU chains ------------------------------------------------
// One 256-thread block per chain head. Chain = consecutive sorted entries with
// the same dst, in (time, idx) order. Matvec with Whh^T skipped while h == 0
// (gh reduces to bhh), which removes ~92% of the matvecs for this workload
// while staying correct for arbitrary initial memory.
__global__ void __launch_bounds__(HIDD) gru_chain_kernel(const float* __restrict__ bhh) {
    int i0 = blockIdx.x;
    if (!g_is_head[i0]) return;
    int t = threadIdx.x;
    int d = g_chain_dst[i0];
    __shared__ float sh[HIDD];
    float h = g_mem[d * HIDD + t];
    sh[t] = h;
    int nz = __syncthreads_or(h != 0.0f);
    float b0 = bhh[t], b1 = bhh[HIDD + t], b2 = bhh[2 * HIDD + t];
    for (int i = i0; i < EE && g_chain_dst[i] == d; ++i) {
        int e = g_chain_edge[i];
        float gh0 = b0, gh1 = b1, gh2 = b2;
        if (nz) {
            #pragma unroll 4
            for (int kk = 0; kk < HIDD; ++kk) {
                float v = sh[kk];
                const float* wp = &g_WhhT[kk * G3H + t];
                gh0 += v * wp[0];
                gh1 += v * wp[HIDD];
                gh2 += v * wp[2 * HIDD];
            }
        }
        const float* gi = &g_gi[(size_t)e * G3H];
        float r  = 1.0f / (1.0f + expf(-(gi[t] + gh0)));
        float z  = 1.0f / (1.0f + expf(-(gi[HIDD + t] + gh1)));
        float nv = tanhf(gi[2 * HIDD + t] + r * gh2);
        float hn = (1.0f - z) * nv + z * h;
        __syncthreads();
        sh[t] = hn;
        h = hn;
        nz = __syncthreads_or(hn != 0.0f);
    }
    g_mem[d * HIDD + t] = h;
}

// ---------------- generic fp32 GEMM: C = act(gather(A) @ W^T + bias) --------
// W row-major [Ncols][K]. 64x64 block tile, 256 threads, 4x4 microtile,
// float4 smem loads (2x LDS.128 per 16 FFMA). K % 16 == 0, Ncols % 64 == 0.
#define BM 64
#define BN 64
#define BK 16
__global__ void __launch_bounds__(256) gemm_kernel(
    const float* __restrict__ A, int lda, const int* __restrict__ gather, int M,
    const float* __restrict__ W, int K, const float* __restrict__ bias,
    float* __restrict__ C, int ldc, int act)
{
    __shared__ float As[BK][BM + 4];
    __shared__ float Ws[BK][BN + 4];
    int tid = threadIdx.x;
    int tx = tid & 15, ty = tid >> 4;
    int lr = tid >> 2;
    int lk = (tid & 3) * 4;
    int arow = blockIdx.y * BM + lr;
    if (arow >= M) arow = M - 1;
    int ga = gather ? gather[arow] : arow;
    const float* Ab = A + (size_t)ga * lda;
    const float* Wb = W + (size_t)(blockIdx.x * BN + lr) * K;
    float acc[4][4];
    #pragma unroll
    for (int i = 0; i < 4; i++)
        #pragma unroll
        for (int j = 0; j < 4; j++) acc[i][j] = 0.0f;

    for (int k0 = 0; k0 < K; k0 += BK) {
        float4 av = *(const float4*)(Ab + k0 + lk);
        float4 wv = *(const float4*)(Wb + k0 + lk);
        As[lk + 0][lr] = av.x; As[lk + 1][lr] = av.y;
        As[lk + 2][lr] = av.z; As[lk + 3][lr] = av.w;
        Ws[lk + 0][lr] = wv.x; Ws[lk + 1][lr] = wv.y;
        Ws[lk + 2][lr] = wv.z; Ws[lk + 3][lr] = wv.w;
        __syncthreads();
        #pragma unroll
        for (int kk = 0; kk < BK; kk++) {
            float4 a = *(const float4*)&As[kk][ty * 4];
            float4 b = *(const float4*)&Ws[kk][tx * 4];
            acc[0][0] += a.x * b.x; acc[0][1] += a.x * b.y; acc[0][2] += a.x * b.z; acc[0][3] += a.x * b.w;
            acc[1][0] += a.y * b.x; acc[1][1] += a.y * b.y; acc[1][2] += a.y * b.z; acc[1][3] += a.y * b.w;
            acc[2][0] += a.z * b.x; acc[2][1] += a.z * b.y; acc[2][2] += a.z * b.z; acc[2][3] += a.z * b.w;
            acc[3][0] += a.w * b.x; acc[3][1] += a.w * b.y; acc[3][2] += a.w * b.z; acc[3][3] += a.w * b.w;
        }
        __syncthreads();
    }
    int cbase = blockIdx.x * BN + tx * 4;
    float bs0 = bias[cbase], bs1 = bias[cbase + 1], bs2 = bias[cbase + 2], bs3 = bias[cbase + 3];
    #pragma unroll
    for (int i = 0; i < 4; i++) {
        int r = blockIdx.y * BM + ty * 4 + i;
        if (r < M) {
            float* Cp = C + (size_t)r * ldc + cbase;
            float v0 = acc[i][0] + bs0, v1 = acc[i][1] + bs1;
            float v2 = acc[i][2] + bs2, v3 = acc[i][3] + bs3;
            if (act) { v0 = fmaxf(v0, 0.f); v1 = fmaxf(v1, 0.f); v2 = fmaxf(v2, 0.f); v3 = fmaxf(v3, 0.f); }
            Cp[0] = v0; Cp[1] = v1; Cp[2] = v2; Cp[3] = v3;
        }
    }
}

// ---------------- attention pieces ------------------------------------------
__device__ __forceinline__ void atomicMaxF(float* addr, float val) {
    int old = __float_as_int(*addr);
    while (__int_as_float(old) < val) {
        int assumed = old;
        old = atomicCAS((int*)addr, assumed, __float_as_int(val));
        if (old == assumed) break;
    }
}

__global__ void alpha_kernel(const float* __restrict__ qe, const float* __restrict__ ke,
                             const int* __restrict__ dst) {
    int e = blockIdx.x * 8 + (threadIdx.x >> 5);
    int lane = threadIdx.x & 31;
    const float* q = qe + (size_t)e * 512;
    const float* k = ke + (size_t)e * 512;
    float s0 = 0.f, s1 = 0.f;
    #pragma unroll
    for (int c = lane; c < 256; c += 32) {
        s0 = fmaf(q[c], k[c], s0);
        s1 = fmaf(q[256 + c], k[256 + c], s1);
    }
    #pragma unroll
    for (int o = 16; o > 0; o >>= 1) {
        s0 += __shfl_xor_sync(0xffffffffu, s0, o);
        s1 += __shfl_xor_sync(0xffffffffu, s1, o);
    }
    if (lane == 0) {
        const float scale = 0.0625f;  // 1/sqrt(256)
        float a0 = s0 * scale, a1 = s1 * scale;
        int d = dst[e];
        g_alpha[e * 2] = a0; g_alpha[e * 2 + 1] = a1;
        atomicMaxF(&g_m[d * 2], a0);
        atomicMaxF(&g_m[d * 2 + 1], a1);
    }
}

__global__ void ex_kernel(const int* __restrict__ dst) {
    int idx = blockIdx.x * 256 + threadIdx.x;
    if (idx < EE * 2) {
        int e = idx >> 1, h = idx & 1;
        int d = dst[e];
        float v = expf(g_alpha[idx] - g_m[d * 2 + h]);
        g_ex[idx] = v;
        atomicAdd(&g_denom[d * 2 + h], v);
    }
}

__global__ void scatter_kernel(const float* __restrict__ ve, const int* __restrict__ dst,
                               float* __restrict__ C) {
    int e = blockIdx.x, c = threadIdx.x;
    int d = dst[e];
    float w0 = g_ex[e * 2]     / g_denom[d * 2]     * 0.5f;
    float w1 = g_ex[e * 2 + 1] / g_denom[d * 2 + 1] * 0.5f;
    atomicAdd(&C[(size_t)d * HIDD + c],
              w0 * ve[(size_t)e * 512 + c] + w1 * ve[(size_t)e * 512 + 256 + c]);
}

// ---------------- launch ----------------------------------------------------
static void run_conv_layer(const float* xin, int lda, int K,
                           const float* qW, const float* qb,
                           const float* kW, const float* kb,
                           const float* vW, const float* vb,
                           const float* sW, const float* sb,
                           const int* src, const int* dst,
                           float* p_qe, float* p_ke, float* p_ve, float* outbuf)
{
    dim3 ge(512 / BN, EE / BM);
    gemm_kernel<<<ge, 256>>>(xin, lda, dst, EE, qW, K, qb, p_qe, 512, 0);
    gemm_kernel<<<ge, 256>>>(xin, lda, src, EE, kW, K, kb, p_ke, 512, 0);
    gemm_kernel<<<ge, 256>>>(xin, lda, src, EE, vW, K, vb, p_ve, 512, 0);
    dim3 gs(HIDD / BN, (NN + BM - 1) / BM);
    gemm_kernel<<<gs, 256>>>(xin, lda, nullptr, NN, sW, K, sb, outbuf, HIDD, 0);
    init_md_kernel<<<(NN * 2 + 255) / 256, 256>>>();
    alpha_kernel<<<EE / 8, 256>>>(p_qe, p_ke, dst);
    ex_kernel<<<(EE * 2 + 255) / 256, 256>>>(dst);
    scatter_kernel<<<EE, HIDD>>>(p_ve, dst, outbuf);
    relu_kernel<<<(NN * HIDD + 255) / 256, 256>>>(outbuf, NN * HIDD);
}

extern "C" void kernel_launch(void* const* d_in, const int* in_sizes, int n_in,
                              void* d_out, int out_size) {
    (void)in_sizes; (void)n_in; (void)out_size;
    const float* x      = (const float*)d_in[0];
    const int*   ei     = (const int*)  d_in[1];
    const float* et     = (const float*)d_in[2];
    const float* memin  = (const float*)d_in[3];
    const float* Wih    = (const float*)d_in[4];
    const float* Whh    = (const float*)d_in[5];
    const float* bih    = (const float*)d_in[6];
    const float* bhh    = (const float*)d_in[7];
    const float* timeW  = (const float*)d_in[8];
    const float* timeB  = (const float*)d_in[9];
    const float* featW  = (const float*)d_in[10];
    const float* featB  = (const float*)d_in[11];
    const float* c0_qW = (const float*)d_in[12]; const float* c0_qb = (const float*)d_in[13];
    const float* c0_kW = (const float*)d_in[14]; const float* c0_kb = (const float*)d_in[15];
    const float* c0_vW = (const float*)d_in[16]; const float* c0_vb = (const float*)d_in[17];
    const float* c0_sW = (const float*)d_in[18]; const float* c0_sb = (const float*)d_in[19];
    const float* c1_qW = (const float*)d_in[20]; const float* c1_qb = (const float*)d_in[21];
    const float* c1_kW = (const float*)d_in[22]; const float* c1_kb = (const float*)d_in[23];
    const float* c1_vW = (const float*)d_in[24]; const float* c1_vb = (const float*)d_in[25];
    const float* c1_sW = (const float*)d_in[26]; const float* c1_sb = (const float*)d_in[27];
    const float* clsW  = (const float*)d_in[28]; const float* clsB  = (const float*)d_in[29];
    float* out = (float*)d_out;

    const int* src = ei;
    const int* dst = ei + EE;

    float *p_msg, *p_gi, *p_mem, *p_emb, *p_buf0, *p_buf1, *p_qe, *p_ke, *p_ve;
    cudaGetSymbolAddress((void**)&p_msg,  g_msg);
    cudaGetSymbolAddress((void**)&p_gi,   g_gi);
    cudaGetSymbolAddress((void**)&p_mem,  g_mem);
    cudaGetSymbolAddress((void**)&p_emb,  g_emb);
    cudaGetSymbolAddress((void**)&p_buf0, g_buf0);
    cudaGetSymbolAddress((void**)&p_buf1, g_buf1);
    cudaGetSymbolAddress((void**)&p_qe,   g_qe);
    cudaGetSymbolAddress((void**)&p_ke,   g_ke);
    cudaGetSymbolAddress((void**)&p_ve,   g_ve);

    cudaFuncSetAttribute(sort_kernel, cudaFuncAttributeMaxDynamicSharedMemorySize, 65536);

    // 1) sort edges into per-dst time-ordered chains
    sort_kernel<<<1, 1024, 65536>>>(et, ei);

    // 2) gi = [x[src] | relu(time)] @ Wih^T + bih  (batched input half of GRU)
    msg_kernel<<<EE, MSGD>>>(x, src, et, timeW, timeB);
    gemm_kernel<<<dim3(G3H / BN, EE / BM), 256>>>(p_msg, MSGD, nullptr, EE,
                                                  Wih, MSGD, bih, p_gi, G3H, 0);

    // 3) GRU memory update (chains parallel over dst)
    transpose_whh<<<(G3H * HIDD + 255) / 256, 256>>>(Whh);
    copy_mem_kernel<<<(NN * HIDD + 255) / 256, 256>>>(memin);
    gru_chain_kernel<<<EE, HIDD>>>(bhh);

    // 4) emb = [relu(x @ featW^T + featB) | mem]
    gemm_kernel<<<dim3(INDIM / BN, (NN + BM - 1) / BM), 256>>>(
        x, INDIM, nullptr, NN, featW, INDIM, featB, p_emb, EMBD, 1);
    concat_kernel<<<(NN * HIDD + 255) / 256, 256>>>();

    // 5) two TransformerConv layers (Q/K/V per edge, skip for all nodes)
    run_conv_layer(p_emb, EMBD, EMBD, c0_qW, c0_qb, c0_kW, c0_kb, c0_vW, c0_vb,
                   c0_sW, c0_sb, src, dst, p_qe, p_ke, p_ve, p_buf0);
    run_conv_layer(p_buf0, HIDD, HIDD, c1_qW, c1_qb, c1_kW, c1_kb, c1_vW, c1_vb,
                   c1_sW, c1_sb, src, dst, p_qe, p_ke, p_ve, p_buf1);

    // 6) classifier
    gemm_kernel<<<dim3(1, (NN + BM - 1) / BM), 256>>>(
        p_buf1, HIDD, nullptr, NN, clsW, HIDD, clsB, out, 64, 0);
}

// round 10
// speedup vs baseline: 1.0006x; 1.0006x over previous
#include <cuda_runtime.h>
#include <math.h>

#define NN    50000
#define EE    8192
#define INDIM 256
#define HIDD  256
#define TDIM  32
#define MSGD  288   // INDIM + TDIM
#define G3H   768
#define EMBD  512

// ---------------- scratch (static device globals; no runtime allocation) ----
static __device__ __align__(128) float g_msg [EE * MSGD];
static __device__ __align__(128) float g_gi  [EE * G3H];
static __device__ __align__(128) float g_WhhT[HIDD * G3H];
static __device__ __align__(128) float g_mem [NN * HIDD];
static __device__ __align__(128) float g_emb [NN * EMBD];
static __device__ __align__(128) float g_buf0[NN * HIDD];
static __device__ __align__(128) float g_buf1[NN * HIDD];
static __device__ __align__(128) float g_qe  [EE * 512];
static __device__ __align__(128) float g_ke  [EE * 512];
static __device__ __align__(128) float g_ve  [EE * 512];
static __device__ float g_alpha[EE * 2];
static __device__ float g_ex   [EE * 2];
static __device__ float g_m    [NN * 2];
static __device__ float g_denom[NN * 2];
static __device__ int   g_chain_edge[EE];
static __device__ int   g_chain_dst [EE];
static __device__ int   g_is_head   [EE];

// ---------------- sort: single-block bitonic on 64-bit keys -----------------
// key = (dst << 45) | (time_bits << 13) | idx
// time in [0,1) -> float bits < 2^30, idx < 2^13, dst < 2^16: no overlap.
// Per-dst order = (time, original index) == JAX stable argsort restricted to dst.
__global__ void sort_kernel(const float* __restrict__ et, const int* __restrict__ ei) {
    extern __shared__ unsigned long long key[];
    const int n = EE;
    for (int i = threadIdx.x; i < n; i += blockDim.x) {
        unsigned long long tb = (unsigned long long)__float_as_uint(et[i]);
        unsigned long long d  = (unsigned long long)(unsigned)ei[EE + i];
        key[i] = (d << 45) | (tb << 13) | (unsigned long long)i;
    }
    __syncthreads();
    for (int k = 2; k <= n; k <<= 1) {
        for (int j = k >> 1; j > 0; j >>= 1) {
            for (int t = threadIdx.x; t < n; t += blockDim.x) {
                int ixj = t ^ j;
                if (ixj > t) {
                    unsigned long long a = key[t], b = key[ixj];
                    bool up = ((t & k) == 0);
                    if ((a > b) == up) { key[t] = b; key[ixj] = a; }
                }
            }
            __syncthreads();
        }
    }
    for (int i = threadIdx.x; i < n; i += blockDim.x) {
        unsigned long long kv = key[i];
        g_chain_edge[i] = (int)(kv & 0x1FFFULL);
        g_chain_dst[i]  = (int)(kv >> 45);
    }
    __syncthreads();
    for (int i = threadIdx.x; i < n; i += blockDim.x)
        g_is_head[i] = (i == 0) || (g_chain_dst[i] != g_chain_dst[i - 1]);
}

// ---------------- small helpers ---------------------------------------------
__global__ void msg_kernel(const float* __restrict__ x, const int* __restrict__ src,
                           const float* __restrict__ et, const float* __restrict__ tW,
                           const float* __restrict__ tb) {
    int e = blockIdx.x, c = threadIdx.x;
    float v;
    if (c < INDIM) v = x[(size_t)src[e] * INDIM + c];
    else { int cc = c - INDIM; v = fmaxf(fmaf(et[e], tW[cc], tb[cc]), 0.0f); }
    g_msg[(size_t)e * MSGD + c] = v;
}

__global__ void transpose_whh(const float* __restrict__ Whh) {
    int idx = blockIdx.x * 256 + threadIdx.x;
    if (idx < G3H * HIDD) {
        int j = idx / HIDD, i = idx % HIDD;
        g_WhhT[i * G3H + j] = Whh[idx];
    }
}

__global__ void copy_mem_kernel(const float* __restrict__ memin) {
    int idx = blockIdx.x * 256 + threadIdx.x;
    if (idx < NN * HIDD) g_mem[idx] = memin[idx];
}

__global__ void concat_kernel() {
    int idx = blockIdx.x * 256 + threadIdx.x;
    if (idx < NN * HIDD) {
        int n = idx / HIDD, c = idx % HIDD;
        g_emb[(size_t)n * EMBD + HIDD + c] = g_mem[idx];
    }
}

__global__ void init_md_kernel() {
    int idx = blockIdx.x * 256 + threadIdx.x;
    if (idx < NN * 2) {
        g_m[idx] = __int_as_float(0xff800000);  // -inf
        g_denom[idx] = 0.0f;
    }
}

__global__ void relu_kernel(float* __restrict__ buf, int n) {
    int idx = blockIdx.x * 256 + threadIdx.x;
    if (idx < n) buf[idx] = fmaxf(buf[idx], 0.0f);
}

// ---------------- GRU chains ------------------------------------------------
// One 256-thread block per chain head. Chain = consecutive sorted entries with
// the same dst, in (time, idx) order. Matvec with Whh^T skipped while h == 0
// (gh reduces to bhh), which removes ~92% of the matvecs for this workload
// while staying correct for arbitrary initial memory.
__global__ void __launch_bounds__(HIDD) gru_chain_kernel(const float* __restrict__ bhh) {
    int i0 = blockIdx.x;
    if (!g_is_head[i0]) return;
    int t = threadIdx.x;
    int d = g_chain_dst[i0];
    __shared__ float sh[HIDD];
    float h = g_mem[d * HIDD + t];
    sh[t] = h;
    int nz = __syncthreads_or(h != 0.0f);
    float b0 = bhh[t], b1 = bhh[HIDD + t], b2 = bhh[2 * HIDD + t];
    for (int i = i0; i < EE && g_chain_dst[i] == d; ++i) {
        int e = g_chain_edge[i];
        float gh0 = b0, gh1 = b1, gh2 = b2;
        if (nz) {
            #pragma unroll 4
            for (int kk = 0; kk < HIDD; ++kk) {
                float v = sh[kk];
                const float* wp = &g_WhhT[kk * G3H + t];
                gh0 += v * wp[0];
                gh1 += v * wp[HIDD];
                gh2 += v * wp[2 * HIDD];
            }
        }
        const float* gi = &g_gi[(size_t)e * G3H];
        float r  = 1.0f / (1.0f + expf(-(gi[t] + gh0)));
        float z  = 1.0f / (1.0f + expf(-(gi[HIDD + t] + gh1)));
        float nv = tanhf(gi[2 * HIDD + t] + r * gh2);
        float hn = (1.0f - z) * nv + z * h;
        __syncthreads();
        sh[t] = hn;
        h = hn;
        nz = __syncthreads_or(hn != 0.0f);
    }
    g_mem[d * HIDD + t] = h;
}

// ---------------- generic fp32 GEMM: C = act(gather(A) @ W^T + bias) --------
// W row-major [Ncols][K]. 64x64 block tile, 256 threads, 4x4 microtile,
// float4 smem loads (2x LDS.128 per 16 FFMA). K % 16 == 0, Ncols % 64 == 0.
#define BM 64
#define BN 64
#define BK 16
__global__ void __launch_bounds__(256) gemm_kernel(
    const float* __restrict__ A, int lda, const int* __restrict__ gather, int M,
    const float* __restrict__ W, int K, const float* __restrict__ bias,
    float* __restrict__ C, int ldc, int act)
{
    __shared__ float As[BK][BM + 4];
    __shared__ float Ws[BK][BN + 4];
    int tid = threadIdx.x;
    int tx = tid & 15, ty = tid >> 4;
    int lr = tid >> 2;
    int lk = (tid & 3) * 4;
    int arow = blockIdx.y * BM + lr;
    if (arow >= M) arow = M - 1;
    int ga = gather ? gather[arow] : arow;
    const float* Ab = A + (size_t)ga * lda;
    const float* Wb = W + (size_t)(blockIdx.x * BN + lr) * K;
    float acc[4][4];
    #pragma unroll
    for (int i = 0; i < 4; i++)
        #pragma unroll
        for (int j = 0; j < 4; j++) acc[i][j] = 0.0f;

    for (int k0 = 0; k0 < K; k0 += BK) {
        float4 av = *(const float4*)(Ab + k0 + lk);
        float4 wv = *(const float4*)(Wb + k0 + lk);
        As[lk + 0][lr] = av.x; As[lk + 1][lr] = av.y;
        As[lk + 2][lr] = av.z; As[lk + 3][lr] = av.w;
        Ws[lk + 0][lr] = wv.x; Ws[lk + 1][lr] = wv.y;
        Ws[lk + 2][lr] = wv.z; Ws[lk + 3][lr] = wv.w;
        __syncthreads();
        #pragma unroll
        for (int kk = 0; kk < BK; kk++) {
            float4 a = *(const float4*)&As[kk][ty * 4];
            float4 b = *(const float4*)&Ws[kk][tx * 4];
            acc[0][0] += a.x * b.x; acc[0][1] += a.x * b.y; acc[0][2] += a.x * b.z; acc[0][3] += a.x * b.w;
            acc[1][0] += a.y * b.x; acc[1][1] += a.y * b.y; acc[1][2] += a.y * b.z; acc[1][3] += a.y * b.w;
            acc[2][0] += a.z * b.x; acc[2][1] += a.z * b.y; acc[2][2] += a.z * b.z; acc[2][3] += a.z * b.w;
            acc[3][0] += a.w * b.x; acc[3][1] += a.w * b.y; acc[3][2] += a.w * b.z; acc[3][3] += a.w * b.w;
        }
        __syncthreads();
    }
    int cbase = blockIdx.x * BN + tx * 4;
    float bs0 = bias[cbase], bs1 = bias[cbase + 1], bs2 = bias[cbase + 2], bs3 = bias[cbase + 3];
    #pragma unroll
    for (int i = 0; i < 4; i++) {
        int r = blockIdx.y * BM + ty * 4 + i;
        if (r < M) {
            float* Cp = C + (size_t)r * ldc + cbase;
            float v0 = acc[i][0] + bs0, v1 = acc[i][1] + bs1;
            float v2 = acc[i][2] + bs2, v3 = acc[i][3] + bs3;
            if (act) { v0 = fmaxf(v0, 0.f); v1 = fmaxf(v1, 0.f); v2 = fmaxf(v2, 0.f); v3 = fmaxf(v3, 0.f); }
            Cp[0] = v0; Cp[1] = v1; Cp[2] = v2; Cp[3] = v3;
        }
    }
}

// ---------------- attention pieces ------------------------------------------
__device__ __forceinline__ void atomicMaxF(float* addr, float val) {
    int old = __float_as_int(*addr);
    while (__int_as_float(old) < val) {
        int assumed = old;
        old = atomicCAS((int*)addr, assumed, __float_as_int(val));
        if (old == assumed) break;
    }
}

__global__ void alpha_kernel(const float* __restrict__ qe, const float* __restrict__ ke,
                             const int* __restrict__ dst) {
    int e = blockIdx.x * 8 + (threadIdx.x >> 5);
    int lane = threadIdx.x & 31;
    const float* q = qe + (size_t)e * 512;
    const float* k = ke + (size_t)e * 512;
    float s0 = 0.f, s1 = 0.f;
    #pragma unroll
    for (int c = lane; c < 256; c += 32) {
        s0 = fmaf(q[c], k[c], s0);
        s1 = fmaf(q[256 + c], k[256 + c], s1);
    }
    #pragma unroll
    for (int o = 16; o > 0; o >>= 1) {
        s0 += __shfl_xor_sync(0xffffffffu, s0, o);
        s1 += __shfl_xor_sync(0xffffffffu, s1, o);
    }
    if (lane == 0) {
        const float scale = 0.0625f;  // 1/sqrt(256)
        float a0 = s0 * scale, a1 = s1 * scale;
        int d = dst[e];
        g_alpha[e * 2] = a0; g_alpha[e * 2 + 1] = a1;
        atomicMaxF(&g_m[d * 2], a0);
        atomicMaxF(&g_m[d * 2 + 1], a1);
    }
}

__global__ void ex_kernel(const int* __restrict__ dst) {
    int idx = blockIdx.x * 256 + threadIdx.x;
    if (idx < EE * 2) {
        int e = idx >> 1, h = idx & 1;
        int d = dst[e];
        float v = expf(g_alpha[idx] - g_m[d * 2 + h]);
        g_ex[idx] = v;
        atomicAdd(&g_denom[d * 2 + h], v);
    }
}

__global__ void scatter_kernel(const float* __restrict__ ve, const int* __restrict__ dst,
                               float* __restrict__ C) {
    int e = blockIdx.x, c = threadIdx.x;
    int d = dst[e];
    float w0 = g_ex[e * 2]     / g_denom[d * 2]     * 0.5f;
    float w1 = g_ex[e * 2 + 1] / g_denom[d * 2 + 1] * 0.5f;
    atomicAdd(&C[(size_t)d * HIDD + c],
              w0 * ve[(size_t)e * 512 + c] + w1 * ve[(size_t)e * 512 + 256 + c]);
}

// ---------------- launch ----------------------------------------------------
static void run_conv_layer(const float* xin, int lda, int K,
                           const float* qW, const float* qb,
                           const float* kW, const float* kb,
                           const float* vW, const float* vb,
                           const float* sW, const float* sb,
                           const int* src, const int* dst,
                           float* p_qe, float* p_ke, float* p_ve, float* outbuf)
{
    dim3 ge(512 / BN, EE / BM);
    gemm_kernel<<<ge, 256>>>(xin, lda, dst, EE, qW, K, qb, p_qe, 512, 0);
    gemm_kernel<<<ge, 256>>>(xin, lda, src, EE, kW, K, kb, p_ke, 512, 0);
    gemm_kernel<<<ge, 256>>>(xin, lda, src, EE, vW, K, vb, p_ve, 512, 0);
    dim3 gs(HIDD / BN, (NN + BM - 1) / BM);
    gemm_kernel<<<gs, 256>>>(xin, lda, nullptr, NN, sW, K, sb, outbuf, HIDD, 0);
    init_md_kernel<<<(NN * 2 + 255) / 256, 256>>>();
    alpha_kernel<<<EE / 8, 256>>>(p_qe, p_ke, dst);
    ex_kernel<<<(EE * 2 + 255) / 256, 256>>>(dst);
    scatter_kernel<<<EE, HIDD>>>(p_ve, dst, outbuf);
    relu_kernel<<<(NN * HIDD + 255) / 256, 256>>>(outbuf, NN * HIDD);
}

extern "C" void kernel_launch(void* const* d_in, const int* in_sizes, int n_in,
                              void* d_out, int out_size) {
    (void)in_sizes; (void)n_in; (void)out_size;
    const float* x      = (const float*)d_in[0];
    const int*   ei     = (const int*)  d_in[1];
    const float* et     = (const float*)d_in[2];
    const float* memin  = (const float*)d_in[3];
    const float* Wih    = (const float*)d_in[4];
    const float* Whh    = (const float*)d_in[5];
    const float* bih    = (const float*)d_in[6];
    const float* bhh    = (const float*)d_in[7];
    const float* timeW  = (const float*)d_in[8];
    const float* timeB  = (const float*)d_in[9];
    const float* featW  = (const float*)d_in[10];
    const float* featB  = (const float*)d_in[11];
    const float* c0_qW = (const float*)d_in[12]; const float* c0_qb = (const float*)d_in[13];
    const float* c0_kW = (const float*)d_in[14]; const float* c0_kb = (const float*)d_in[15];
    const float* c0_vW = (const float*)d_in[16]; const float* c0_vb = (const float*)d_in[17];
    const float* c0_sW = (const float*)d_in[18]; const float* c0_sb = (const float*)d_in[19];
    const float* c1_qW = (const float*)d_in[20]; const float* c1_qb = (const float*)d_in[21];
    const float* c1_kW = (const float*)d_in[22]; const float* c1_kb = (const float*)d_in[23];
    const float* c1_vW = (const float*)d_in[24]; const float* c1_vb = (const float*)d_in[25];
    const float* c1_sW = (const float*)d_in[26]; const float* c1_sb = (const float*)d_in[27];
    const float* clsW  = (const float*)d_in[28]; const float* clsB  = (const float*)d_in[29];
    float* out = (float*)d_out;

    const int* src = ei;
    const int* dst = ei + EE;

    float *p_msg, *p_gi, *p_mem, *p_emb, *p_buf0, *p_buf1, *p_qe, *p_ke, *p_ve;
    cudaGetSymbolAddress((void**)&p_msg,  g_msg);
    cudaGetSymbolAddress((void**)&p_gi,   g_gi);
    cudaGetSymbolAddress((void**)&p_mem,  g_mem);
    cudaGetSymbolAddress((void**)&p_emb,  g_emb);
    cudaGetSymbolAddress((void**)&p_buf0, g_buf0);
    cudaGetSymbolAddress((void**)&p_buf1, g_buf1);
    cudaGetSymbolAddress((void**)&p_qe,   g_qe);
    cudaGetSymbolAddress((void**)&p_ke,   g_ke);
    cudaGetSymbolAddress((void**)&p_ve,   g_ve);

    cudaFuncSetAttribute(sort_kernel, cudaFuncAttributeMaxDynamicSharedMemorySize, 65536);

    // 1) sort edges into per-dst time-ordered chains
    sort_kernel<<<1, 1024, 65536>>>(et, ei);

    // 2) gi = [x[src] | relu(time)] @ Wih^T + bih  (batched input half of GRU)
    msg_kernel<<<EE, MSGD>>>(x, src, et, timeW, timeB);
    gemm_kernel<<<dim3(G3H / BN, EE / BM), 256>>>(p_msg, MSGD, nullptr, EE,
                                                  Wih, MSGD, bih, p_gi, G3H, 0);

    // 3) GRU memory update (chains parallel over dst)
    transpose_whh<<<(G3H * HIDD + 255) / 256, 256>>>(Whh);
    copy_mem_kernel<<<(NN * HIDD + 255) / 256, 256>>>(memin);
    gru_chain_kernel<<<EE, HIDD>>>(bhh);

    // 4) emb = [relu(x @ featW^T + featB) | mem]
    gemm_kernel<<<dim3(INDIM / BN, (NN + BM - 1) / BM), 256>>>(
        x, INDIM, nullptr, NN, featW, INDIM, featB, p_emb, EMBD, 1);
    concat_kernel<<<(NN * HIDD + 255) / 256, 256>>>();

    // 5) two TransformerConv layers (Q/K/V per edge, skip for all nodes)
    run_conv_layer(p_emb, EMBD, EMBD, c0_qW, c0_qb, c0_kW, c0_kb, c0_vW, c0_vb,
                   c0_sW, c0_sb, src, dst, p_qe, p_ke, p_ve, p_buf0);
    run_conv_layer(p_buf0, HIDD, HIDD, c1_qW, c1_qb, c1_kW, c1_kb, c1_vW, c1_vb,
                   c1_sW, c1_sb, src, dst, p_qe, p_ke, p_ve, p_buf1);

    // 6) classifier
    gemm_kernel<<<dim3(1, (NN + BM - 1) / BM), 256>>>(
        p_buf1, HIDD, nullptr, NN, clsW, HIDD, clsB, out, 64, 0);
}

// round 12
// speedup vs baseline: 1.5375x; 1.5366x over previous
#include <cuda_runtime.h>
#include <cuda_bf16.h>
#include <math.h>
#include <stdint.h>

#define NN    50000
#define EE    8192
#define INDIM 256
#define HIDD  256
#define MSGD  288
#define KPADM 320   // MSGD padded to multiple of 64
#define G3H   768
#define EMBD  512

// ---------------- scratch (static device globals; no runtime allocation) ----
static __device__ __align__(128) float g_msg [EE * MSGD];
static __device__ __align__(128) float g_gi  [EE * G3H];
static __device__ __align__(128) float g_WhhT[HIDD * G3H];
static __device__ __align__(128) float g_mem [NN * HIDD];
static __device__ __align__(128) float g_emb [NN * EMBD];
static __device__ __align__(128) float g_buf0[NN * HIDD];
static __device__ __align__(128) float g_buf1[NN * HIDD];
static __device__ __align__(128) float g_qe  [EE * 512];
static __device__ __align__(128) float g_ke  [EE * 512];
static __device__ __align__(128) float g_ve  [EE * 512];
static __device__ __align__(256) __nv_bfloat16 g_apair[(size_t)NN * 1024];
static __device__ __align__(256) __nv_bfloat16 g_wpair[3407872];
static __device__ float g_alpha[EE * 2];
static __device__ float g_ex   [EE * 2];
static __device__ float g_m    [NN * 2];
static __device__ float g_denom[NN * 2];
static __device__ int   g_chain_edge[EE];
static __device__ int   g_chain_dst [EE];
static __device__ int   g_is_head   [EE];

// weight-pair arena offsets (bf16 elements; each W[N][K] -> pair [N][2K])
#define OFF_WIH  0u          // 768 x 640
#define OFF_FEAT 491520u     // 256 x 512
#define OFF_Q0   622592u     // 512 x 1024
#define OFF_K0   1146880u
#define OFF_V0   1671168u
#define OFF_S0   2195456u    // 256 x 1024
#define OFF_Q1   2457600u    // 512 x 512
#define OFF_K1   2719744u
#define OFF_V1   2981888u
#define OFF_S1   3244032u    // 256 x 512
#define OFF_CLS  3375104u    // 64 x 512

// ---------------- helpers ----------------------------------------------------
__device__ __forceinline__ uint32_t smem_u32(const void* p) {
    uint32_t a;
    asm("{ .reg .u64 t; cvta.to.shared.u64 t, %1; cvt.u32.u64 %0, t; }" : "=r"(a) : "l"(p));
    return a;
}

#define LDM4(r, addr) \
    asm volatile("ldmatrix.sync.aligned.m8n8.x4.shared.b16 {%0,%1,%2,%3}, [%4];" \
        : "=r"((r)[0]), "=r"((r)[1]), "=r"((r)[2]), "=r"((r)[3]) : "r"(addr))

#define MMA16816(c, a, b) \
    asm volatile("mma.sync.aligned.m16n8k16.row.col.f32.bf16.bf16.f32 " \
        "{%0,%1,%2,%3}, {%4,%5,%6,%7}, {%8,%9}, {%0,%1,%2,%3};" \
        : "+f"((c)[0]), "+f"((c)[1]), "+f"((c)[2]), "+f"((c)[3]) \
        : "r"((a)[0]), "r"((a)[1]), "r"((a)[2]), "r"((a)[3]), \
          "r"((b)[0]), "r"((b)[1]))

#define CPASYNC16(saddr, gptr) \
    asm volatile("cp.async.ca.shared.global [%0], [%1], 16;" \
        :: "r"(saddr), "l"(gptr) : "memory")

// ---------------- split-bf16 conversion (interleaved per-64 layout) ----------
// Logical element k of a row: group kk=k/64, pos=k%64.
//   hi -> out[row*2K + kk*128 + pos], lo -> out[row*2K + kk*128 + 64 + pos]
// So a 128-column chunk [kk*128, kk*128+128) holds hi|lo of k in [kk*64, kk*64+64).
__global__ void cvt_pair(const float* __restrict__ in, __nv_bfloat16* __restrict__ out,
                         int rows, int incols, int K) {
    long long total = (long long)rows * K;
    long long i = (long long)blockIdx.x * blockDim.x + threadIdx.x;
    if (i >= total) return;
    int r = (int)(i / K), k = (int)(i - (long long)r * K);
    float v = (k < incols) ? in[(size_t)r * incols + k] : 0.0f;
    __nv_bfloat16 h = __float2bfloat16(v);
    __nv_bfloat16 l = __float2bfloat16(v - __bfloat162float(h));
    size_t rb = (size_t)r * 2 * K + (size_t)(k >> 6) * 128 + (k & 63);
    out[rb] = h;
    out[rb + 64] = l;
}

// ---------------- HMMA split-bf16 GEMM ---------------------------------------
// C[M, Ncols] = act( gather(A_pair) @ W_pair^T + bias ), fp32 accum in regs.
// Per 64-k chunk, staged tile holds hi|lo (256B rows); compute hi*hi + lo*hi +
// hi*lo (drop lo*lo, ~2^-16 relative). CTA tile 128 x NTILE, 512 threads.
template<int NTILE, int ACT>
__global__ void __launch_bounds__(512, 1)
mma_gemm(const __nv_bfloat16* __restrict__ A, int K2, const int* __restrict__ gather,
         int M, const __nv_bfloat16* __restrict__ W, const float* __restrict__ bias,
         float* __restrict__ C, int ldc, int K)
{
    constexpr int NWN = (NTILE >= 256) ? 4 : 2;   // warps along N
    constexpr int WN  = NTILE / NWN;              // 64 / 32
    constexpr int NF  = WN / 8;                   // 8 / 4
    constexpr int NWM = 16 / NWN;                 // 4 / 8
    constexpr int WM  = 128 / NWM;                // 32 / 16
    constexpr int MF  = WM / 16;                  // 2 / 1
    constexpr int ASZ = 128 * 256;                // 32KB A stage
    constexpr int WSZ = NTILE * 256;
    constexpr int STAGE = ASZ + WSZ;

    extern __shared__ char dsm[];
    __shared__ int s_grow[128];
    char* tb = (char*)(((uintptr_t)dsm + 1023) & ~(uintptr_t)1023);
    const uint32_t sbase = smem_u32(tb);
    const int tid = threadIdx.x, wid = tid >> 5, lane = tid & 31;
    const int wm = (wid / NWN) * WM, wn = (wid % NWN) * WN;
    const int wrow0 = blockIdx.x * NTILE;

    if (tid < 128) {
        int r = blockIdx.y * 128 + tid;
        if (r >= M) r = M - 1;
        s_grow[tid] = (gather ? gather[r] : r) * K2;
    }
    __syncthreads();

    float cacc[MF][NF][4];
    #pragma unroll
    for (int mf = 0; mf < MF; mf++)
        #pragma unroll
        for (int nf = 0; nf < NF; nf++)
            #pragma unroll
            for (int q = 0; q < 4; q++) cacc[mf][nf][q] = 0.0f;

    const int nch = K / 64;

    // ---- stage loader (cp.async, SW-swizzled 256B rows) ----
    #define LOAD_STAGE(s_, kk_) do { \
        uint32_t sa_ = sbase + (s_) * STAGE; \
        int coff_ = (kk_) * 128; \
        _Pragma("unroll") \
        for (int v = tid; v < 2048; v += 512) { \
            int row = v >> 4, j = v & 15; \
            const __nv_bfloat16* g = A + s_grow[row] + coff_ + j * 8; \
            uint32_t ad = sa_ + row * 256 + ((j ^ (row & 7)) << 4); \
            CPASYNC16(ad, g); \
        } \
        uint32_t sw_ = sa_ + ASZ; \
        _Pragma("unroll") \
        for (int v = tid; v < NTILE * 16; v += 512) { \
            int row = v >> 4, j = v & 15; \
            const __nv_bfloat16* g = W + (size_t)(wrow0 + row) * K2 + coff_ + j * 8; \
            uint32_t ad = sw_ + row * 256 + ((j ^ (row & 7)) << 4); \
            CPASYNC16(ad, g); \
        } \
        asm volatile("cp.async.commit_group;" ::: "memory"); \
    } while (0)

    LOAD_STAGE(0, 0);

    for (int c = 0; c < nch; c++) {
        int s = c & 1;
        if (c + 1 < nch) {
            LOAD_STAGE(s ^ 1, c + 1);
            asm volatile("cp.async.wait_group 1;" ::: "memory");
        } else {
            asm volatile("cp.async.wait_group 0;" ::: "memory");
        }
        __syncthreads();

        uint32_t sa = sbase + s * STAGE, sw = sa + ASZ;
        const int arow = lane & 15;
        const int brow = (lane & 7) + ((lane >> 4) << 3);
        #pragma unroll
        for (int ks = 0; ks < 4; ks++) {
            uint32_t ah[MF][4], al[MF][4];
            #pragma unroll
            for (int mf = 0; mf < MF; mf++) {
                int row = wm + mf * 16 + arow;
                int sl = ks * 2 + (lane >> 4);
                LDM4(ah[mf], sa + row * 256 + ((sl ^ (row & 7)) << 4));
                LDM4(al[mf], sa + row * 256 + (((sl + 8) ^ (row & 7)) << 4));
            }
            uint32_t b[NF * 2];
            // W-hi: terms hi*hi and lo*hi
            #pragma unroll
            for (int p = 0; p < NF / 2; p++) {
                int row = wn + p * 16 + brow;
                int sl = ks * 2 + ((lane >> 3) & 1);
                LDM4(&b[p * 4], sw + row * 256 + ((sl ^ (row & 7)) << 4));
            }
            #pragma unroll
            for (int mf = 0; mf < MF; mf++)
                #pragma unroll
                for (int nf = 0; nf < NF; nf++) {
                    MMA16816(cacc[mf][nf], ah[mf], &b[nf * 2]);
                    MMA16816(cacc[mf][nf], al[mf], &b[nf * 2]);
                }
            // W-lo: term hi*lo
            #pragma unroll
            for (int p = 0; p < NF / 2; p++) {
                int row = wn + p * 16 + brow;
                int sl = 8 + ks * 2 + ((lane >> 3) & 1);
                LDM4(&b[p * 4], sw + row * 256 + ((sl ^ (row & 7)) << 4));
            }
            #pragma unroll
            for (int mf = 0; mf < MF; mf++)
                #pragma unroll
                for (int nf = 0; nf < NF; nf++)
                    MMA16816(cacc[mf][nf], ah[mf], &b[nf * 2]);
        }
        __syncthreads();
    }

    // ---- epilogue: bias + act, direct float2 stores ----
    #pragma unroll
    for (int mf = 0; mf < MF; mf++) {
        int r0 = blockIdx.y * 128 + wm + mf * 16 + (lane >> 2);
        #pragma unroll
        for (int nf = 0; nf < NF; nf++) {
            int col = wrow0 + wn + nf * 8 + (lane & 3) * 2;
            float b0 = bias[col], b1 = bias[col + 1];
            float v0 = cacc[mf][nf][0] + b0, v1 = cacc[mf][nf][1] + b1;
            float v2 = cacc[mf][nf][2] + b0, v3 = cacc[mf][nf][3] + b1;
            if (ACT) {
                v0 = fmaxf(v0, 0.f); v1 = fmaxf(v1, 0.f);
                v2 = fmaxf(v2, 0.f); v3 = fmaxf(v3, 0.f);
            }
            if (r0 < M)     *(float2*)&C[(size_t)r0 * ldc + col]       = make_float2(v0, v1);
            if (r0 + 8 < M) *(float2*)&C[(size_t)(r0 + 8) * ldc + col] = make_float2(v2, v3);
        }
    }
    #undef LOAD_STAGE
}

// ---------------- sort: single-block bitonic on 64-bit keys -----------------
__global__ void sort_kernel(const float* __restrict__ et, const int* __restrict__ ei) {
    extern __shared__ unsigned long long key[];
    const int n = EE;
    for (int i = threadIdx.x; i < n; i += blockDim.x) {
        unsigned long long tbits = (unsigned long long)__float_as_uint(et[i]);
        unsigned long long d = (unsigned long long)(unsigned)ei[EE + i];
        key[i] = (d << 45) | (tbits << 13) | (unsigned long long)i;
    }
    __syncthreads();
    for (int k = 2; k <= n; k <<= 1)
        for (int j = k >> 1; j > 0; j >>= 1) {
            for (int t = threadIdx.x; t < n; t += blockDim.x) {
                int ixj = t ^ j;
                if (ixj > t) {
                    unsigned long long a = key[t], b = key[ixj];
                    bool up = ((t & k) == 0);
                    if ((a > b) == up) { key[t] = b; key[ixj] = a; }
                }
            }
            __syncthreads();
        }
    for (int i = threadIdx.x; i < n; i += blockDim.x) {
        unsigned long long kv = key[i];
        g_chain_edge[i] = (int)(kv & 0x1FFFULL);
        g_chain_dst[i]  = (int)(kv >> 45);
    }
    __syncthreads();
    for (int i = threadIdx.x; i < n; i += blockDim.x)
        g_is_head[i] = (i == 0) || (g_chain_dst[i] != g_chain_dst[i - 1]);
}

// ---------------- small helpers ---------------------------------------------
__global__ void msg_kernel(const float* __restrict__ x, const int* __restrict__ src,
                           const float* __restrict__ et, const float* __restrict__ tW,
                           const float* __restrict__ tb) {
    int e = blockIdx.x, c = threadIdx.x;
    float v;
    if (c < INDIM) v = x[(size_t)src[e] * INDIM + c];
    else { int cc = c - INDIM; v = fmaxf(fmaf(et[e], tW[cc], tb[cc]), 0.0f); }
    g_msg[(size_t)e * MSGD + c] = v;
}

__global__ void transpose_whh(const float* __restrict__ Whh) {
    int idx = blockIdx.x * 256 + threadIdx.x;
    if (idx < G3H * HIDD) {
        int j = idx / HIDD, i = idx % HIDD;
        g_WhhT[i * G3H + j] = Whh[idx];
    }
}

__global__ void copy_mem_kernel(const float* __restrict__ memin) {
    int idx = blockIdx.x * 256 + threadIdx.x;
    if (idx < NN * HIDD) g_mem[idx] = memin[idx];
}

__global__ void concat_kernel() {
    int idx = blockIdx.x * 256 + threadIdx.x;
    if (idx < NN * HIDD) {
        int n = idx / HIDD, c = idx % HIDD;
        g_emb[(size_t)n * EMBD + HIDD + c] = g_mem[idx];
    }
}

__global__ void init_md_kernel() {
    int idx = blockIdx.x * 256 + threadIdx.x;
    if (idx < NN * 2) { g_m[idx] = __int_as_float(0xff800000); g_denom[idx] = 0.0f; }
}

__global__ void relu_kernel(float* __restrict__ buf, int n) {
    int idx = blockIdx.x * 256 + threadIdx.x;
    if (idx < n) buf[idx] = fmaxf(buf[idx], 0.0f);
}

// ---------------- GRU chains ------------------------------------------------
__global__ void __launch_bounds__(HIDD) gru_chain_kernel(const float* __restrict__ bhh) {
    int i0 = blockIdx.x;
    if (!g_is_head[i0]) return;
    int t = threadIdx.x;
    int d = g_chain_dst[i0];
    __shared__ float sh[HIDD];
    float h = g_mem[d * HIDD + t];
    sh[t] = h;
    int nz = __syncthreads_or(h != 0.0f);
    float b0 = bhh[t], b1 = bhh[HIDD + t], b2 = bhh[2 * HIDD + t];
    for (int i = i0; i < EE && g_chain_dst[i] == d; ++i) {
        int e = g_chain_edge[i];
        float gh0 = b0, gh1 = b1, gh2 = b2;
        if (nz) {
            #pragma unroll 4
            for (int kk = 0; kk < HIDD; ++kk) {
                float v = sh[kk];
                const float* wp = &g_WhhT[kk * G3H + t];
                gh0 += v * wp[0];
                gh1 += v * wp[HIDD];
                gh2 += v * wp[2 * HIDD];
            }
        }
        const float* gi = &g_gi[(size_t)e * G3H];
        float r  = 1.0f / (1.0f + expf(-(gi[t] + gh0)));
        float z  = 1.0f / (1.0f + expf(-(gi[HIDD + t] + gh1)));
        float nv = tanhf(gi[2 * HIDD + t] + r * gh2);
        float hn = (1.0f - z) * nv + z * h;
        __syncthreads();
        sh[t] = hn;
        h = hn;
        nz = __syncthreads_or(hn != 0.0f);
    }
    g_mem[d * HIDD + t] = h;
}

// ---------------- attention pieces ------------------------------------------
__device__ __forceinline__ void atomicMaxF(float* addr, float val) {
    int old = __float_as_int(*addr);
    while (__int_as_float(old) < val) {
        int assumed = old;
        old = atomicCAS((int*)addr, assumed, __float_as_int(val));
        if (old == assumed) break;
    }
}

__global__ void alpha_kernel(const float* __restrict__ qe, const float* __restrict__ ke,
                             const int* __restrict__ dst) {
    int e = blockIdx.x * 8 + (threadIdx.x >> 5);
    int lane = threadIdx.x & 31;
    const float* q = qe + (size_t)e * 512;
    const float* k = ke + (size_t)e * 512;
    float s0 = 0.f, s1 = 0.f;
    #pragma unroll
    for (int c = lane; c < 256; c += 32) {
        s0 = fmaf(q[c], k[c], s0);
        s1 = fmaf(q[256 + c], k[256 + c], s1);
    }
    #pragma unroll
    for (int o = 16; o > 0; o >>= 1) {
        s0 += __shfl_xor_sync(0xffffffffu, s0, o);
        s1 += __shfl_xor_sync(0xffffffffu, s1, o);
    }
    if (lane == 0) {
        const float scale = 0.0625f;
        float a0 = s0 * scale, a1 = s1 * scale;
        int d = dst[e];
        g_alpha[e * 2] = a0; g_alpha[e * 2 + 1] = a1;
        atomicMaxF(&g_m[d * 2], a0);
        atomicMaxF(&g_m[d * 2 + 1], a1);
    }
}

__global__ void ex_kernel(const int* __restrict__ dst) {
    int idx = blockIdx.x * 256 + threadIdx.x;
    if (idx < EE * 2) {
        int e = idx >> 1, h = idx & 1;
        int d = dst[e];
        float v = expf(g_alpha[idx] - g_m[d * 2 + h]);
        g_ex[idx] = v;
        atomicAdd(&g_denom[d * 2 + h], v);
    }
}

__global__ void scatter_kernel(const float* __restrict__ ve, const int* __restrict__ dst,
                               float* __restrict__ C) {
    int e = blockIdx.x, c = threadIdx.x;
    int d = dst[e];
    float w0 = g_ex[e * 2]     / g_denom[d * 2]     * 0.5f;
    float w1 = g_ex[e * 2 + 1] / g_denom[d * 2 + 1] * 0.5f;
    atomicAdd(&C[(size_t)d * HIDD + c],
              w0 * ve[(size_t)e * 512 + c] + w1 * ve[(size_t)e * 512 + 256 + c]);
}

// ---------------- host ------------------------------------------------------
#define SMA256 197632   // 1024 slack + 2 * (32KB A + 64KB W)
#define SMA64  99328    // 1024 slack + 2 * (32KB A + 16KB W)

static void run_conv_layer_t(const __nv_bfloat16* apair, int K2, int K,
                             const __nv_bfloat16* wp,
                             const float* qb, const float* kb, const float* vb,
                             const float* sb,
                             size_t oq, size_t ok, size_t ov, size_t os,
                             const int* src, const int* dst,
                             float* p_qe, float* p_ke, float* p_ve, float* outbuf)
{
    dim3 ge(2, EE / 128);
    mma_gemm<256, 0><<<ge, 512, SMA256>>>(apair, K2, dst, EE, wp + oq, qb, p_qe, 512, K);
    mma_gemm<256, 0><<<ge, 512, SMA256>>>(apair, K2, src, EE, wp + ok, kb, p_ke, 512, K);
    mma_gemm<256, 0><<<ge, 512, SMA256>>>(apair, K2, src, EE, wp + ov, vb, p_ve, 512, K);
    mma_gemm<256, 0><<<dim3(1, (NN + 127) / 128), 512, SMA256>>>(
        apair, K2, nullptr, NN, wp + os, sb, outbuf, HIDD, K);
    init_md_kernel<<<(NN * 2 + 255) / 256, 256>>>();
    alpha_kernel<<<EE / 8, 256>>>(p_qe, p_ke, dst);
    ex_kernel<<<(EE * 2 + 255) / 256, 256>>>(dst);
    scatter_kernel<<<EE, HIDD>>>(p_ve, dst, outbuf);
    relu_kernel<<<(NN * HIDD + 255) / 256, 256>>>(outbuf, NN * HIDD);
}

extern "C" void kernel_launch(void* const* d_in, const int* in_sizes, int n_in,
                              void* d_out, int out_size) {
    (void)in_sizes; (void)n_in; (void)out_size;
    const float* x     = (const float*)d_in[0];
    const int*   ei    = (const int*)  d_in[1];
    const float* et    = (const float*)d_in[2];
    const float* memin = (const float*)d_in[3];
    const float* Wih   = (const float*)d_in[4];
    const float* Whh   = (const float*)d_in[5];
    const float* bih   = (const float*)d_in[6];
    const float* bhh   = (const float*)d_in[7];
    const float* timeW = (const float*)d_in[8];
    const float* timeB = (const float*)d_in[9];
    const float* featW = (const float*)d_in[10];
    const float* featB = (const float*)d_in[11];
    const float* c0_qW = (const float*)d_in[12]; const float* c0_qb = (const float*)d_in[13];
    const float* c0_kW = (const float*)d_in[14]; const float* c0_kb = (const float*)d_in[15];
    const float* c0_vW = (const float*)d_in[16]; const float* c0_vb = (const float*)d_in[17];
    const float* c0_sW = (const float*)d_in[18]; const float* c0_sb = (const float*)d_in[19];
    const float* c1_qW = (const float*)d_in[20]; const float* c1_qb = (const float*)d_in[21];
    const float* c1_kW = (const float*)d_in[22]; const float* c1_kb = (const float*)d_in[23];
    const float* c1_vW = (const float*)d_in[24]; const float* c1_vb = (const float*)d_in[25];
    const float* c1_sW = (const float*)d_in[26]; const float* c1_sb = (const float*)d_in[27];
    const float* clsW  = (const float*)d_in[28]; const float* clsB  = (const float*)d_in[29];
    float* out = (float*)d_out;

    const int* src = ei;
    const int* dst = ei + EE;

    float *p_msg, *p_gi, *p_emb, *p_buf0, *p_buf1, *p_qe, *p_ke, *p_ve;
    __nv_bfloat16 *p_ap, *p_wp;
    cudaGetSymbolAddress((void**)&p_msg,  g_msg);
    cudaGetSymbolAddress((void**)&p_gi,   g_gi);
    cudaGetSymbolAddress((void**)&p_emb,  g_emb);
    cudaGetSymbolAddress((void**)&p_buf0, g_buf0);
    cudaGetSymbolAddress((void**)&p_buf1, g_buf1);
    cudaGetSymbolAddress((void**)&p_qe,   g_qe);
    cudaGetSymbolAddress((void**)&p_ke,   g_ke);
    cudaGetSymbolAddress((void**)&p_ve,   g_ve);
    cudaGetSymbolAddress((void**)&p_ap,   g_apair);
    cudaGetSymbolAddress((void**)&p_wp,   g_wpair);

    cudaFuncSetAttribute(sort_kernel, cudaFuncAttributeMaxDynamicSharedMemorySize, 65536);
    cudaFuncSetAttribute(mma_gemm<256, 0>, cudaFuncAttributeMaxDynamicSharedMemorySize, SMA256);
    cudaFuncSetAttribute(mma_gemm<256, 1>, cudaFuncAttributeMaxDynamicSharedMemorySize, SMA256);
    cudaFuncSetAttribute(mma_gemm<64, 0>,  cudaFuncAttributeMaxDynamicSharedMemorySize, SMA64);

    // 0) split-bf16 weight pairs (interleaved hi|lo per 64-group)
    #define CVW(W_, rows_, incols_, K_, off_) \
        cvt_pair<<<(int)(((long long)(rows_) * (K_) + 255) / 256), 256>>>( \
            W_, p_wp + (off_), rows_, incols_, K_)
    CVW(Wih,   768, MSGD, KPADM, OFF_WIH);
    CVW(featW, 256, 256,  256,   OFF_FEAT);
    CVW(c0_qW, 512, 512,  512,   OFF_Q0);
    CVW(c0_kW, 512, 512,  512,   OFF_K0);
    CVW(c0_vW, 512, 512,  512,   OFF_V0);
    CVW(c0_sW, 256, 512,  512,   OFF_S0);
    CVW(c1_qW, 512, 256,  256,   OFF_Q1);
    CVW(c1_kW, 512, 256,  256,   OFF_K1);
    CVW(c1_vW, 512, 256,  256,   OFF_V1);
    CVW(c1_sW, 256, 256,  256,   OFF_S1);
    CVW(clsW,  64,  256,  256,   OFF_CLS);

    // 1) sort edges into per-dst time-ordered chains
    sort_kernel<<<1, 1024, 65536>>>(et, ei);

    // 2) gi = [x[src] | relu(time)] @ Wih^T + bih  via split-bf16 HMMA
    msg_kernel<<<EE, MSGD>>>(x, src, et, timeW, timeB);
    cvt_pair<<<(int)(((long long)EE * KPADM + 255) / 256), 256>>>(p_msg, p_ap, EE, MSGD, KPADM);
    mma_gemm<256, 0><<<dim3(3, EE / 128), 512, SMA256>>>(
        p_ap, 2 * KPADM, nullptr, EE, p_wp + OFF_WIH, bih, p_gi, G3H, KPADM);

    // 3) GRU memory update (chains parallel over dst)
    transpose_whh<<<(G3H * HIDD + 255) / 256, 256>>>(Whh);
    copy_mem_kernel<<<(NN * HIDD + 255) / 256, 256>>>(memin);
    gru_chain_kernel<<<EE, HIDD>>>(bhh);

    // 4) emb = [relu(x @ featW^T + featB) | mem]
    cvt_pair<<<(int)(((long long)NN * 256 + 255) / 256), 256>>>(x, p_ap, NN, 256, 256);
    mma_gemm<256, 1><<<dim3(2, (NN + 127) / 128), 512, SMA256>>>(
        p_ap, 512, nullptr, NN, p_wp + OFF_FEAT, featB, p_emb, EMBD, 256);
    concat_kernel<<<(NN * HIDD + 255) / 256, 256>>>();

    // 5) two TransformerConv layers (Q/K/V per edge, skip for all nodes)
    cvt_pair<<<(int)(((long long)NN * 512 + 255) / 256), 256>>>(p_emb, p_ap, NN, 512, 512);
    run_conv_layer_t(p_ap, 1024, 512, p_wp, c0_qb, c0_kb, c0_vb, c0_sb,
                     OFF_Q0, OFF_K0, OFF_V0, OFF_S0, src, dst, p_qe, p_ke, p_ve, p_buf0);
    cvt_pair<<<(int)(((long long)NN * 256 + 255) / 256), 256>>>(p_buf0, p_ap, NN, 256, 256);
    run_conv_layer_t(p_ap, 512, 256, p_wp, c1_qb, c1_kb, c1_vb, c1_sb,
                     OFF_Q1, OFF_K1, OFF_V1, OFF_S1, src, dst, p_qe, p_ke, p_ve, p_buf1);

    // 6) classifier
    cvt_pair<<<(int)(((long long)NN * 256 + 255) / 256), 256>>>(p_buf1, p_ap, NN, 256, 256);
    mma_gemm<64, 0><<<dim3(1, (NN + 127) / 128), 512, SMA64>>>(
        p_ap, 512, nullptr, NN, p_wp + OFF_CLS, clsB, out, 64, 256);
}

// round 13
// speedup vs baseline: 1.9720x; 1.2826x over previous
#include <cuda_runtime.h>
#include <cuda_bf16.h>
#include <math.h>
#include <stdint.h>

#define NN    50000
#define EE    8192
#define INDIM 256
#define HIDD  256
#define MSGD  288
#define KPADM 320   // MSGD padded to multiple of 64
#define G3H   768
#define EMBD  512

// ---------------- scratch (static device globals; no runtime allocation) ----
static __device__ __align__(128) float g_gi  [EE * G3H];
static __device__ __align__(128) float g_WhhT[HIDD * G3H];
static __device__ __align__(128) float g_mem [NN * HIDD];
static __device__ __align__(128) float g_buf0[NN * HIDD];
static __device__ __align__(128) float g_buf1[NN * HIDD];
static __device__ __align__(128) float g_qe  [EE * 512];
static __device__ __align__(128) float g_ke  [EE * 512];
static __device__ __align__(128) float g_ve  [EE * 512];
static __device__ __align__(256) __nv_bfloat16 g_apair[(size_t)NN * 1024];
static __device__ __align__(256) __nv_bfloat16 g_xpair[(size_t)NN * 512];
static __device__ __align__(256) __nv_bfloat16 g_mpair[EE * 2 * KPADM];
static __device__ __align__(256) __nv_bfloat16 g_wpair[3407872];
static __device__ float g_alpha[EE * 2];
static __device__ float g_ex   [EE * 2];
static __device__ float g_m    [NN * 2];
static __device__ float g_denom[NN * 2];
static __device__ int   g_chain_edge[EE];
static __device__ int   g_chain_dst [EE];
static __device__ int   g_is_head   [EE];

// weight-pair arena offsets (bf16 elements; each W[N][K] -> pair [N][2K]).
// Q/K/V per layer are contiguous so one merged GEMM can index across them.
#define OFF_WIH  0u          // 768 x 640
#define OFF_FEAT 491520u     // 256 x 512
#define OFF_Q0   622592u     // 512 x 1024 (K0, V0 follow contiguously)
#define OFF_K0   1146880u
#define OFF_V0   1671168u
#define OFF_S0   2195456u    // 256 x 1024
#define OFF_Q1   2457600u    // 512 x 512 (K1, V1 follow contiguously)
#define OFF_K1   2719744u
#define OFF_V1   2981888u
#define OFF_S1   3244032u    // 256 x 512
#define OFF_CLS  3375104u    // 64 x 512

// ---------------- helpers ----------------------------------------------------
__device__ __forceinline__ uint32_t smem_u32(const void* p) {
    uint32_t a;
    asm("{ .reg .u64 t; cvta.to.shared.u64 t, %1; cvt.u32.u64 %0, t; }" : "=r"(a) : "l"(p));
    return a;
}

#define LDM4(r, addr) \
    asm volatile("ldmatrix.sync.aligned.m8n8.x4.shared.b16 {%0,%1,%2,%3}, [%4];" \
        : "=r"((r)[0]), "=r"((r)[1]), "=r"((r)[2]), "=r"((r)[3]) : "r"(addr))

#define MMA16816(c, a, b) \
    asm volatile("mma.sync.aligned.m16n8k16.row.col.f32.bf16.bf16.f32 " \
        "{%0,%1,%2,%3}, {%4,%5,%6,%7}, {%8,%9}, {%0,%1,%2,%3};" \
        : "+f"((c)[0]), "+f"((c)[1]), "+f"((c)[2]), "+f"((c)[3]) \
        : "r"((a)[0]), "r"((a)[1]), "r"((a)[2]), "r"((a)[3]), \
          "r"((b)[0]), "r"((b)[1]))

#define CPASYNC16(saddr, gptr) \
    asm volatile("cp.async.ca.shared.global [%0], [%1], 16;" \
        :: "r"(saddr), "l"(gptr) : "memory")

__device__ __forceinline__ void pair_store2(__nv_bfloat16* P, size_t base,
                                            float a, float b) {
    __nv_bfloat16 h0 = __float2bfloat16(a), h1 = __float2bfloat16(b);
    __nv_bfloat16 l0 = __float2bfloat16(a - __bfloat162float(h0));
    __nv_bfloat16 l1 = __float2bfloat16(b - __bfloat162float(h1));
    __nv_bfloat162 hh; hh.x = h0; hh.y = h1;
    __nv_bfloat162 ll; ll.x = l0; ll.y = l1;
    *(__nv_bfloat162*)&P[base]      = hh;
    *(__nv_bfloat162*)&P[base + 64] = ll;
}

// ---------------- split-bf16 conversion (interleaved per-64 layout) ----------
// hi -> out[row*2K + (k/64)*128 + k%64], lo at +64.
__global__ void cvt_pair(const float* __restrict__ in, __nv_bfloat16* __restrict__ out,
                         int rows, int incols, int K) {
    long long total = (long long)rows * K;
    long long i = (long long)blockIdx.x * blockDim.x + threadIdx.x;
    if (i >= total) return;
    int r = (int)(i / K), k = (int)(i - (long long)r * K);
    float v = (k < incols) ? in[(size_t)r * incols + k] : 0.0f;
    __nv_bfloat16 h = __float2bfloat16(v);
    __nv_bfloat16 l = __float2bfloat16(v - __bfloat162float(h));
    size_t rb = (size_t)r * 2 * K + (size_t)(k >> 6) * 128 + (k & 63);
    out[rb] = h;
    out[rb + 64] = l;
}

// fused relu + pair-conversion: fp32 [NN x 256] -> pair arena (logical width 256)
__global__ void relu_cvt(const float* __restrict__ in, __nv_bfloat16* __restrict__ out) {
    int i = blockIdx.x * 256 + threadIdx.x;
    if (i >= NN * 256) return;
    int r = i >> 8, c = i & 255;
    float v = fmaxf(in[i], 0.0f);
    __nv_bfloat16 h = __float2bfloat16(v);
    __nv_bfloat16 l = __float2bfloat16(v - __bfloat162float(h));
    size_t b = (size_t)r * 512 + ((c >> 6) << 7) + (c & 63);
    out[b] = h;
    out[b + 64] = l;
}

// ---------------- HMMA split-bf16 GEMM ---------------------------------------
// C = act( gather(A_pair) @ W_pair^T + bias ); fp32 accumulate in registers.
// OUT=0: fp32 C with leading dim ldc. OUT=1: pair-format bf16 C, logical row
// width ldc (row stride 2*ldc), hi|lo interleaved per 64-group.
template<int NTILE, int ACT, int OUT>
__global__ void __launch_bounds__(512, 1)
mma_gemm(const __nv_bfloat16* __restrict__ A, int K2, const int* __restrict__ gather,
         int M, const __nv_bfloat16* __restrict__ W, const float* __restrict__ bias,
         void* __restrict__ Cv, int ldc, int K)
{
    constexpr int NWN = (NTILE >= 256) ? 4 : 2;
    constexpr int WN  = NTILE / NWN;
    constexpr int NF  = WN / 8;
    constexpr int NWM = 16 / NWN;
    constexpr int WM  = 128 / NWM;
    constexpr int MF  = WM / 16;
    constexpr int ASZ = 128 * 256;
    constexpr int WSZ = NTILE * 256;
    constexpr int STAGE = ASZ + WSZ;

    extern __shared__ char dsm[];
    __shared__ int s_grow[128];
    char* tb = (char*)(((uintptr_t)dsm + 1023) & ~(uintptr_t)1023);
    const uint32_t sbase = smem_u32(tb);
    const int tid = threadIdx.x, wid = tid >> 5, lane = tid & 31;
    const int wm = (wid / NWN) * WM, wn = (wid % NWN) * WN;
    const int wrow0 = blockIdx.x * NTILE;

    if (tid < 128) {
        int r = blockIdx.y * 128 + tid;
        if (r >= M) r = M - 1;
        s_grow[tid] = (gather ? gather[r] : r) * K2;
    }
    __syncthreads();

    float cacc[MF][NF][4];
    #pragma unroll
    for (int mf = 0; mf < MF; mf++)
        #pragma unroll
        for (int nf = 0; nf < NF; nf++)
            #pragma unroll
            for (int q = 0; q < 4; q++) cacc[mf][nf][q] = 0.0f;

    const int nch = K / 64;

    #define LOAD_STAGE(s_, kk_) do { \
        uint32_t sa_ = sbase + (s_) * STAGE; \
        int coff_ = (kk_) * 128; \
        _Pragma("unroll") \
        for (int v = tid; v < 2048; v += 512) { \
            int row = v >> 4, j = v & 15; \
            const __nv_bfloat16* g = A + s_grow[row] + coff_ + j * 8; \
            uint32_t ad = sa_ + row * 256 + ((j ^ (row & 7)) << 4); \
            CPASYNC16(ad, g); \
        } \
        uint32_t sw_ = sa_ + ASZ; \
        _Pragma("unroll") \
        for (int v = tid; v < NTILE * 16; v += 512) { \
            int row = v >> 4, j = v & 15; \
            const __nv_bfloat16* g = W + (size_t)(wrow0 + row) * K2 + coff_ + j * 8; \
            uint32_t ad = sw_ + row * 256 + ((j ^ (row & 7)) << 4); \
            CPASYNC16(ad, g); \
        } \
        asm volatile("cp.async.commit_group;" ::: "memory"); \
    } while (0)

    LOAD_STAGE(0, 0);

    for (int c = 0; c < nch; c++) {
        int s = c & 1;
        if (c + 1 < nch) {
            LOAD_STAGE(s ^ 1, c + 1);
            asm volatile("cp.async.wait_group 1;" ::: "memory");
        } else {
            asm volatile("cp.async.wait_group 0;" ::: "memory");
        }
        __syncthreads();

        uint32_t sa = sbase + s * STAGE, sw = sa + ASZ;
        const int arow = lane & 15;
        const int brow = (lane & 7) + ((lane >> 4) << 3);
        #pragma unroll
        for (int ks = 0; ks < 4; ks++) {
            uint32_t ah[MF][4], al[MF][4];
            #pragma unroll
            for (int mf = 0; mf < MF; mf++) {
                int row = wm + mf * 16 + arow;
                int sl = ks * 2 + (lane >> 4);
                LDM4(ah[mf], sa + row * 256 + ((sl ^ (row & 7)) << 4));
                LDM4(al[mf], sa + row * 256 + (((sl + 8) ^ (row & 7)) << 4));
            }
            uint32_t b[NF * 2];
            #pragma unroll
            for (int p = 0; p < NF / 2; p++) {
                int row = wn + p * 16 + brow;
                int sl = ks * 2 + ((lane >> 3) & 1);
                LDM4(&b[p * 4], sw + row * 256 + ((sl ^ (row & 7)) << 4));
            }
            #pragma unroll
            for (int mf = 0; mf < MF; mf++)
                #pragma unroll
                for (int nf = 0; nf < NF; nf++) {
                    MMA16816(cacc[mf][nf], ah[mf], &b[nf * 2]);
                    MMA16816(cacc[mf][nf], al[mf], &b[nf * 2]);
                }
            #pragma unroll
            for (int p = 0; p < NF / 2; p++) {
                int row = wn + p * 16 + brow;
                int sl = 8 + ks * 2 + ((lane >> 3) & 1);
                LDM4(&b[p * 4], sw + row * 256 + ((sl ^ (row & 7)) << 4));
            }
            #pragma unroll
            for (int mf = 0; mf < MF; mf++)
                #pragma unroll
                for (int nf = 0; nf < NF; nf++)
                    MMA16816(cacc[mf][nf], ah[mf], &b[nf * 2]);
        }
        __syncthreads();
    }

    #pragma unroll
    for (int mf = 0; mf < MF; mf++) {
        int r0 = blockIdx.y * 128 + wm + mf * 16 + (lane >> 2);
        #pragma unroll
        for (int nf = 0; nf < NF; nf++) {
            int col = wrow0 + wn + nf * 8 + (lane & 3) * 2;
            float b0 = bias[col], b1 = bias[col + 1];
            float v0 = cacc[mf][nf][0] + b0, v1 = cacc[mf][nf][1] + b1;
            float v2 = cacc[mf][nf][2] + b0, v3 = cacc[mf][nf][3] + b1;
            if (ACT) {
                v0 = fmaxf(v0, 0.f); v1 = fmaxf(v1, 0.f);
                v2 = fmaxf(v2, 0.f); v3 = fmaxf(v3, 0.f);
            }
            if (OUT == 0) {
                float* C = (float*)Cv;
                if (r0 < M)     *(float2*)&C[(size_t)r0 * ldc + col]       = make_float2(v0, v1);
                if (r0 + 8 < M) *(float2*)&C[(size_t)(r0 + 8) * ldc + col] = make_float2(v2, v3);
            } else {
                __nv_bfloat16* P = (__nv_bfloat16*)Cv;
                size_t rs = 2 * (size_t)ldc;
                size_t g = (size_t)((col >> 6) << 7) + (col & 63);
                if (r0 < M)     pair_store2(P, (size_t)r0 * rs + g, v0, v1);
                if (r0 + 8 < M) pair_store2(P, (size_t)(r0 + 8) * rs + g, v2, v3);
            }
        }
    }
    #undef LOAD_STAGE
}

// ---------------- merged Q/K/V edge GEMM -------------------------------------
// W arena has Q,K,V contiguous (3*Ncols rows). x-block pairs: 0-1 -> Q (dst
// gather), 2-3 -> K (src), 4-5 -> V (src). One launch fills the chip.
__global__ void __launch_bounds__(512, 1)
qkv_gemm(const __nv_bfloat16* __restrict__ A, int K2,
         const int* __restrict__ dstg, const int* __restrict__ srcg,
         const __nv_bfloat16* __restrict__ W,
         const float* __restrict__ qb, const float* __restrict__ kb,
         const float* __restrict__ vb,
         float* __restrict__ qo, float* __restrict__ ko, float* __restrict__ vo,
         int K)
{
    constexpr int NTILE = 256;
    constexpr int WN = 64, NF = 8, WM = 32, MF = 2;
    constexpr int ASZ = 128 * 256, WSZ = NTILE * 256, STAGE = ASZ + WSZ;

    extern __shared__ char dsm[];
    __shared__ int s_grow[128];
    char* tb = (char*)(((uintptr_t)dsm + 1023) & ~(uintptr_t)1023);
    const uint32_t sbase = smem_u32(tb);
    const int tid = threadIdx.x, wid = tid >> 5, lane = tid & 31;
    const int wm = (wid / 4) * WM, wn = (wid % 4) * WN;
    const int which = blockIdx.x >> 1;
    const int wrow0 = blockIdx.x * NTILE;

    if (tid < 128) {
        int r = blockIdx.y * 128 + tid;
        const int* gv = (which == 0) ? dstg : srcg;
        s_grow[tid] = gv[r] * K2;
    }
    __syncthreads();

    float cacc[MF][NF][4];
    #pragma unroll
    for (int mf = 0; mf < MF; mf++)
        #pragma unroll
        for (int nf = 0; nf < NF; nf++)
            #pragma unroll
            for (int q = 0; q < 4; q++) cacc[mf][nf][q] = 0.0f;

    const int nch = K / 64;

    #define LOAD_STAGE_Q(s_, kk_) do { \
        uint32_t sa_ = sbase + (s_) * STAGE; \
        int coff_ = (kk_) * 128; \
        _Pragma("unroll") \
        for (int v = tid; v < 2048; v += 512) { \
            int row = v >> 4, j = v & 15; \
            const __nv_bfloat16* g = A + s_grow[row] + coff_ + j * 8; \
            uint32_t ad = sa_ + row * 256 + ((j ^ (row & 7)) << 4); \
            CPASYNC16(ad, g); \
        } \
        uint32_t sw_ = sa_ + ASZ; \
        _Pragma("unroll") \
        for (int v = tid; v < NTILE * 16; v += 512) { \
            int row = v >> 4, j = v & 15; \
            const __nv_bfloat16* g = W + (size_t)(wrow0 + row) * K2 + coff_ + j * 8; \
            uint32_t ad = sw_ + row * 256 + ((j ^ (row & 7)) << 4); \
            CPASYNC16(ad, g); \
        } \
        asm volatile("cp.async.commit_group;" ::: "memory"); \
    } while (0)

    LOAD_STAGE_Q(0, 0);
    for (int c = 0; c < nch; c++) {
        int s = c & 1;
        if (c + 1 < nch) {
            LOAD_STAGE_Q(s ^ 1, c + 1);
            asm volatile("cp.async.wait_group 1;" ::: "memory");
        } else {
            asm volatile("cp.async.wait_group 0;" ::: "memory");
        }
        __syncthreads();
        uint32_t sa = sbase + s * STAGE, sw = sa + ASZ;
        const int arow = lane & 15;
        const int brow = (lane & 7) + ((lane >> 4) << 3);
        #pragma unroll
        for (int ks = 0; ks < 4; ks++) {
            uint32_t ah[MF][4], al[MF][4];
            #pragma unroll
            for (int mf = 0; mf < MF; mf++) {
                int row = wm + mf * 16 + arow;
                int sl = ks * 2 + (lane >> 4);
                LDM4(ah[mf], sa + row * 256 + ((sl ^ (row & 7)) << 4));
                LDM4(al[mf], sa + row * 256 + (((sl + 8) ^ (row & 7)) << 4));
            }
            uint32_t b[NF * 2];
            #pragma unroll
            for (int p = 0; p < NF / 2; p++) {
                int row = wn + p * 16 + brow;
                int sl = ks * 2 + ((lane >> 3) & 1);
                LDM4(&b[p * 4], sw + row * 256 + ((sl ^ (row & 7)) << 4));
            }
            #pragma unroll
            for (int mf = 0; mf < MF; mf++)
                #pragma unroll
                for (int nf = 0; nf < NF; nf++) {
                    MMA16816(cacc[mf][nf], ah[mf], &b[nf * 2]);
                    MMA16816(cacc[mf][nf], al[mf], &b[nf * 2]);
                }
            #pragma unroll
            for (int p = 0; p < NF / 2; p++) {
                int row = wn + p * 16 + brow;
                int sl = 8 + ks * 2 + ((lane >> 3) & 1);
                LDM4(&b[p * 4], sw + row * 256 + ((sl ^ (row & 7)) << 4));
            }
            #pragma unroll
            for (int mf = 0; mf < MF; mf++)
                #pragma unroll
                for (int nf = 0; nf < NF; nf++)
                    MMA16816(cacc[mf][nf], ah[mf], &b[nf * 2]);
        }
        __syncthreads();
    }

    const float* bias = (which == 0) ? qb : (which == 1) ? kb : vb;
    float* C = (which == 0) ? qo : (which == 1) ? ko : vo;
    const int cb0 = (blockIdx.x & 1) * NTILE;
    #pragma unroll
    for (int mf = 0; mf < MF; mf++) {
        int r0 = blockIdx.y * 128 + wm + mf * 16 + (lane >> 2);
        #pragma unroll
        for (int nf = 0; nf < NF; nf++) {
            int col = cb0 + wn + nf * 8 + (lane & 3) * 2;
            float b0 = bias[col], b1 = bias[col + 1];
            *(float2*)&C[(size_t)r0 * 512 + col] =
                make_float2(cacc[mf][nf][0] + b0, cacc[mf][nf][1] + b1);
            *(float2*)&C[(size_t)(r0 + 8) * 512 + col] =
                make_float2(cacc[mf][nf][2] + b0, cacc[mf][nf][3] + b1);
        }
    }
    #undef LOAD_STAGE_Q
}

// ---------------- sort: single-block bitonic on 64-bit keys -----------------
__global__ void sort_kernel(const float* __restrict__ et, const int* __restrict__ ei) {
    extern __shared__ unsigned long long key[];
    const int n = EE;
    for (int i = threadIdx.x; i < n; i += blockDim.x) {
        unsigned long long tbits = (unsigned long long)__float_as_uint(et[i]);
        unsigned long long d = (unsigned long long)(unsigned)ei[EE + i];
        key[i] = (d << 45) | (tbits << 13) | (unsigned long long)i;
    }
    __syncthreads();
    for (int k = 2; k <= n; k <<= 1)
        for (int j = k >> 1; j > 0; j >>= 1) {
            for (int t = threadIdx.x; t < n; t += blockDim.x) {
                int ixj = t ^ j;
                if (ixj > t) {
                    unsigned long long a = key[t], b = key[ixj];
                    bool up = ((t & k) == 0);
                    if ((a > b) == up) { key[t] = b; key[ixj] = a; }
                }
            }
            __syncthreads();
        }
    for (int i = threadIdx.x; i < n; i += blockDim.x) {
        unsigned long long kv = key[i];
        g_chain_edge[i] = (int)(kv & 0x1FFFULL);
        g_chain_dst[i]  = (int)(kv >> 45);
    }
    __syncthreads();
    for (int i = threadIdx.x; i < n; i += blockDim.x)
        g_is_head[i] = (i == 0) || (g_chain_dst[i] != g_chain_dst[i - 1]);
}

// ---------------- small fused helpers ----------------------------------------
// msg pair: [x[src] | relu(time-lin) | 0-pad] split directly to bf16 pair.
__global__ void msg_pair(const float* __restrict__ x, const int* __restrict__ src,
                         const float* __restrict__ et, const float* __restrict__ tW,
                         const float* __restrict__ tb) {
    int e = blockIdx.x, c = threadIdx.x;
    float v = 0.0f;
    if (c < INDIM) v = x[(size_t)src[e] * INDIM + c];
    else if (c < MSGD) { int cc = c - INDIM; v = fmaxf(fmaf(et[e], tW[cc], tb[cc]), 0.0f); }
    __nv_bfloat16 h = __float2bfloat16(v);
    __nv_bfloat16 l = __float2bfloat16(v - __bfloat162float(h));
    size_t b = (size_t)e * (2 * KPADM) + ((c >> 6) << 7) + (c & 63);
    g_mpair[b] = h;
    g_mpair[b + 64] = l;
}

__global__ void transpose_whh(const float* __restrict__ Whh) {
    int idx = blockIdx.x * 256 + threadIdx.x;
    if (idx < G3H * HIDD) {
        int j = idx / HIDD, i = idx % HIDD;
        g_WhhT[i * G3H + j] = Whh[idx];
    }
}

// copy memory to fp32 working buffer AND write its pair form into the emb
// arena's upper half (groups 4-7 of logical width 512).
__global__ void copy_mem_pair(const float* __restrict__ memin) {
    int idx = blockIdx.x * 256 + threadIdx.x;
    if (idx >= NN * HIDD) return;
    float v = memin[idx];
    g_mem[idx] = v;
    int r = idx >> 8, c = idx & 255;
    __nv_bfloat16 h = __float2bfloat16(v);
    __nv_bfloat16 l = __float2bfloat16(v - __bfloat162float(h));
    size_t b = (size_t)r * 1024 + ((4 + (c >> 6)) << 7) + (c & 63);
    g_apair[b] = h;
    g_apair[b + 64] = l;
}

__global__ void init_md_kernel() {
    int idx = blockIdx.x * 256 + threadIdx.x;
    if (idx < NN * 2) { g_m[idx] = __int_as_float(0xff800000); g_denom[idx] = 0.0f; }
}

// ---------------- GRU chains (writes pair directly into emb arena) -----------
__global__ void __launch_bounds__(HIDD) gru_chain_kernel(const float* __restrict__ bhh) {
    int i0 = blockIdx.x;
    if (!g_is_head[i0]) return;
    int t = threadIdx.x;
    int d = g_chain_dst[i0];
    __shared__ float sh[HIDD];
    float h = g_mem[d * HIDD + t];
    sh[t] = h;
    int nz = __syncthreads_or(h != 0.0f);
    float b0 = bhh[t], b1 = bhh[HIDD + t], b2 = bhh[2 * HIDD + t];
    for (int i = i0; i < EE && g_chain_dst[i] == d; ++i) {
        int e = g_chain_edge[i];
        float gh0 = b0, gh1 = b1, gh2 = b2;
        if (nz) {
            #pragma unroll 4
            for (int kk = 0; kk < HIDD; ++kk) {
                float v = sh[kk];
                const float* wp = &g_WhhT[kk * G3H + t];
                gh0 += v * wp[0];
                gh1 += v * wp[HIDD];
                gh2 += v * wp[2 * HIDD];
            }
        }
        const float* gi = &g_gi[(size_t)e * G3H];
        float r  = 1.0f / (1.0f + expf(-(gi[t] + gh0)));
        float z  = 1.0f / (1.0f + expf(-(gi[HIDD + t] + gh1)));
        float nv = tanhf(gi[2 * HIDD + t] + r * gh2);
        float hn = (1.0f - z) * nv + z * h;
        __syncthreads();
        sh[t] = hn;
        h = hn;
        nz = __syncthreads_or(hn != 0.0f);
    }
    __nv_bfloat16 hh = __float2bfloat16(h);
    __nv_bfloat16 ll = __float2bfloat16(h - __bfloat162float(hh));
    size_t b = (size_t)d * 1024 + ((4 + (t >> 6)) << 7) + (t & 63);
    g_apair[b] = hh;
    g_apair[b + 64] = ll;
}

// ---------------- attention pieces ------------------------------------------
__device__ __forceinline__ void atomicMaxF(float* addr, float val) {
    int old = __float_as_int(*addr);
    while (__int_as_float(old) < val) {
        int assumed = old;
        old = atomicCAS((int*)addr, assumed, __float_as_int(val));
        if (old == assumed) break;
    }
}

__global__ void alpha_kernel(const float* __restrict__ qe, const float* __restrict__ ke,
                             const int* __restrict__ dst) {
    int e = blockIdx.x * 8 + (threadIdx.x >> 5);
    int lane = threadIdx.x & 31;
    const float* q = qe + (size_t)e * 512;
    const float* k = ke + (size_t)e * 512;
    float s0 = 0.f, s1 = 0.f;
    #pragma unroll
    for (int c = lane; c < 256; c += 32) {
        s0 = fmaf(q[c], k[c], s0);
        s1 = fmaf(q[256 + c], k[256 + c], s1);
    }
    #pragma unroll
    for (int o = 16; o > 0; o >>= 1) {
        s0 += __shfl_xor_sync(0xffffffffu, s0, o);
        s1 += __shfl_xor_sync(0xffffffffu, s1, o);
    }
    if (lane == 0) {
        const float scale = 0.0625f;
        float a0 = s0 * scale, a1 = s1 * scale;
        int d = dst[e];
        g_alpha[e * 2] = a0; g_alpha[e * 2 + 1] = a1;
        atomicMaxF(&g_m[d * 2], a0);
        atomicMaxF(&g_m[d * 2 + 1], a1);
    }
}

__global__ void ex_kernel(const int* __restrict__ dst) {
    int idx = blockIdx.x * 256 + threadIdx.x;
    if (idx < EE * 2) {
        int e = idx >> 1, h = idx & 1;
        int d = dst[e];
        float v = expf(g_alpha[idx] - g_m[d * 2 + h]);
        g_ex[idx] = v;
        atomicAdd(&g_denom[d * 2 + h], v);
    }
}

__global__ void scatter_kernel(const float* __restrict__ ve, const int* __restrict__ dst,
                               float* __restrict__ C) {
    int e = blockIdx.x, c = threadIdx.x;
    int d = dst[e];
    float w0 = g_ex[e * 2]     / g_denom[d * 2]     * 0.5f;
    float w1 = g_ex[e * 2 + 1] / g_denom[d * 2 + 1] * 0.5f;
    atomicAdd(&C[(size_t)d * HIDD + c],
              w0 * ve[(size_t)e * 512 + c] + w1 * ve[(size_t)e * 512 + 256 + c]);
}

// ---------------- host ------------------------------------------------------
#define SMA256 197632
#define SMA64  99328

extern "C" void kernel_launch(void* const* d_in, const int* in_sizes, int n_in,
                              void* d_out, int out_size) {
    (void)in_sizes; (void)n_in; (void)out_size;
    const float* x     = (const float*)d_in[0];
    const int*   ei    = (const int*)  d_in[1];
    const float* et    = (const float*)d_in[2];
    const float* memin = (const float*)d_in[3];
    const float* Wih   = (const float*)d_in[4];
    const float* Whh   = (const float*)d_in[5];
    const float* bih   = (const float*)d_in[6];
    const float* bhh   = (const float*)d_in[7];
    const float* timeW = (const float*)d_in[8];
    const float* timeB = (const float*)d_in[9];
    const float* featW = (const float*)d_in[10];
    const float* featB = (const float*)d_in[11];
    const float* c0_qW = (const float*)d_in[12]; const float* c0_qb = (const float*)d_in[13];
    const float* c0_kW = (const float*)d_in[14]; const float* c0_kb = (const float*)d_in[15];
    const float* c0_vW = (const float*)d_in[16]; const float* c0_vb = (const float*)d_in[17];
    const float* c0_sW = (const float*)d_in[18]; const float* c0_sb = (const float*)d_in[19];
    const float* c1_qW = (const float*)d_in[20]; const float* c1_qb = (const float*)d_in[21];
    const float* c1_kW = (const float*)d_in[22]; const float* c1_kb = (const float*)d_in[23];
    const float* c1_vW = (const float*)d_in[24]; const float* c1_vb = (const float*)d_in[25];
    const float* c1_sW = (const float*)d_in[26]; const float* c1_sb = (const float*)d_in[27];
    const float* clsW  = (const float*)d_in[28]; const float* clsB  = (const float*)d_in[29];
    float* out = (float*)d_out;

    const int* src = ei;
    const int* dst = ei + EE;

    float *p_gi, *p_buf0, *p_buf1, *p_qe, *p_ke, *p_ve;
    __nv_bfloat16 *p_ap, *p_xp, *p_mp, *p_wp;
    cudaGetSymbolAddress((void**)&p_gi,   g_gi);
    cudaGetSymbolAddress((void**)&p_buf0, g_buf0);
    cudaGetSymbolAddress((void**)&p_buf1, g_buf1);
    cudaGetSymbolAddress((void**)&p_qe,   g_qe);
    cudaGetSymbolAddress((void**)&p_ke,   g_ke);
    cudaGetSymbolAddress((void**)&p_ve,   g_ve);
    cudaGetSymbolAddress((void**)&p_ap,   g_apair);
    cudaGetSymbolAddress((void**)&p_xp,   g_xpair);
    cudaGetSymbolAddress((void**)&p_mp,   g_mpair);
    cudaGetSymbolAddress((void**)&p_wp,   g_wpair);

    cudaFuncSetAttribute(sort_kernel, cudaFuncAttributeMaxDynamicSharedMemorySize, 65536);
    cudaFuncSetAttribute(mma_gemm<256, 0, 0>, cudaFuncAttributeMaxDynamicSharedMemorySize, SMA256);
    cudaFuncSetAttribute(mma_gemm<256, 1, 1>, cudaFuncAttributeMaxDynamicSharedMemorySize, SMA256);
    cudaFuncSetAttribute(mma_gemm<64, 0, 0>,  cudaFuncAttributeMaxDynamicSharedMemorySize, SMA64);
    cudaFuncSetAttribute(qkv_gemm, cudaFuncAttributeMaxDynamicSharedMemorySize, SMA256);

    // 0) split-bf16 weight pairs (interleaved hi|lo per 64-group)
    #define CVW(W_, rows_, incols_, K_, off_) \
        cvt_pair<<<(int)(((long long)(rows_) * (K_) + 255) / 256), 256>>>( \
            W_, p_wp + (off_), rows_, incols_, K_)
    CVW(Wih,   768, MSGD, KPADM, OFF_WIH);
    CVW(featW, 256, 256,  256,   OFF_FEAT);
    CVW(c0_qW, 512, 512,  512,   OFF_Q0);
    CVW(c0_kW, 512, 512,  512,   OFF_K0);
    CVW(c0_vW, 512, 512,  512,   OFF_V0);
    CVW(c0_sW, 256, 512,  512,   OFF_S0);
    CVW(c1_qW, 512, 256,  256,   OFF_Q1);
    CVW(c1_kW, 512, 256,  256,   OFF_K1);
    CVW(c1_vW, 512, 256,  256,   OFF_V1);
    CVW(c1_sW, 256, 256,  256,   OFF_S1);
    CVW(clsW,  64,  256,  256,   OFF_CLS);

    // x pair (feat GEMM input)
    cvt_pair<<<(int)(((long long)NN * 256 + 255) / 256), 256>>>(x, p_xp, NN, 256, 256);

    // 1) sort edges into per-dst time-ordered chains
    sort_kernel<<<1, 1024, 65536>>>(et, ei);

    // 2) gi = [x[src] | relu(time)] @ Wih^T + bih  (msg written as pair directly)
    msg_pair<<<EE, KPADM>>>(x, src, et, timeW, timeB);
    mma_gemm<256, 0, 0><<<dim3(3, EE / 128), 512, SMA256>>>(
        p_mp, 2 * KPADM, nullptr, EE, p_wp + OFF_WIH, bih, p_gi, G3H, KPADM);

    // 3) GRU memory update; final h split-written into emb-pair upper half
    transpose_whh<<<(G3H * HIDD + 255) / 256, 256>>>(Whh);
    copy_mem_pair<<<(NN * HIDD + 255) / 256, 256>>>(memin);
    gru_chain_kernel<<<EE, HIDD>>>(bhh);

    // 4) feat GEMM writes relu'd pair directly into emb-pair lower half
    mma_gemm<256, 1, 1><<<dim3(1, (NN + 127) / 128), 512, SMA256>>>(
        p_xp, 512, nullptr, NN, p_wp + OFF_FEAT, featB, (void*)p_ap, 512, 256);

    // 5) layer 0: merged QKV + skip, attention, fused relu+pair
    qkv_gemm<<<dim3(6, EE / 128), 512, SMA256>>>(
        p_ap, 1024, dst, src, p_wp + OFF_Q0, c0_qb, c0_kb, c0_vb,
        p_qe, p_ke, p_ve, 512);
    mma_gemm<256, 0, 0><<<dim3(1, (NN + 127) / 128), 512, SMA256>>>(
        p_ap, 1024, nullptr, NN, p_wp + OFF_S0, c0_sb, p_buf0, HIDD, 512);
    init_md_kernel<<<(NN * 2 + 255) / 256, 256>>>();
    alpha_kernel<<<EE / 8, 256>>>(p_qe, p_ke, dst);
    ex_kernel<<<(EE * 2 + 255) / 256, 256>>>(dst);
    scatter_kernel<<<EE, HIDD>>>(p_ve, dst, p_buf0);
    relu_cvt<<<(NN * 256 + 255) / 256, 256>>>(p_buf0, p_ap);

    // 6) layer 1
    qkv_gemm<<<dim3(6, EE / 128), 512, SMA256>>>(
        p_ap, 512, dst, src, p_wp + OFF_Q1, c1_qb, c1_kb, c1_vb,
        p_qe, p_ke, p_ve, 256);
    mma_gemm<256, 0, 0><<<dim3(1, (NN + 127) / 128), 512, SMA256>>>(
        p_ap, 512, nullptr, NN, p_wp + OFF_S1, c1_sb, p_buf1, HIDD, 256);
    init_md_kernel<<<(NN * 2 + 255) / 256, 256>>>();
    alpha_kernel<<<EE / 8, 256>>>(p_qe, p_ke, dst);
    ex_kernel<<<(EE * 2 + 255) / 256, 256>>>(dst);
    scatter_kernel<<<EE, HIDD>>>(p_ve, dst, p_buf1);
    relu_cvt<<<(NN * 256 + 255) / 256, 256>>>(p_buf1, p_ap);

    // 7) classifier
    mma_gemm<64, 0, 0><<<dim3(1, (NN + 127) / 128), 512, SMA64>>>(
        p_ap, 512, nullptr, NN, p_wp + OFF_CLS, clsB, out, 64, 256);
}

// round 14
// speedup vs baseline: 1.9967x; 1.0125x over previous
#include <cuda_runtime.h>
#include <cuda_bf16.h>
#include <math.h>
#include <stdint.h>

#define NN    50000
#define EE    8192
#define INDIM 256
#define HIDD  256
#define MSGD  288
#define KPADM 320   // MSGD padded to multiple of 64
#define G3H   768
#define EMBD  512

// ---------------- scratch (static device globals; no runtime allocation) ----
static __device__ __align__(128) float g_gi  [EE * G3H];
static __device__ __align__(128) float g_WhhT[HIDD * G3H];
static __device__ __align__(128) float g_mem [NN * HIDD];
static __device__ __align__(128) float g_buf0[NN * HIDD];
static __device__ __align__(128) float g_buf1[NN * HIDD];
static __device__ __align__(128) float g_qe  [EE * 512];
static __device__ __align__(128) float g_ke  [EE * 512];
static __device__ __align__(128) float g_ve  [EE * 512];
static __device__ __align__(256) __nv_bfloat16 g_apair[(size_t)NN * 1024];
static __device__ __align__(256) __nv_bfloat16 g_xpair[(size_t)NN * 512];
static __device__ __align__(256) __nv_bfloat16 g_mpair[EE * 2 * KPADM];
static __device__ __align__(256) __nv_bfloat16 g_wpair[3407872];
static __device__ float g_alpha[EE * 2];
static __device__ float g_ex   [EE * 2];
static __device__ float g_m    [NN * 2];
static __device__ float g_denom[NN * 2];
static __device__ int   g_chain_edge[EE];
static __device__ int   g_chain_dst [EE];
static __device__ int   g_is_head   [EE];

// chunk-major swizzled weight arenas: [kchunk][Ntot rows][256B swizzled row]
// (bf16 element offsets). QKV per layer merged into one arena of Ntot=1536.
#define OFF_WIH  0u          // ntot 768,  K 320 -> 5 chunks
#define OFF_FEAT 491520u     // ntot 256,  K 256 -> 4
#define OFF_QKV0 622592u     // ntot 1536, K 512 -> 8
#define OFF_S0   2195456u    // ntot 256,  K 512 -> 8
#define OFF_QKV1 2457600u    // ntot 1536, K 256 -> 4
#define OFF_S1   3244032u    // ntot 256,  K 256 -> 4
#define OFF_CLS  3375104u    // ntot 64,   K 256 -> 4

// ---------------- helpers ----------------------------------------------------
__device__ __forceinline__ uint32_t smem_u32(const void* p) {
    uint32_t a;
    asm("{ .reg .u64 t; cvta.to.shared.u64 t, %1; cvt.u32.u64 %0, t; }" : "=r"(a) : "l"(p));
    return a;
}
__device__ __forceinline__ void mbar_init(uint32_t a, uint32_t c) {
    asm volatile("mbarrier.init.shared.b64 [%0], %1;" :: "r"(a), "r"(c) : "memory");
}
__device__ __forceinline__ void mbar_wait(uint32_t a, uint32_t ph) {
    asm volatile(
        "{\n\t.reg .pred P;\n\t"
        "WL_%=:\n\t"
        "mbarrier.try_wait.parity.acquire.cta.shared::cta.b64 P, [%0], %1, 0x989680;\n\t"
        "@P bra.uni WD_%=;\n\t"
        "bra.uni WL_%=;\n\t"
        "WD_%=:\n\t}"
        :: "r"(a), "r"(ph) : "memory");
}

#define LDM4(r, addr) \
    asm volatile("ldmatrix.sync.aligned.m8n8.x4.shared.b16 {%0,%1,%2,%3}, [%4];" \
        : "=r"((r)[0]), "=r"((r)[1]), "=r"((r)[2]), "=r"((r)[3]) : "r"(addr))

#define MMA16816(c, a, b) \
    asm volatile("mma.sync.aligned.m16n8k16.row.col.f32.bf16.bf16.f32 " \
        "{%0,%1,%2,%3}, {%4,%5,%6,%7}, {%8,%9}, {%0,%1,%2,%3};" \
        : "+f"((c)[0]), "+f"((c)[1]), "+f"((c)[2]), "+f"((c)[3]) \
        : "r"((a)[0]), "r"((a)[1]), "r"((a)[2]), "r"((a)[3]), \
          "r"((b)[0]), "r"((b)[1]))

#define CPASYNC16(saddr, gptr) \
    asm volatile("cp.async.ca.shared.global [%0], [%1], 16;" \
        :: "r"(saddr), "l"(gptr) : "memory")

__device__ __forceinline__ void pair_store2(__nv_bfloat16* P, size_t base,
                                            float a, float b) {
    __nv_bfloat16 h0 = __float2bfloat16(a), h1 = __float2bfloat16(b);
    __nv_bfloat16 l0 = __float2bfloat16(a - __bfloat162float(h0));
    __nv_bfloat16 l1 = __float2bfloat16(b - __bfloat162float(h1));
    __nv_bfloat162 hh; hh.x = h0; hh.y = h1;
    __nv_bfloat162 ll; ll.x = l0; ll.y = l1;
    *(__nv_bfloat162*)&P[base]      = hh;
    *(__nv_bfloat162*)&P[base + 64] = ll;
}

// ---------------- activation pair conversion (row-pair layout) ---------------
// hi -> out[row*2K + (k/64)*128 + k%64], lo at +64.
__global__ void cvt_pair(const float* __restrict__ in, __nv_bfloat16* __restrict__ out,
                         int rows, int incols, int K) {
    long long total = (long long)rows * K;
    long long i = (long long)blockIdx.x * blockDim.x + threadIdx.x;
    if (i >= total) return;
    int r = (int)(i / K), k = (int)(i - (long long)r * K);
    float v = (k < incols) ? in[(size_t)r * incols + k] : 0.0f;
    __nv_bfloat16 h = __float2bfloat16(v);
    __nv_bfloat16 l = __float2bfloat16(v - __bfloat162float(h));
    size_t rb = (size_t)r * 2 * K + (size_t)(k >> 6) * 128 + (k & 63);
    out[rb] = h;
    out[rb + 64] = l;
}

// fused relu + pair-conversion: fp32 [NN x 256] -> pair arena (logical width 256)
__global__ void relu_cvt(const float* __restrict__ in, __nv_bfloat16* __restrict__ out) {
    int i = blockIdx.x * 256 + threadIdx.x;
    if (i >= NN * 256) return;
    int r = i >> 8, c = i & 255;
    float v = fmaxf(in[i], 0.0f);
    __nv_bfloat16 h = __float2bfloat16(v);
    __nv_bfloat16 l = __float2bfloat16(v - __bfloat162float(h));
    size_t b = (size_t)r * 512 + ((c >> 6) << 7) + (c & 63);
    out[b] = h;
    out[b + 64] = l;
}

// ---------------- fused weight conversion (ONE launch, chunk-major swizzled) -
// For weight w, logical (row r, col k): n = rowoff+r, kk=k/64, pos=k%64,
// j=pos/8, b=pos%8. hi at arena[aroff + (kk*ntot+n)*128 + ((j^(n&7))<<3) + b],
// lo at j+8. This is byte-identical to the smem stage image, so one
// cp.async.bulk per stage suffices in the GEMMs.
struct WTab { const float* p[11]; };

__global__ void cvt_weights(WTab t, __nv_bfloat16* __restrict__ out) {
    const int   Kw[11]    = {320,256,512,512,512,512,256,256,256,256,256};
    const int   incol[11] = {288,256,512,512,512,512,256,256,256,256,256};
    const int   ntot[11]  = {768,256,1536,1536,1536,256,1536,1536,1536,256,64};
    const int   roff[11]  = {0,0,0,512,1024,0,0,512,1024,0,0};
    const unsigned ao[11] = {OFF_WIH,OFF_FEAT,OFF_QKV0,OFF_QKV0,OFF_QKV0,OFF_S0,
                             OFF_QKV1,OFF_QKV1,OFF_QKV1,OFF_S1,OFF_CLS};
    const int pre[12] = {0,245760,311296,573440,835584,1097728,1228800,
                         1359872,1490944,1622016,1687552,1703936};
    int i = blockIdx.x * 256 + threadIdx.x;
    if (i >= 1703936) return;
    int w = 0;
    #pragma unroll
    for (int q = 0; q < 10; q++) if (i >= pre[q + 1]) w = q + 1;
    int rel = i - pre[w];
    int K = Kw[w];
    int r = rel / K, k = rel - r * K;
    float v = (k < incol[w]) ? t.p[w][(size_t)r * incol[w] + k] : 0.0f;
    __nv_bfloat16 h = __float2bfloat16(v);
    __nv_bfloat16 l = __float2bfloat16(v - __bfloat162float(h));
    int n = roff[w] + r;
    int kk = k >> 6, pos = k & 63, j = pos >> 3, b = pos & 7;
    size_t base = (size_t)ao[w] + ((size_t)kk * ntot[w] + n) * 128;
    out[base + ((j ^ (n & 7)) << 3) + b] = h;
    out[base + (((j + 8) ^ (n & 7)) << 3) + b] = l;
}

// ---------------- HMMA split-bf16 GEMM ---------------------------------------
// C = act( gather(A_pair) @ W^T + bias ); fp32 accumulate in registers.
// A: row-pair layout (stride K2 elems). W: chunk-major swizzled arena, chunk
// stride wstride bytes; staged with ONE cp.async.bulk per stage (mbarrier).
// OUT=0: fp32 C (ldc). OUT=1: pair-format bf16 C (logical width ldc).
template<int NTILE, int ACT, int OUT>
__global__ void __launch_bounds__(512, 1)
mma_gemm(const __nv_bfloat16* __restrict__ A, int K2, const int* __restrict__ gather,
         int M, const __nv_bfloat16* __restrict__ W, int wstride,
         const float* __restrict__ bias, void* __restrict__ Cv, int ldc, int K)
{
    constexpr int NWN = (NTILE >= 256) ? 4 : 2;
    constexpr int WN  = NTILE / NWN;
    constexpr int NF  = WN / 8;
    constexpr int NWM = 16 / NWN;
    constexpr int WM  = 128 / NWM;
    constexpr int MF  = WM / 16;
    constexpr int ASZ = 128 * 256;
    constexpr int WSZ = NTILE * 256;
    constexpr int STAGE = ASZ + WSZ;

    extern __shared__ char dsm[];
    __shared__ int s_grow[128];
    __shared__ unsigned long long s_barw[2];
    char* tb = (char*)(((uintptr_t)dsm + 1023) & ~(uintptr_t)1023);
    const uint32_t sbase = smem_u32(tb);
    const uint32_t bw0 = smem_u32(&s_barw[0]), bw1 = smem_u32(&s_barw[1]);
    const int tid = threadIdx.x, wid = tid >> 5, lane = tid & 31;
    const int wm = (wid / NWN) * WM, wn = (wid % NWN) * WN;
    const int wrow0 = blockIdx.x * NTILE;

    if (tid == 0) {
        mbar_init(bw0, 1); mbar_init(bw1, 1);
        asm volatile("fence.proxy.async.shared::cta;" ::: "memory");
    }
    if (tid < 128) {
        int r = blockIdx.y * 128 + tid;
        if (r >= M) r = M - 1;
        s_grow[tid] = (gather ? gather[r] : r) * K2;
    }
    __syncthreads();

    float cacc[MF][NF][4];
    #pragma unroll
    for (int mf = 0; mf < MF; mf++)
        #pragma unroll
        for (int nf = 0; nf < NF; nf++)
            #pragma unroll
            for (int q = 0; q < 4; q++) cacc[mf][nf][q] = 0.0f;

    const int nch = K / 64;
    uint32_t phw0 = 0, phw1 = 0;

    #define LOAD_STAGE(s_, kk_) do { \
        uint32_t sa_ = sbase + (s_) * STAGE; \
        int coff_ = (kk_) * 128; \
        _Pragma("unroll") \
        for (int v = tid; v < 2048; v += 512) { \
            int row = v >> 4, j = v & 15; \
            const __nv_bfloat16* g = A + s_grow[row] + coff_ + j * 8; \
            uint32_t ad = sa_ + row * 256 + ((j ^ (row & 7)) << 4); \
            CPASYNC16(ad, g); \
        } \
        asm volatile("cp.async.commit_group;" ::: "memory"); \
        if (tid == 0) { \
            uint32_t mb_ = (s_) ? bw1 : bw0; \
            asm volatile("mbarrier.arrive.expect_tx.shared.b64 _, [%0], %1;" \
                :: "r"(mb_), "r"((uint32_t)WSZ) : "memory"); \
            const void* gs_ = (const char*)W + (size_t)(kk_) * wstride + (size_t)wrow0 * 256; \
            asm volatile("cp.async.bulk.shared::cluster.global.mbarrier::complete_tx::bytes " \
                "[%0], [%1], %2, [%3];" \
                :: "r"(sa_ + (uint32_t)ASZ), "l"(gs_), "r"((uint32_t)WSZ), "r"(mb_) : "memory"); \
        } \
    } while (0)

    LOAD_STAGE(0, 0);

    for (int c = 0; c < nch; c++) {
        int s = c & 1;
        if (c + 1 < nch) {
            LOAD_STAGE(s ^ 1, c + 1);
            asm volatile("cp.async.wait_group 1;" ::: "memory");
        } else {
            asm volatile("cp.async.wait_group 0;" ::: "memory");
        }
        if (s == 0) { mbar_wait(bw0, phw0); phw0 ^= 1; }
        else        { mbar_wait(bw1, phw1); phw1 ^= 1; }
        __syncthreads();

        uint32_t sa = sbase + s * STAGE, sw = sa + ASZ;
        const int arow = lane & 15;
        const int brow = (lane & 7) + ((lane >> 4) << 3);
        #pragma unroll
        for (int ks = 0; ks < 4; ks++) {
            uint32_t ah[MF][4], al[MF][4];
            #pragma unroll
            for (int mf = 0; mf < MF; mf++) {
                int row = wm + mf * 16 + arow;
                int sl = ks * 2 + (lane >> 4);
                LDM4(ah[mf], sa + row * 256 + ((sl ^ (row & 7)) << 4));
                LDM4(al[mf], sa + row * 256 + (((sl + 8) ^ (row & 7)) << 4));
            }
            uint32_t b[NF * 2];
            #pragma unroll
            for (int p = 0; p < NF / 2; p++) {
                int row = wn + p * 16 + brow;
                int sl = ks * 2 + ((lane >> 3) & 1);
                LDM4(&b[p * 4], sw + row * 256 + ((sl ^ (row & 7)) << 4));
            }
            #pragma unroll
            for (int mf = 0; mf < MF; mf++)
                #pragma unroll
                for (int nf = 0; nf < NF; nf++) {
                    MMA16816(cacc[mf][nf], ah[mf], &b[nf * 2]);
                    MMA16816(cacc[mf][nf], al[mf], &b[nf * 2]);
                }
            #pragma unroll
            for (int p = 0; p < NF / 2; p++) {
                int row = wn + p * 16 + brow;
                int sl = 8 + ks * 2 + ((lane >> 3) & 1);
                LDM4(&b[p * 4], sw + row * 256 + ((sl ^ (row & 7)) << 4));
            }
            #pragma unroll
            for (int mf = 0; mf < MF; mf++)
                #pragma unroll
                for (int nf = 0; nf < NF; nf++)
                    MMA16816(cacc[mf][nf], ah[mf], &b[nf * 2]);
        }
        __syncthreads();
    }

    #pragma unroll
    for (int mf = 0; mf < MF; mf++) {
        int r0 = blockIdx.y * 128 + wm + mf * 16 + (lane >> 2);
        #pragma unroll
        for (int nf = 0; nf < NF; nf++) {
            int col = wrow0 + wn + nf * 8 + (lane & 3) * 2;
            float b0 = bias[col], b1 = bias[col + 1];
            float v0 = cacc[mf][nf][0] + b0, v1 = cacc[mf][nf][1] + b1;
            float v2 = cacc[mf][nf][2] + b0, v3 = cacc[mf][nf][3] + b1;
            if (ACT) {
                v0 = fmaxf(v0, 0.f); v1 = fmaxf(v1, 0.f);
                v2 = fmaxf(v2, 0.f); v3 = fmaxf(v3, 0.f);
            }
            if (OUT == 0) {
                float* C = (float*)Cv;
                if (r0 < M)     *(float2*)&C[(size_t)r0 * ldc + col]       = make_float2(v0, v1);
                if (r0 + 8 < M) *(float2*)&C[(size_t)(r0 + 8) * ldc + col] = make_float2(v2, v3);
            } else {
                __nv_bfloat16* P = (__nv_bfloat16*)Cv;
                size_t rs = 2 * (size_t)ldc;
                size_t g = (size_t)((col >> 6) << 7) + (col & 63);
                if (r0 < M)     pair_store2(P, (size_t)r0 * rs + g, v0, v1);
                if (r0 + 8 < M) pair_store2(P, (size_t)(r0 + 8) * rs + g, v2, v3);
            }
        }
    }
    #undef LOAD_STAGE
}

// ---------------- merged Q/K/V edge GEMM (chunk-major W, bulk staging) -------
// W arena ntot=1536 rows (Q|K|V). x-blocks 0-1 -> Q (dst), 2-3 -> K (src),
// 4-5 -> V (src).
__global__ void __launch_bounds__(512, 1)
qkv_gemm(const __nv_bfloat16* __restrict__ A, int K2,
         const int* __restrict__ dstg, const int* __restrict__ srcg,
         const __nv_bfloat16* __restrict__ W, int wstride,
         const float* __restrict__ qb, const float* __restrict__ kb,
         const float* __restrict__ vb,
         float* __restrict__ qo, float* __restrict__ ko, float* __restrict__ vo,
         int K)
{
    constexpr int NTILE = 256;
    constexpr int WN = 64, NF = 8, WM = 32, MF = 2;
    constexpr int ASZ = 128 * 256, WSZ = NTILE * 256, STAGE = ASZ + WSZ;

    extern __shared__ char dsm[];
    __shared__ int s_grow[128];
    __shared__ unsigned long long s_barw[2];
    char* tb = (char*)(((uintptr_t)dsm + 1023) & ~(uintptr_t)1023);
    const uint32_t sbase = smem_u32(tb);
    const uint32_t bw0 = smem_u32(&s_barw[0]), bw1 = smem_u32(&s_barw[1]);
    const int tid = threadIdx.x, wid = tid >> 5, lane = tid & 31;
    const int wm = (wid / 4) * WM, wn = (wid % 4) * WN;
    const int which = blockIdx.x >> 1;
    const int wrow0 = blockIdx.x * NTILE;

    if (tid == 0) {
        mbar_init(bw0, 1); mbar_init(bw1, 1);
        asm volatile("fence.proxy.async.shared::cta;" ::: "memory");
    }
    if (tid < 128) {
        int r = blockIdx.y * 128 + tid;
        const int* gv = (which == 0) ? dstg : srcg;
        s_grow[tid] = gv[r] * K2;
    }
    __syncthreads();

    float cacc[MF][NF][4];
    #pragma unroll
    for (int mf = 0; mf < MF; mf++)
        #pragma unroll
        for (int nf = 0; nf < NF; nf++)
            #pragma unroll
            for (int q = 0; q < 4; q++) cacc[mf][nf][q] = 0.0f;

    const int nch = K / 64;
    uint32_t phw0 = 0, phw1 = 0;

    #define LOAD_STAGE_Q(s_, kk_) do { \
        uint32_t sa_ = sbase + (s_) * STAGE; \
        int coff_ = (kk_) * 128; \
        _Pragma("unroll") \
        for (int v = tid; v < 2048; v += 512) { \
            int row = v >> 4, j = v & 15; \
            const __nv_bfloat16* g = A + s_grow[row] + coff_ + j * 8; \
            uint32_t ad = sa_ + row * 256 + ((j ^ (row & 7)) << 4); \
            CPASYNC16(ad, g); \
        } \
        asm volatile("cp.async.commit_group;" ::: "memory"); \
        if (tid == 0) { \
            uint32_t mb_ = (s_) ? bw1 : bw0; \
            asm volatile("mbarrier.arrive.expect_tx.shared.b64 _, [%0], %1;" \
                :: "r"(mb_), "r"((uint32_t)WSZ) : "memory"); \
            const void* gs_ = (const char*)W + (size_t)(kk_) * wstride + (size_t)wrow0 * 256; \
            asm volatile("cp.async.bulk.shared::cluster.global.mbarrier::complete_tx::bytes " \
                "[%0], [%1], %2, [%3];" \
                :: "r"(sa_ + (uint32_t)ASZ), "l"(gs_), "r"((uint32_t)WSZ), "r"(mb_) : "memory"); \
        } \
    } while (0)

    LOAD_STAGE_Q(0, 0);
    for (int c = 0; c < nch; c++) {
        int s = c & 1;
        if (c + 1 < nch) {
            LOAD_STAGE_Q(s ^ 1, c + 1);
            asm volatile("cp.async.wait_group 1;" ::: "memory");
        } else {
            asm volatile("cp.async.wait_group 0;" ::: "memory");
        }
        if (s == 0) { mbar_wait(bw0, phw0); phw0 ^= 1; }
        else        { mbar_wait(bw1, phw1); phw1 ^= 1; }
        __syncthreads();

        uint32_t sa = sbase + s * STAGE, sw = sa + ASZ;
        const int arow = lane & 15;
        const int brow = (lane & 7) + ((lane >> 4) << 3);
        #pragma unroll
        for (int ks = 0; ks < 4; ks++) {
            uint32_t ah[MF][4], al[MF][4];
            #pragma unroll
            for (int mf = 0; mf < MF; mf++) {
                int row = wm + mf * 16 + arow;
                int sl = ks * 2 + (lane >> 4);
                LDM4(ah[mf], sa + row * 256 + ((sl ^ (row & 7)) << 4));
                LDM4(al[mf], sa + row * 256 + (((sl + 8) ^ (row & 7)) << 4));
            }
            uint32_t b[NF * 2];
            #pragma unroll
            for (int p = 0; p < NF / 2; p++) {
                int row = wn + p * 16 + brow;
                int sl = ks * 2 + ((lane >> 3) & 1);
                LDM4(&b[p * 4], sw + row * 256 + ((sl ^ (row & 7)) << 4));
            }
            #pragma unroll
            for (int mf = 0; mf < MF; mf++)
                #pragma unroll
                for (int nf = 0; nf < NF; nf++) {
                    MMA16816(cacc[mf][nf], ah[mf], &b[nf * 2]);
                    MMA16816(cacc[mf][nf], al[mf], &b[nf * 2]);
                }
            #pragma unroll
            for (int p = 0; p < NF / 2; p++) {
                int row = wn + p * 16 + brow;
                int sl = 8 + ks * 2 + ((lane >> 3) & 1);
                LDM4(&b[p * 4], sw + row * 256 + ((sl ^ (row & 7)) << 4));
            }
            #pragma unroll
            for (int mf = 0; mf < MF; mf++)
                #pragma unroll
                for (int nf = 0; nf < NF; nf++)
                    MMA16816(cacc[mf][nf], ah[mf], &b[nf * 2]);
        }
        __syncthreads();
    }

    const float* bias = (which == 0) ? qb : (which == 1) ? kb : vb;
    float* C = (which == 0) ? qo : (which == 1) ? ko : vo;
    const int cb0 = (blockIdx.x & 1) * NTILE;
    #pragma unroll
    for (int mf = 0; mf < MF; mf++) {
        int r0 = blockIdx.y * 128 + wm + mf * 16 + (lane >> 2);
        #pragma unroll
        for (int nf = 0; nf < NF; nf++) {
            int col = cb0 + wn + nf * 8 + (lane & 3) * 2;
            float b0 = bias[col], b1 = bias[col + 1];
            *(float2*)&C[(size_t)r0 * 512 + col] =
                make_float2(cacc[mf][nf][0] + b0, cacc[mf][nf][1] + b1);
            *(float2*)&C[(size_t)(r0 + 8) * 512 + col] =
                make_float2(cacc[mf][nf][2] + b0, cacc[mf][nf][3] + b1);
        }
    }
    #undef LOAD_STAGE_Q
}

// ---------------- sort: single-block bitonic on 64-bit keys -----------------
__global__ void sort_kernel(const float* __restrict__ et, const int* __restrict__ ei) {
    extern __shared__ unsigned long long key[];
    const int n = EE;
    for (int i = threadIdx.x; i < n; i += blockDim.x) {
        unsigned long long tbits = (unsigned long long)__float_as_uint(et[i]);
        unsigned long long d = (unsigned long long)(unsigned)ei[EE + i];
        key[i] = (d << 45) | (tbits << 13) | (unsigned long long)i;
    }
    __syncthreads();
    for (int k = 2; k <= n; k <<= 1)
        for (int j = k >> 1; j > 0; j >>= 1) {
            for (int t = threadIdx.x; t < n; t += blockDim.x) {
                int ixj = t ^ j;
                if (ixj > t) {
                    unsigned long long a = key[t], b = key[ixj];
                    bool up = ((t & k) == 0);
                    if ((a > b) == up) { key[t] = b; key[ixj] = a; }
                }
            }
            __syncthreads();
        }
    for (int i = threadIdx.x; i < n; i += blockDim.x) {
        unsigned long long kv = key[i];
        g_chain_edge[i] = (int)(kv & 0x1FFFULL);
        g_chain_dst[i]  = (int)(kv >> 45);
    }
    __syncthreads();
    for (int i = threadIdx.x; i < n; i += blockDim.x)
        g_is_head[i] = (i == 0) || (g_chain_dst[i] != g_chain_dst[i - 1]);
}

// ---------------- small fused helpers ----------------------------------------
__global__ void msg_pair(const float* __restrict__ x, const int* __restrict__ src,
                         const float* __restrict__ et, const float* __restrict__ tW,
                         const float* __restrict__ tb) {
    int e = blockIdx.x, c = threadIdx.x;
    float v = 0.0f;
    if (c < INDIM) v = x[(size_t)src[e] * INDIM + c];
    else if (c < MSGD) { int cc = c - INDIM; v = fmaxf(fmaf(et[e], tW[cc], tb[cc]), 0.0f); }
    __nv_bfloat16 h = __float2bfloat16(v);
    __nv_bfloat16 l = __float2bfloat16(v - __bfloat162float(h));
    size_t b = (size_t)e * (2 * KPADM) + ((c >> 6) << 7) + (c & 63);
    g_mpair[b] = h;
    g_mpair[b + 64] = l;
}

__global__ void transpose_whh(const float* __restrict__ Whh) {
    int idx = blockIdx.x * 256 + threadIdx.x;
    if (idx < G3H * HIDD) {
        int j = idx / HIDD, i = idx % HIDD;
        g_WhhT[i * G3H + j] = Whh[idx];
    }
}

__global__ void copy_mem_pair(const float* __restrict__ memin) {
    int idx = blockIdx.x * 256 + threadIdx.x;
    if (idx >= NN * HIDD) return;
    float v = memin[idx];
    g_mem[idx] = v;
    int r = idx >> 8, c = idx & 255;
    __nv_bfloat16 h = __float2bfloat16(v);
    __nv_bfloat16 l = __float2bfloat16(v - __bfloat162float(h));
    size_t b = (size_t)r * 1024 + ((4 + (c >> 6)) << 7) + (c & 63);
    g_apair[b] = h;
    g_apair[b + 64] = l;
}

__global__ void init_md_kernel() {
    int idx = blockIdx.x * 256 + threadIdx.x;
    if (idx < NN * 2) { g_m[idx] = __int_as_float(0xff800000); g_denom[idx] = 0.0f; }
}

// ---------------- GRU chains (writes pair directly into emb arena) -----------
__global__ void __launch_bounds__(HIDD) gru_chain_kernel(const float* __restrict__ bhh) {
    int i0 = blockIdx.x;
    if (!g_is_head[i0]) return;
    int t = threadIdx.x;
    int d = g_chain_dst[i0];
    __shared__ float sh[HIDD];
    float h = g_mem[d * HIDD + t];
    sh[t] = h;
    int nz = __syncthreads_or(h != 0.0f);
    float b0 = bhh[t], b1 = bhh[HIDD + t], b2 = bhh[2 * HIDD + t];
    for (int i = i0; i < EE && g_chain_dst[i] == d; ++i) {
        int e = g_chain_edge[i];
        float gh0 = b0, gh1 = b1, gh2 = b2;
        if (nz) {
            #pragma unroll 4
            for (int kk = 0; kk < HIDD; ++kk) {
                float v = sh[kk];
                const float* wp = &g_WhhT[kk * G3H + t];
                gh0 += v * wp[0];
                gh1 += v * wp[HIDD];
                gh2 += v * wp[2 * HIDD];
            }
        }
        const float* gi = &g_gi[(size_t)e * G3H];
        float r  = 1.0f / (1.0f + expf(-(gi[t] + gh0)));
        float z  = 1.0f / (1.0f + expf(-(gi[HIDD + t] + gh1)));
        float nv = tanhf(gi[2 * HIDD + t] + r * gh2);
        float hn = (1.0f - z) * nv + z * h;
        __syncthreads();
        sh[t] = hn;
        h = hn;
        nz = __syncthreads_or(hn != 0.0f);
    }
    __nv_bfloat16 hh = __float2bfloat16(h);
    __nv_bfloat16 ll = __float2bfloat16(h - __bfloat162float(hh));
    size_t b = (size_t)d * 1024 + ((4 + (t >> 6)) << 7) + (t & 63);
    g_apair[b] = hh;
    g_apair[b + 64] = ll;
}

// ---------------- attention pieces ------------------------------------------
__device__ __forceinline__ void atomicMaxF(float* addr, float val) {
    int old = __float_as_int(*addr);
    while (__int_as_float(old) < val) {
        int assumed = old;
        old = atomicCAS((int*)addr, assumed, __float_as_int(val));
        if (old == assumed) break;
    }
}

__global__ void alpha_kernel(const float* __restrict__ qe, const float* __restrict__ ke,
                             const int* __restrict__ dst) {
    int e = blockIdx.x * 8 + (threadIdx.x >> 5);
    int lane = threadIdx.x & 31;
    const float* q = qe + (size_t)e * 512;
    const float* k = ke + (size_t)e * 512;
    float s0 = 0.f, s1 = 0.f;
    #pragma unroll
    for (int c = lane; c < 256; c += 32) {
        s0 = fmaf(q[c], k[c], s0);
        s1 = fmaf(q[256 + c], k[256 + c], s1);
    }
    #pragma unroll
    for (int o = 16; o > 0; o >>= 1) {
        s0 += __shfl_xor_sync(0xffffffffu, s0, o);
        s1 += __shfl_xor_sync(0xffffffffu, s1, o);
    }
    if (lane == 0) {
        const float scale = 0.0625f;
        float a0 = s0 * scale, a1 = s1 * scale;
        int d = dst[e];
        g_alpha[e * 2] = a0; g_alpha[e * 2 + 1] = a1;
        atomicMaxF(&g_m[d * 2], a0);
        atomicMaxF(&g_m[d * 2 + 1], a1);
    }
}

__global__ void ex_kernel(const int* __restrict__ dst) {
    int idx = blockIdx.x * 256 + threadIdx.x;
    if (idx < EE * 2) {
        int e = idx >> 1, h = idx & 1;
        int d = dst[e];
        float v = expf(g_alpha[idx] - g_m[d * 2 + h]);
        g_ex[idx] = v;
        atomicAdd(&g_denom[d * 2 + h], v);
    }
}

__global__ void scatter_kernel(const float* __restrict__ ve, const int* __restrict__ dst,
                               float* __restrict__ C) {
    int e = blockIdx.x, c = threadIdx.x;
    int d = dst[e];
    float w0 = g_ex[e * 2]     / g_denom[d * 2]     * 0.5f;
    float w1 = g_ex[e * 2 + 1] / g_denom[d * 2 + 1] * 0.5f;
    atomicAdd(&C[(size_t)d * HIDD + c],
              w0 * ve[(size_t)e * 512 + c] + w1 * ve[(size_t)e * 512 + 256 + c]);
}

// ---------------- host ------------------------------------------------------
#define SMA256 197632
#define SMA64  99328

extern "C" void kernel_launch(void* const* d_in, const int* in_sizes, int n_in,
                              void* d_out, int out_size) {
    (void)in_sizes; (void)n_in; (void)out_size;
    const float* x     = (const float*)d_in[0];
    const int*   ei    = (const int*)  d_in[1];
    const float* et    = (const float*)d_in[2];
    const float* memin = (const float*)d_in[3];
    const float* Whh   = (const float*)d_in[5];
    const float* bih   = (const float*)d_in[6];
    const float* bhh   = (const float*)d_in[7];
    const float* timeW = (const float*)d_in[8];
    const float* timeB = (const float*)d_in[9];
    const float* featB = (const float*)d_in[11];
    const float* c0_qb = (const float*)d_in[13];
    const float* c0_kb = (const float*)d_in[15];
    const float* c0_vb = (const float*)d_in[17];
    const float* c0_sb = (const float*)d_in[19];
    const float* c1_qb = (const float*)d_in[21];
    const float* c1_kb = (const float*)d_in[23];
    const float* c1_vb = (const float*)d_in[25];
    const float* c1_sb = (const float*)d_in[27];
    const float* clsB  = (const float*)d_in[29];
    float* out = (float*)d_out;

    const int* src = ei;
    const int* dst = ei + EE;

    float *p_gi, *p_buf0, *p_buf1, *p_qe, *p_ke, *p_ve;
    __nv_bfloat16 *p_ap, *p_xp, *p_mp, *p_wp;
    cudaGetSymbolAddress((void**)&p_gi,   g_gi);
    cudaGetSymbolAddress((void**)&p_buf0, g_buf0);
    cudaGetSymbolAddress((void**)&p_buf1, g_buf1);
    cudaGetSymbolAddress((void**)&p_qe,   g_qe);
    cudaGetSymbolAddress((void**)&p_ke,   g_ke);
    cudaGetSymbolAddress((void**)&p_ve,   g_ve);
    cudaGetSymbolAddress((void**)&p_ap,   g_apair);
    cudaGetSymbolAddress((void**)&p_xp,   g_xpair);
    cudaGetSymbolAddress((void**)&p_mp,   g_mpair);
    cudaGetSymbolAddress((void**)&p_wp,   g_wpair);

    cudaFuncSetAttribute(sort_kernel, cudaFuncAttributeMaxDynamicSharedMemorySize, 65536);
    cudaFuncSetAttribute(mma_gemm<256, 0, 0>, cudaFuncAttributeMaxDynamicSharedMemorySize, SMA256);
    cudaFuncSetAttribute(mma_gemm<256, 1, 1>, cudaFuncAttributeMaxDynamicSharedMemorySize, SMA256);
    cudaFuncSetAttribute(mma_gemm<64, 0, 0>,  cudaFuncAttributeMaxDynamicSharedMemorySize, SMA64);
    cudaFuncSetAttribute(qkv_gemm, cudaFuncAttributeMaxDynamicSharedMemorySize, SMA256);

    // 0) ALL weight conversions in one launch (chunk-major swizzled arenas)
    WTab wt;
    wt.p[0]  = (const float*)d_in[4];   // Wih
    wt.p[1]  = (const float*)d_in[10];  // featW
    wt.p[2]  = (const float*)d_in[12];  // c0_qW
    wt.p[3]  = (const float*)d_in[14];  // c0_kW
    wt.p[4]  = (const float*)d_in[16];  // c0_vW
    wt.p[5]  = (const float*)d_in[18];  // c0_sW
    wt.p[6]  = (const float*)d_in[20];  // c1_qW
    wt.p[7]  = (const float*)d_in[22];  // c1_kW
    wt.p[8]  = (const float*)d_in[24];  // c1_vW
    wt.p[9]  = (const float*)d_in[26];  // c1_sW
    wt.p[10] = (const float*)d_in[28];  // clsW
    cvt_weights<<<6656, 256>>>(wt, p_wp);

    // x pair (feat GEMM input)
    cvt_pair<<<(int)(((long long)NN * 256 + 255) / 256), 256>>>(x, p_xp, NN, 256, 256);

    // 1) sort edges into per-dst time-ordered chains
    sort_kernel<<<1, 1024, 65536>>>(et, ei);

    // 2) gi = [x[src] | relu(time)] @ Wih^T + bih
    msg_pair<<<EE, KPADM>>>(x, src, et, timeW, timeB);
    mma_gemm<256, 0, 0><<<dim3(3, EE / 128), 512, SMA256>>>(
        p_mp, 2 * KPADM, nullptr, EE, p_wp + OFF_WIH, 768 * 256, bih, p_gi, G3H, KPADM);

    // 3) GRU memory update; final h split-written into emb-pair upper half
    transpose_whh<<<(G3H * HIDD + 255) / 256, 256>>>(Whh);
    copy_mem_pair<<<(NN * HIDD + 255) / 256, 256>>>(memin);
    gru_chain_kernel<<<EE, HIDD>>>(bhh);

    // 4) feat GEMM writes relu'd pair directly into emb-pair lower half
    mma_gemm<256, 1, 1><<<dim3(1, (NN + 127) / 128), 512, SMA256>>>(
        p_xp, 512, nullptr, NN, p_wp + OFF_FEAT, 256 * 256, featB, (void*)p_ap, 512, 256);

    // 5) layer 0: merged QKV + skip, attention, fused relu+pair
    qkv_gemm<<<dim3(6, EE / 128), 512, SMA256>>>(
        p_ap, 1024, dst, src, p_wp + OFF_QKV0, 1536 * 256, c0_qb, c0_kb, c0_vb,
        p_qe, p_ke, p_ve, 512);
    mma_gemm<256, 0, 0><<<dim3(1, (NN + 127) / 128), 512, SMA256>>>(
        p_ap, 1024, nullptr, NN, p_wp + OFF_S0, 256 * 256, c0_sb, p_buf0, HIDD, 512);
    init_md_kernel<<<(NN * 2 + 255) / 256, 256>>>();
    alpha_kernel<<<EE / 8, 256>>>(p_qe, p_ke, dst);
    ex_kernel<<<(EE * 2 + 255) / 256, 256>>>(dst);
    scatter_kernel<<<EE, HIDD>>>(p_ve, dst, p_buf0);
    relu_cvt<<<(NN * 256 + 255) / 256, 256>>>(p_buf0, p_ap);

    // 6) layer 1
    qkv_gemm<<<dim3(6, EE / 128), 512, SMA256>>>(
        p_ap, 512, dst, src, p_wp + OFF_QKV1, 1536 * 256, c1_qb, c1_kb, c1_vb,
        p_qe, p_ke, p_ve, 256);
    mma_gemm<256, 0, 0><<<dim3(1, (NN + 127) / 128), 512, SMA256>>>(
        p_ap, 512, nullptr, NN, p_wp + OFF_S1, 256 * 256, c1_sb, p_buf1, HIDD, 256);
    init_md_kernel<<<(NN * 2 + 255) / 256, 256>>>();
    alpha_kernel<<<EE / 8, 256>>>(p_qe, p_ke, dst);
    ex_kernel<<<(EE * 2 + 255) / 256, 256>>>(dst);
    scatter_kernel<<<EE, HIDD>>>(p_ve, dst, p_buf1);
    relu_cvt<<<(NN * 256 + 255) / 256, 256>>>(p_buf1, p_ap);

    // 7) classifier
    mma_gemm<64, 0, 0><<<dim3(1, (NN + 127) / 128), 512, SMA64>>>(
        p_ap, 512, nullptr, NN, p_wp + OFF_CLS, 64 * 256, clsB, out, 64, 256);
}

// round 16
// speedup vs baseline: 2.0797x; 1.0416x over previous
#include <cuda_runtime.h>
#include <cuda_bf16.h>
#include <math.h>
#include <stdint.h>

#define NN    50000
#define EE    8192
#define INDIM 256
#define HIDD  256
#define MSGD  288
#define KPADM 320   // MSGD padded to multiple of 64
#define G3H   768
#define EMBD  512

// ---------------- scratch (static device globals; no runtime allocation) ----
static __device__ __align__(128) float g_gi  [EE * G3H];
static __device__ __align__(128) float g_WhhT[HIDD * G3H];
static __device__ __align__(128) float g_mem [NN * HIDD];
static __device__ __align__(128) float g_buf0[NN * HIDD];
static __device__ __align__(128) float g_buf1[NN * HIDD];
static __device__ __align__(128) float g_qe  [EE * 512];
static __device__ __align__(128) float g_ke  [EE * 512];
static __device__ __align__(128) float g_ve  [EE * 512];
static __device__ __align__(256) __nv_bfloat16 g_apair[(size_t)NN * 1024];
static __device__ __align__(256) __nv_bfloat16 g_xpair[(size_t)NN * 512];
static __device__ __align__(256) __nv_bfloat16 g_mpair[EE * 2 * KPADM];
static __device__ __align__(256) __nv_bfloat16 g_wpair[3407872];
static __device__ float g_alpha[EE * 2];
static __device__ float g_ex   [EE * 2];
static __device__ float g_m    [2][NN * 2];   // per-layer softmax max
static __device__ float g_denom[2][NN * 2];   // per-layer softmax denom
static __device__ int   g_chain_edge[EE];
static __device__ int   g_chain_dst [EE];
static __device__ int   g_is_head   [EE];

// chunk-major swizzled weight arenas: [kchunk][Ntot rows][256B swizzled row]
#define OFF_WIH  0u          // ntot 768,  K 320 -> 5 chunks
#define OFF_FEAT 491520u     // ntot 256,  K 256 -> 4
#define OFF_QKV0 622592u     // ntot 1536, K 512 -> 8
#define OFF_S0   2195456u    // ntot 256,  K 512 -> 8
#define OFF_QKV1 2457600u    // ntot 1536, K 256 -> 4
#define OFF_S1   3244032u    // ntot 256,  K 256 -> 4
#define OFF_CLS  3375104u    // ntot 64,   K 256 -> 4

// ---------------- helpers ----------------------------------------------------
__device__ __forceinline__ uint32_t smem_u32(const void* p) {
    uint32_t a;
    asm("{ .reg .u64 t; cvta.to.shared.u64 t, %1; cvt.u32.u64 %0, t; }" : "=r"(a) : "l"(p));
    return a;
}
__device__ __forceinline__ void mbar_init(uint32_t a, uint32_t c) {
    asm volatile("mbarrier.init.shared.b64 [%0], %1;" :: "r"(a), "r"(c) : "memory");
}
__device__ __forceinline__ void mbar_wait(uint32_t a, uint32_t ph) {
    asm volatile(
        "{\n\t.reg .pred P;\n\t"
        "WL_%=:\n\t"
        "mbarrier.try_wait.parity.acquire.cta.shared::cta.b64 P, [%0], %1, 0x989680;\n\t"
        "@P bra.uni WD_%=;\n\t"
        "bra.uni WL_%=;\n\t"
        "WD_%=:\n\t}"
        :: "r"(a), "r"(ph) : "memory");
}

#define LDM4(r, addr) \
    asm volatile("ldmatrix.sync.aligned.m8n8.x4.shared.b16 {%0,%1,%2,%3}, [%4];" \
        : "=r"((r)[0]), "=r"((r)[1]), "=r"((r)[2]), "=r"((r)[3]) : "r"(addr))

#define MMA16816(c, a, b) \
    asm volatile("mma.sync.aligned.m16n8k16.row.col.f32.bf16.bf16.f32 " \
        "{%0,%1,%2,%3}, {%4,%5,%6,%7}, {%8,%9}, {%0,%1,%2,%3};" \
        : "+f"((c)[0]), "+f"((c)[1]), "+f"((c)[2]), "+f"((c)[3]) \
        : "r"((a)[0]), "r"((a)[1]), "r"((a)[2]), "r"((a)[3]), \
          "r"((b)[0]), "r"((b)[1]))

#define CPASYNC16(saddr, gptr) \
    asm volatile("cp.async.ca.shared.global [%0], [%1], 16;" \
        :: "r"(saddr), "l"(gptr) : "memory")

__device__ __forceinline__ void pair_store2(__nv_bfloat16* P, size_t base,
                                            float a, float b) {
    __nv_bfloat16 h0 = __float2bfloat16(a), h1 = __float2bfloat16(b);
    __nv_bfloat16 l0 = __float2bfloat16(a - __bfloat162float(h0));
    __nv_bfloat16 l1 = __float2bfloat16(b - __bfloat162float(h1));
    __nv_bfloat162 hh; hh.x = h0; hh.y = h1;
    __nv_bfloat162 ll; ll.x = l0; ll.y = l1;
    *(__nv_bfloat162*)&P[base]      = hh;
    *(__nv_bfloat162*)&P[base + 64] = ll;
}
__device__ __forceinline__ void pair_store1(__nv_bfloat16* P, size_t base, float v) {
    __nv_bfloat16 h = __float2bfloat16(v);
    __nv_bfloat16 l = __float2bfloat16(v - __bfloat162float(h));
    P[base] = h;
    P[base + 64] = l;
}

// ---------------- FUSED PROLOGUE ---------------------------------------------
// One launch; block-range role dispatch, grid-stride loops per role.
//  block 0        : bitonic edge sort -> chains (smem 64KB)
//  [1,161)        : msg pair  [x[src]|relu(time)|pad]
//  [161,417)      : x -> pair (feat GEMM input)
//  [417,673)      : memory copy (fp32 working) + pair into emb upper half
//  [673,681)      : Whh transpose
//  [681,713)      : all 11 weight conversions (chunk-major swizzled arena)
//  [713,717)      : softmax m/denom init, BOTH layers
#define PRO_GRID 717

struct PArgs {
    const float* x;
    const int*   ei;
    const float* et;
    const float* memin;
    const float* Whh;
    const float* timeW;
    const float* timeB;
    const float* w[11];
};

__global__ void __launch_bounds__(256) prologue(PArgs a) {
    const int b = blockIdx.x, tid = threadIdx.x;

    if (b == 0) {
        // ---- bitonic sort of 64-bit keys (256 threads) ----
        extern __shared__ unsigned long long key[];
        const int n = EE;
        for (int i = tid; i < n; i += 256) {
            unsigned long long tbits = (unsigned long long)__float_as_uint(a.et[i]);
            unsigned long long d = (unsigned long long)(unsigned)a.ei[EE + i];
            key[i] = (d << 45) | (tbits << 13) | (unsigned long long)i;
        }
        __syncthreads();
        for (int k = 2; k <= n; k <<= 1)
            for (int j = k >> 1; j > 0; j >>= 1) {
                for (int t = tid; t < n; t += 256) {
                    int ixj = t ^ j;
                    if (ixj > t) {
                        unsigned long long u = key[t], v = key[ixj];
                        bool up = ((t & k) == 0);
                        if ((u > v) == up) { key[t] = v; key[ixj] = u; }
                    }
                }
                __syncthreads();
            }
        for (int i = tid; i < n; i += 256) {
            unsigned long long kv = key[i];
            g_chain_edge[i] = (int)(kv & 0x1FFFULL);
            g_chain_dst[i]  = (int)(kv >> 45);
        }
        __syncthreads();
        for (int i = tid; i < n; i += 256)
            g_is_head[i] = (i == 0) || (g_chain_dst[i] != g_chain_dst[i - 1]);
        return;
    }
    if (b < 161) {
        // ---- msg pair ----
        const int* src = a.ei;
        const long long total = (long long)EE * KPADM;
        for (long long i = (long long)(b - 1) * 256 + tid; i < total; i += 160LL * 256) {
            int e = (int)(i / KPADM), c = (int)(i - (long long)e * KPADM);
            float v = 0.0f;
            if (c < INDIM) v = a.x[(size_t)src[e] * INDIM + c];
            else if (c < MSGD) {
                int cc = c - INDIM;
                v = fmaxf(fmaf(a.et[e], a.timeW[cc], a.timeB[cc]), 0.0f);
            }
            pair_store1(g_mpair, (size_t)e * (2 * KPADM) + ((c >> 6) << 7) + (c & 63), v);
        }
        return;
    }
    if (b < 417) {
        // ---- x -> pair ----
        const long long total = (long long)NN * 256;
        for (long long i = (long long)(b - 161) * 256 + tid; i < total; i += 256LL * 256) {
            int r = (int)(i >> 8), c = (int)(i & 255);
            pair_store1(g_xpair, (size_t)r * 512 + ((c >> 6) << 7) + (c & 63),
                        a.x[(size_t)r * 256 + c]);
        }
        return;
    }
    if (b < 673) {
        // ---- memory copy + pair into emb upper half ----
        const long long total = (long long)NN * 256;
        for (long long i = (long long)(b - 417) * 256 + tid; i < total; i += 256LL * 256) {
            float v = a.memin[i];
            g_mem[i] = v;
            int r = (int)(i >> 8), c = (int)(i & 255);
            pair_store1(g_apair, (size_t)r * 1024 + ((4 + (c >> 6)) << 7) + (c & 63), v);
        }
        return;
    }
    if (b < 681) {
        // ---- Whh transpose ----
        for (int i = (b - 673) * 256 + tid; i < G3H * HIDD; i += 8 * 256) {
            int j = i / HIDD, k = i % HIDD;
            g_WhhT[k * G3H + j] = a.Whh[i];
        }
        return;
    }
    if (b < 713) {
        // ---- all weight conversions (chunk-major swizzled) ----
        const int   Kw[11]    = {320,256,512,512,512,512,256,256,256,256,256};
        const int   incol[11] = {288,256,512,512,512,512,256,256,256,256,256};
        const int   ntot[11]  = {768,256,1536,1536,1536,256,1536,1536,1536,256,64};
        const int   roff[11]  = {0,0,0,512,1024,0,0,512,1024,0,0};
        const unsigned ao[11] = {OFF_WIH,OFF_FEAT,OFF_QKV0,OFF_QKV0,OFF_QKV0,OFF_S0,
                                 OFF_QKV1,OFF_QKV1,OFF_QKV1,OFF_S1,OFF_CLS};
        const int pre[12] = {0,245760,311296,573440,835584,1097728,1228800,
                             1359872,1490944,1622016,1687552,1703936};
        for (int i = (b - 681) * 256 + tid; i < 1703936; i += 32 * 256) {
            int w = 0;
            #pragma unroll
            for (int q = 0; q < 10; q++) if (i >= pre[q + 1]) w = q + 1;
            int rel = i - pre[w];
            int K = Kw[w];
            int r = rel / K, k = rel - r * K;
            float v = (k < incol[w]) ? a.w[w][(size_t)r * incol[w] + k] : 0.0f;
            __nv_bfloat16 h = __float2bfloat16(v);
            __nv_bfloat16 l = __float2bfloat16(v - __bfloat162float(h));
            int n = roff[w] + r;
            int kk = k >> 6, pos = k & 63, j = pos >> 3, bb = pos & 7;
            size_t base = (size_t)ao[w] + ((size_t)kk * ntot[w] + n) * 128;
            g_wpair[base + ((j ^ (n & 7)) << 3) + bb] = h;
            g_wpair[base + (((j + 8) ^ (n & 7)) << 3) + bb] = l;
        }
        return;
    }
    {
        // ---- softmax m/denom init for both layers ----
        for (int i = (b - 713) * 256 + tid; i < NN * 2; i += 4 * 256) {
            g_m[0][i] = __int_as_float(0xff800000);
            g_m[1][i] = __int_as_float(0xff800000);
            g_denom[0][i] = 0.0f;
            g_denom[1][i] = 0.0f;
        }
    }
}

// fused relu + pair-conversion: fp32 [NN x 256] -> pair arena (logical width 256)
__global__ void relu_cvt(const float* __restrict__ in, __nv_bfloat16* __restrict__ out) {
    int i = blockIdx.x * 256 + threadIdx.x;
    if (i >= NN * 256) return;
    int r = i >> 8, c = i & 255;
    float v = fmaxf(in[i], 0.0f);
    pair_store1(out, (size_t)r * 512 + ((c >> 6) << 7) + (c & 63), v);
}

// ---------------- HMMA split-bf16 GEMM ---------------------------------------
template<int NTILE, int ACT, int OUT>
__global__ void __launch_bounds__(512, 1)
mma_gemm(const __nv_bfloat16* __restrict__ A, int K2, const int* __restrict__ gather,
         int M, const __nv_bfloat16* __restrict__ W, int wstride,
         const float* __restrict__ bias, void* __restrict__ Cv, int ldc, int K)
{
    constexpr int NWN = (NTILE >= 256) ? 4 : 2;
    constexpr int WN  = NTILE / NWN;
    constexpr int NF  = WN / 8;
    constexpr int NWM = 16 / NWN;
    constexpr int WM  = 128 / NWM;
    constexpr int MF  = WM / 16;
    constexpr int ASZ = 128 * 256;
    constexpr int WSZ = NTILE * 256;
    constexpr int STAGE = ASZ + WSZ;

    extern __shared__ char dsm[];
    __shared__ int s_grow[128];
    __shared__ unsigned long long s_barw[2];
    char* tb = (char*)(((uintptr_t)dsm + 1023) & ~(uintptr_t)1023);
    const uint32_t sbase = smem_u32(tb);
    const uint32_t bw0 = smem_u32(&s_barw[0]), bw1 = smem_u32(&s_barw[1]);
    const int tid = threadIdx.x, wid = tid >> 5, lane = tid & 31;
    const int wm = (wid / NWN) * WM, wn = (wid % NWN) * WN;
    const int wrow0 = blockIdx.x * NTILE;

    if (tid == 0) {
        mbar_init(bw0, 1); mbar_init(bw1, 1);
        asm volatile("fence.proxy.async.shared::cta;" ::: "memory");
    }
    if (tid < 128) {
        int r = blockIdx.y * 128 + tid;
        if (r >= M) r = M - 1;
        s_grow[tid] = (gather ? gather[r] : r) * K2;
    }
    __syncthreads();

    float cacc[MF][NF][4];
    #pragma unroll
    for (int mf = 0; mf < MF; mf++)
        #pragma unroll
        for (int nf = 0; nf < NF; nf++)
            #pragma unroll
            for (int q = 0; q < 4; q++) cacc[mf][nf][q] = 0.0f;

    const int nch = K / 64;
    uint32_t phw0 = 0, phw1 = 0;

    #define LOAD_STAGE(s_, kk_) do { \
        uint32_t sa_ = sbase + (s_) * STAGE; \
        int coff_ = (kk_) * 128; \
        _Pragma("unroll") \
        for (int v = tid; v < 2048; v += 512) { \
            int row = v >> 4, j = v & 15; \
            const __nv_bfloat16* g = A + s_grow[row] + coff_ + j * 8; \
            uint32_t ad = sa_ + row * 256 + ((j ^ (row & 7)) << 4); \
            CPASYNC16(ad, g); \
        } \
        asm volatile("cp.async.commit_group;" ::: "memory"); \
        if (tid == 0) { \
            uint32_t mb_ = (s_) ? bw1 : bw0; \
            asm volatile("mbarrier.arrive.expect_tx.shared.b64 _, [%0], %1;" \
                :: "r"(mb_), "r"((uint32_t)WSZ) : "memory"); \
            const void* gs_ = (const char*)W + (size_t)(kk_) * wstride + (size_t)wrow0 * 256; \
            asm volatile("cp.async.bulk.shared::cluster.global.mbarrier::complete_tx::bytes " \
                "[%0], [%1], %2, [%3];" \
                :: "r"(sa_ + (uint32_t)ASZ), "l"(gs_), "r"((uint32_t)WSZ), "r"(mb_) : "memory"); \
        } \
    } while (0)

    LOAD_STAGE(0, 0);

    for (int c = 0; c < nch; c++) {
        int s = c & 1;
        if (c + 1 < nch) {
            LOAD_STAGE(s ^ 1, c + 1);
            asm volatile("cp.async.wait_group 1;" ::: "memory");
        } else {
            asm volatile("cp.async.wait_group 0;" ::: "memory");
        }
        if (s == 0) { mbar_wait(bw0, phw0); phw0 ^= 1; }
        else        { mbar_wait(bw1, phw1); phw1 ^= 1; }
        __syncthreads();

        uint32_t sa = sbase + s * STAGE, sw = sa + ASZ;
        const int arow = lane & 15;
        const int brow = (lane & 7) + ((lane >> 4) << 3);
        #pragma unroll
        for (int ks = 0; ks < 4; ks++) {
            uint32_t ah[MF][4], al[MF][4];
            #pragma unroll
            for (int mf = 0; mf < MF; mf++) {
                int row = wm + mf * 16 + arow;
                int sl = ks * 2 + (lane >> 4);
                LDM4(ah[mf], sa + row * 256 + ((sl ^ (row & 7)) << 4));
                LDM4(al[mf], sa + row * 256 + (((sl + 8) ^ (row & 7)) << 4));
            }
            uint32_t bb[NF * 2];
            #pragma unroll
            for (int p = 0; p < NF / 2; p++) {
                int row = wn + p * 16 + brow;
                int sl = ks * 2 + ((lane >> 3) & 1);
                LDM4(&bb[p * 4], sw + row * 256 + ((sl ^ (row & 7)) << 4));
            }
            #pragma unroll
            for (int mf = 0; mf < MF; mf++)
                #pragma unroll
                for (int nf = 0; nf < NF; nf++) {
                    MMA16816(cacc[mf][nf], ah[mf], &bb[nf * 2]);
                    MMA16816(cacc[mf][nf], al[mf], &bb[nf * 2]);
                }
            #pragma unroll
            for (int p = 0; p < NF / 2; p++) {
                int row = wn + p * 16 + brow;
                int sl = 8 + ks * 2 + ((lane >> 3) & 1);
                LDM4(&bb[p * 4], sw + row * 256 + ((sl ^ (row & 7)) << 4));
            }
            #pragma unroll
            for (int mf = 0; mf < MF; mf++)
                #pragma unroll
                for (int nf = 0; nf < NF; nf++)
                    MMA16816(cacc[mf][nf], ah[mf], &bb[nf * 2]);
        }
        __syncthreads();
    }

    #pragma unroll
    for (int mf = 0; mf < MF; mf++) {
        int r0 = blockIdx.y * 128 + wm + mf * 16 + (lane >> 2);
        #pragma unroll
        for (int nf = 0; nf < NF; nf++) {
            int col = wrow0 + wn + nf * 8 + (lane & 3) * 2;
            float b0 = bias[col], b1 = bias[col + 1];
            float v0 = cacc[mf][nf][0] + b0, v1 = cacc[mf][nf][1] + b1;
            float v2 = cacc[mf][nf][2] + b0, v3 = cacc[mf][nf][3] + b1;
            if (ACT) {
                v0 = fmaxf(v0, 0.f); v1 = fmaxf(v1, 0.f);
                v2 = fmaxf(v2, 0.f); v3 = fmaxf(v3, 0.f);
            }
            if (OUT == 0) {
                float* C = (float*)Cv;
                if (r0 < M)     *(float2*)&C[(size_t)r0 * ldc + col]       = make_float2(v0, v1);
                if (r0 + 8 < M) *(float2*)&C[(size_t)(r0 + 8) * ldc + col] = make_float2(v2, v3);
            } else {
                __nv_bfloat16* P = (__nv_bfloat16*)Cv;
                size_t rs = 2 * (size_t)ldc;
                size_t g = (size_t)((col >> 6) << 7) + (col & 63);
                if (r0 < M)     pair_store2(P, (size_t)r0 * rs + g, v0, v1);
                if (r0 + 8 < M) pair_store2(P, (size_t)(r0 + 8) * rs + g, v2, v3);
            }
        }
    }
    #undef LOAD_STAGE
}

// ---------------- merged Q/K/V edge GEMM -------------------------------------
__global__ void __launch_bounds__(512, 1)
qkv_gemm(const __nv_bfloat16* __restrict__ A, int K2,
         const int* __restrict__ dstg, const int* __restrict__ srcg,
         const __nv_bfloat16* __restrict__ W, int wstride,
         const float* __restrict__ qb, const float* __restrict__ kb,
         const float* __restrict__ vb,
         float* __restrict__ qo, float* __restrict__ ko, float* __restrict__ vo,
         int K)
{
    constexpr int NTILE = 256;
    constexpr int WN = 64, NF = 8, WM = 32, MF = 2;
    constexpr int ASZ = 128 * 256, WSZ = NTILE * 256, STAGE = ASZ + WSZ;

    extern __shared__ char dsm[];
    __shared__ int s_grow[128];
    __shared__ unsigned long long s_barw[2];
    char* tb = (char*)(((uintptr_t)dsm + 1023) & ~(uintptr_t)1023);
    const uint32_t sbase = smem_u32(tb);
    const uint32_t bw0 = smem_u32(&s_barw[0]), bw1 = smem_u32(&s_barw[1]);
    const int tid = threadIdx.x, wid = tid >> 5, lane = tid & 31;
    const int wm = (wid / 4) * WM, wn = (wid % 4) * WN;
    const int which = blockIdx.x >> 1;
    const int wrow0 = blockIdx.x * NTILE;

    if (tid == 0) {
        mbar_init(bw0, 1); mbar_init(bw1, 1);
        asm volatile("fence.proxy.async.shared::cta;" ::: "memory");
    }
    if (tid < 128) {
        int r = blockIdx.y * 128 + tid;
        const int* gv = (which == 0) ? dstg : srcg;
        s_grow[tid] = gv[r] * K2;
    }
    __syncthreads();

    float cacc[MF][NF][4];
    #pragma unroll
    for (int mf = 0; mf < MF; mf++)
        #pragma unroll
        for (int nf = 0; nf < NF; nf++)
            #pragma unroll
            for (int q = 0; q < 4; q++) cacc[mf][nf][q] = 0.0f;

    const int nch = K / 64;
    uint32_t phw0 = 0, phw1 = 0;

    #define LOAD_STAGE_Q(s_, kk_) do { \
        uint32_t sa_ = sbase + (s_) * STAGE; \
        int coff_ = (kk_) * 128; \
        _Pragma("unroll") \
        for (int v = tid; v < 2048; v += 512) { \
            int row = v >> 4, j = v & 15; \
            const __nv_bfloat16* g = A + s_grow[row] + coff_ + j * 8; \
            uint32_t ad = sa_ + row * 256 + ((j ^ (row & 7)) << 4); \
            CPASYNC16(ad, g); \
        } \
        asm volatile("cp.async.commit_group;" ::: "memory"); \
        if (tid == 0) { \
            uint32_t mb_ = (s_) ? bw1 : bw0; \
            asm volatile("mbarrier.arrive.expect_tx.shared.b64 _, [%0], %1;" \
                :: "r"(mb_), "r"((uint32_t)WSZ) : "memory"); \
            const void* gs_ = (const char*)W + (size_t)(kk_) * wstride + (size_t)wrow0 * 256; \
            asm volatile("cp.async.bulk.shared::cluster.global.mbarrier::complete_tx::bytes " \
                "[%0], [%1], %2, [%3];" \
                :: "r"(sa_ + (uint32_t)ASZ), "l"(gs_), "r"((uint32_t)WSZ), "r"(mb_) : "memory"); \
        } \
    } while (0)

    LOAD_STAGE_Q(0, 0);
    for (int c = 0; c < nch; c++) {
        int s = c & 1;
        if (c + 1 < nch) {
            LOAD_STAGE_Q(s ^ 1, c + 1);
            asm volatile("cp.async.wait_group 1;" ::: "memory");
        } else {
            asm volatile("cp.async.wait_group 0;" ::: "memory");
        }
        if (s == 0) { mbar_wait(bw0, phw0); phw0 ^= 1; }
        else        { mbar_wait(bw1, phw1); phw1 ^= 1; }
        __syncthreads();

        uint32_t sa = sbase + s * STAGE, sw = sa + ASZ;
        const int arow = lane & 15;
        const int brow = (lane & 7) + ((lane >> 4) << 3);
        #pragma unroll
        for (int ks = 0; ks < 4; ks++) {
            uint32_t ah[MF][4], al[MF][4];
            #pragma unroll
            for (int mf = 0; mf < MF; mf++) {
                int row = wm + mf * 16 + arow;
                int sl = ks * 2 + (lane >> 4);
                LDM4(ah[mf], sa + row * 256 + ((sl ^ (row & 7)) << 4));
                LDM4(al[mf], sa + row * 256 + (((sl + 8) ^ (row & 7)) << 4));
            }
            uint32_t bb[NF * 2];
            #pragma unroll
            for (int p = 0; p < NF / 2; p++) {
                int row = wn + p * 16 + brow;
                int sl = ks * 2 + ((lane >> 3) & 1);
                LDM4(&bb[p * 4], sw + row * 256 + ((sl ^ (row & 7)) << 4));
            }
            #pragma unroll
            for (int mf = 0; mf < MF; mf++)
                #pragma unroll
                for (int nf = 0; nf < NF; nf++) {
                    MMA16816(cacc[mf][nf], ah[mf], &bb[nf * 2]);
                    MMA16816(cacc[mf][nf], al[mf], &bb[nf * 2]);
                }
            #pragma unroll
            for (int p = 0; p < NF / 2; p++) {
                int row = wn + p * 16 + brow;
                int sl = 8 + ks * 2 + ((lane >> 3) & 1);
                LDM4(&bb[p * 4], sw + row * 256 + ((sl ^ (row & 7)) << 4));
            }
            #pragma unroll
            for (int mf = 0; mf < MF; mf++)
                #pragma unroll
                for (int nf = 0; nf < NF; nf++)
                    MMA16816(cacc[mf][nf], ah[mf], &bb[nf * 2]);
        }
        __syncthreads();
    }

    const float* bias = (which == 0) ? qb : (which == 1) ? kb : vb;
    float* C = (which == 0) ? qo : (which == 1) ? ko : vo;
    const int cb0 = (blockIdx.x & 1) * NTILE;
    #pragma unroll
    for (int mf = 0; mf < MF; mf++) {
        int r0 = blockIdx.y * 128 + wm + mf * 16 + (lane >> 2);
        #pragma unroll
        for (int nf = 0; nf < NF; nf++) {
            int col = cb0 + wn + nf * 8 + (lane & 3) * 2;
            float b0 = bias[col], b1 = bias[col + 1];
            *(float2*)&C[(size_t)r0 * 512 + col] =
                make_float2(cacc[mf][nf][0] + b0, cacc[mf][nf][1] + b1);
            *(float2*)&C[(size_t)(r0 + 8) * 512 + col] =
                make_float2(cacc[mf][nf][2] + b0, cacc[mf][nf][3] + b1);
        }
    }
    #undef LOAD_STAGE_Q
}

// ---------------- GRU chains (writes pair directly into emb arena) -----------
__global__ void __launch_bounds__(HIDD) gru_chain_kernel(const float* __restrict__ bhh) {
    int i0 = blockIdx.x;
    if (!g_is_head[i0]) return;
    int t = threadIdx.x;
    int d = g_chain_dst[i0];
    __shared__ float sh[HIDD];
    float h = g_mem[d * HIDD + t];
    sh[t] = h;
    int nz = __syncthreads_or(h != 0.0f);
    float b0 = bhh[t], b1 = bhh[HIDD + t], b2 = bhh[2 * HIDD + t];
    for (int i = i0; i < EE && g_chain_dst[i] == d; ++i) {
        int e = g_chain_edge[i];
        float gh0 = b0, gh1 = b1, gh2 = b2;
        if (nz) {
            #pragma unroll 4
            for (int kk = 0; kk < HIDD; ++kk) {
                float v = sh[kk];
                const float* wp = &g_WhhT[kk * G3H + t];
                gh0 += v * wp[0];
                gh1 += v * wp[HIDD];
                gh2 += v * wp[2 * HIDD];
            }
        }
        const float* gi = &g_gi[(size_t)e * G3H];
        float r  = 1.0f / (1.0f + expf(-(gi[t] + gh0)));
        float z  = 1.0f / (1.0f + expf(-(gi[HIDD + t] + gh1)));
        float nv = tanhf(gi[2 * HIDD + t] + r * gh2);
        float hn = (1.0f - z) * nv + z * h;
        __syncthreads();
        sh[t] = hn;
        h = hn;
        nz = __syncthreads_or(hn != 0.0f);
    }
    pair_store1(g_apair, (size_t)d * 1024 + ((4 + (t >> 6)) << 7) + (t & 63), h);
}

// ---------------- attention pieces ------------------------------------------
__device__ __forceinline__ void atomicMaxF(float* addr, float val) {
    int old = __float_as_int(*addr);
    while (__int_as_float(old) < val) {
        int assumed = old;
        old = atomicCAS((int*)addr, assumed, __float_as_int(val));
        if (old == assumed) break;
    }
}

__global__ void alpha_kernel(const float* __restrict__ qe, const float* __restrict__ ke,
                             const int* __restrict__ dst, int li) {
    int e = blockIdx.x * 8 + (threadIdx.x >> 5);
    int lane = threadIdx.x & 31;
    const float* q = qe + (size_t)e * 512;
    const float* k = ke + (size_t)e * 512;
    float s0 = 0.f, s1 = 0.f;
    #pragma unroll
    for (int c = lane; c < 256; c += 32) {
        s0 = fmaf(q[c], k[c], s0);
        s1 = fmaf(q[256 + c], k[256 + c], s1);
    }
    #pragma unroll
    for (int o = 16; o > 0; o >>= 1) {
        s0 += __shfl_xor_sync(0xffffffffu, s0, o);
        s1 += __shfl_xor_sync(0xffffffffu, s1, o);
    }
    if (lane == 0) {
        const float scale = 0.0625f;
        float a0 = s0 * scale, a1 = s1 * scale;
        int d = dst[e];
        g_alpha[e * 2] = a0; g_alpha[e * 2 + 1] = a1;
        atomicMaxF(&g_m[li][d * 2], a0);
        atomicMaxF(&g_m[li][d * 2 + 1], a1);
    }
}

__global__ void ex_kernel(const int* __restrict__ dst, int li) {
    int idx = blockIdx.x * 256 + threadIdx.x;
    if (idx < EE * 2) {
        int e = idx >> 1, h = idx & 1;
        int d = dst[e];
        float v = expf(g_alpha[idx] - g_m[li][d * 2 + h]);
        g_ex[idx] = v;
        atomicAdd(&g_denom[li][d * 2 + h], v);
    }
}

__global__ void scatter_kernel(const float* __restrict__ ve, const int* __restrict__ dst,
                               float* __restrict__ C, int li) {
    int e = blockIdx.x, c = threadIdx.x;
    int d = dst[e];
    float w0 = g_ex[e * 2]     / g_denom[li][d * 2]     * 0.5f;
    float w1 = g_ex[e * 2 + 1] / g_denom[li][d * 2 + 1] * 0.5f;
    atomicAdd(&C[(size_t)d * HIDD + c],
              w0 * ve[(size_t)e * 512 + c] + w1 * ve[(size_t)e * 512 + 256 + c]);
}

// ---------------- host ------------------------------------------------------
#define SMA256 197632
#define SMA64  99328

extern "C" void kernel_launch(void* const* d_in, const int* in_sizes, int n_in,
                              void* d_out, int out_size) {
    (void)in_sizes; (void)n_in; (void)out_size;
    const float* x     = (const float*)d_in[0];
    const int*   ei    = (const int*)  d_in[1];
    const float* et    = (const float*)d_in[2];
    const float* bih   = (const float*)d_in[6];
    const float* bhh   = (const float*)d_in[7];
    const float* featB = (const float*)d_in[11];
    const float* c0_qb = (const float*)d_in[13];
    const float* c0_kb = (const float*)d_in[15];
    const float* c0_vb = (const float*)d_in[17];
    const float* c0_sb = (const float*)d_in[19];
    const float* c1_qb = (const float*)d_in[21];
    const float* c1_kb = (const float*)d_in[23];
    const float* c1_vb = (const float*)d_in[25];
    const float* c1_sb = (const float*)d_in[27];
    const float* clsB  = (const float*)d_in[29];
    float* out = (float*)d_out;

    const int* src = ei;
    const int* dst = ei + EE;

    float *p_gi, *p_buf0, *p_buf1, *p_qe, *p_ke, *p_ve;
    __nv_bfloat16 *p_ap, *p_xp, *p_mp, *p_wp;
    cudaGetSymbolAddress((void**)&p_gi,   g_gi);
    cudaGetSymbolAddress((void**)&p_buf0, g_buf0);
    cudaGetSymbolAddress((void**)&p_buf1, g_buf1);
    cudaGetSymbolAddress((void**)&p_qe,   g_qe);
    cudaGetSymbolAddress((void**)&p_ke,   g_ke);
    cudaGetSymbolAddress((void**)&p_ve,   g_ve);
    cudaGetSymbolAddress((void**)&p_ap,   g_apair);
    cudaGetSymbolAddress((void**)&p_xp,   g_xpair);
    cudaGetSymbolAddress((void**)&p_mp,   g_mpair);
    cudaGetSymbolAddress((void**)&p_wp,   g_wpair);

    cudaFuncSetAttribute(prologue, cudaFuncAttributeMaxDynamicSharedMemorySize, 65536);
    cudaFuncSetAttribute(mma_gemm<256, 0, 0>, cudaFuncAttributeMaxDynamicSharedMemorySize, SMA256);
    cudaFuncSetAttribute(mma_gemm<256, 1, 1>, cudaFuncAttributeMaxDynamicSharedMemorySize, SMA256);
    cudaFuncSetAttribute(mma_gemm<64, 0, 0>,  cudaFuncAttributeMaxDynamicSharedMemorySize, SMA64);
    cudaFuncSetAttribute(qkv_gemm, cudaFuncAttributeMaxDynamicSharedMemorySize, SMA256);

    // 0) fused prologue: sort + msg + cvt_x + mem copy/pair + WhhT + weights + init
    PArgs pa;
    pa.x = x; pa.ei = ei; pa.et = et;
    pa.memin = (const float*)d_in[3];
    pa.Whh   = (const float*)d_in[5];
    pa.timeW = (const float*)d_in[8];
    pa.timeB = (const float*)d_in[9];
    pa.w[0]  = (const float*)d_in[4];
    pa.w[1]  = (const float*)d_in[10];
    pa.w[2]  = (const float*)d_in[12];
    pa.w[3]  = (const float*)d_in[14];
    pa.w[4]  = (const float*)d_in[16];
    pa.w[5]  = (const float*)d_in[18];
    pa.w[6]  = (const float*)d_in[20];
    pa.w[7]  = (const float*)d_in[22];
    pa.w[8]  = (const float*)d_in[24];
    pa.w[9]  = (const float*)d_in[26];
    pa.w[10] = (const float*)d_in[28];
    prologue<<<PRO_GRID, 256, 65536>>>(pa);

    // 1) gi = msg @ Wih^T + bih
    mma_gemm<256, 0, 0><<<dim3(3, EE / 128), 512, SMA256>>>(
        p_mp, 2 * KPADM, nullptr, EE, p_wp + OFF_WIH, 768 * 256, bih, p_gi, G3H, KPADM);

    // 2) GRU memory update; final h pair-written into emb upper half
    gru_chain_kernel<<<EE, HIDD>>>(bhh);

    // 3) feat GEMM writes relu'd pair into emb lower half
    mma_gemm<256, 1, 1><<<dim3(1, (NN + 127) / 128), 512, SMA256>>>(
        p_xp, 512, nullptr, NN, p_wp + OFF_FEAT, 256 * 256, featB, (void*)p_ap, 512, 256);

    // 4) layer 0
    qkv_gemm<<<dim3(6, EE / 128), 512, SMA256>>>(
        p_ap, 1024, dst, src, p_wp + OFF_QKV0, 1536 * 256, c0_qb, c0_kb, c0_vb,
        p_qe, p_ke, p_ve, 512);
    mma_gemm<256, 0, 0><<<dim3(1, (NN + 127) / 128), 512, SMA256>>>(
        p_ap, 1024, nullptr, NN, p_wp + OFF_S0, 256 * 256, c0_sb, p_buf0, HIDD, 512);
    alpha_kernel<<<EE / 8, 256>>>(p_qe, p_ke, dst, 0);
    ex_kernel<<<(EE * 2 + 255) / 256, 256>>>(dst, 0);
    scatter_kernel<<<EE, HIDD>>>(p_ve, dst, p_buf0, 0);
    relu_cvt<<<(NN * 256 + 255) / 256, 256>>>(p_buf0, p_ap);

    // 5) layer 1
    qkv_gemm<<<dim3(6, EE / 128), 512, SMA256>>>(
        p_ap, 512, dst, src, p_wp + OFF_QKV1, 1536 * 256, c1_qb, c1_kb, c1_vb,
        p_qe, p_ke, p_ve, 256);
    mma_gemm<256, 0, 0><<<dim3(1, (NN + 127) / 128), 512, SMA256>>>(
        p_ap, 512, nullptr, NN, p_wp + OFF_S1, 256 * 256, c1_sb, p_buf1, HIDD, 256);
    alpha_kernel<<<EE / 8, 256>>>(p_qe, p_ke, dst, 1);
    ex_kernel<<<(EE * 2 + 255) / 256, 256>>>(dst, 1);
    scatter_kernel<<<EE, HIDD>>>(p_ve, dst, p_buf1, 1);
    relu_cvt<<<(NN * 256 + 255) / 256, 256>>>(p_buf1, p_ap);

    // 6) classifier
    mma_gemm<64, 0, 0><<<dim3(1, (NN + 127) / 128), 512, SMA64>>>(
        p_ap, 512, nullptr, NN, p_wp + OFF_CLS, 64 * 256, clsB, out, 64, 256);
}

// round 17
// speedup vs baseline: 2.1379x; 1.0280x over previous
#include <cuda_runtime.h>
#include <cuda_bf16.h>
#include <math.h>
#include <stdint.h>

#define NN    50000
#define EE    8192
#define INDIM 256
#define HIDD  256
#define MSGD  288
#define KPADM 320   // MSGD padded to multiple of 64
#define G3H   768
#define EMBD  512

// ---------------- scratch (static device globals; no runtime allocation) ----
static __device__ __align__(128) float g_gi  [EE * G3H];
static __device__ __align__(128) float g_WhhT[HIDD * G3H];
static __device__ __align__(128) float g_mem [NN * HIDD];
static __device__ __align__(128) float g_buf0[NN * HIDD];
static __device__ __align__(128) float g_buf1[NN * HIDD];
static __device__ __align__(128) float g_qe  [EE * 512];
static __device__ __align__(128) float g_ke  [EE * 512];
static __device__ __align__(128) float g_ve  [EE * 512];
static __device__ __align__(256) __nv_bfloat16 g_apair[(size_t)NN * 1024];
static __device__ __align__(256) __nv_bfloat16 g_xpair[(size_t)NN * 512];
static __device__ __align__(256) __nv_bfloat16 g_mpair[EE * 2 * KPADM];
static __device__ __align__(256) __nv_bfloat16 g_wpair[3407872];
static __device__ float g_alpha[EE * 2];
static __device__ float g_ex   [EE * 2];
static __device__ float g_m    [2][NN * 2];   // per-layer softmax max
static __device__ float g_denom[2][NN * 2];   // per-layer softmax denom
static __device__ int   g_chain_edge[EE];
static __device__ int   g_chain_dst [EE];
static __device__ int   g_is_head   [EE];

// chunk-major swizzled weight arenas: [kchunk][Ntot rows][256B swizzled row]
#define OFF_WIH  0u          // ntot 768,  K 320 -> 5 chunks
#define OFF_FEAT 491520u     // ntot 256,  K 256 -> 4
#define OFF_QKV0 622592u     // ntot 1536, K 512 -> 8
#define OFF_S0   2195456u    // ntot 256,  K 512 -> 8
#define OFF_QKV1 2457600u    // ntot 1536, K 256 -> 4
#define OFF_S1   3244032u    // ntot 256,  K 256 -> 4
#define OFF_CLS  3375104u    // ntot 64,   K 256 -> 4

// ---------------- helpers ----------------------------------------------------
__device__ __forceinline__ uint32_t smem_u32(const void* p) {
    uint32_t a;
    asm("{ .reg .u64 t; cvta.to.shared.u64 t, %1; cvt.u32.u64 %0, t; }" : "=r"(a) : "l"(p));
    return a;
}
__device__ __forceinline__ void mbar_init(uint32_t a, uint32_t c) {
    asm volatile("mbarrier.init.shared.b64 [%0], %1;" :: "r"(a), "r"(c) : "memory");
}
__device__ __forceinline__ void mbar_wait(uint32_t a, uint32_t ph) {
    asm volatile(
        "{\n\t.reg .pred P;\n\t"
        "WL_%=:\n\t"
        "mbarrier.try_wait.parity.acquire.cta.shared::cta.b64 P, [%0], %1, 0x989680;\n\t"
        "@P bra.uni WD_%=;\n\t"
        "bra.uni WL_%=;\n\t"
        "WD_%=:\n\t}"
        :: "r"(a), "r"(ph) : "memory");
}

#define LDM4(r, addr) \
    asm volatile("ldmatrix.sync.aligned.m8n8.x4.shared.b16 {%0,%1,%2,%3}, [%4];" \
        : "=r"((r)[0]), "=r"((r)[1]), "=r"((r)[2]), "=r"((r)[3]) : "r"(addr))

#define MMA16816(c, a, b) \
    asm volatile("mma.sync.aligned.m16n8k16.row.col.f32.bf16.bf16.f32 " \
        "{%0,%1,%2,%3}, {%4,%5,%6,%7}, {%8,%9}, {%0,%1,%2,%3};" \
        : "+f"((c)[0]), "+f"((c)[1]), "+f"((c)[2]), "+f"((c)[3]) \
        : "r"((a)[0]), "r"((a)[1]), "r"((a)[2]), "r"((a)[3]), \
          "r"((b)[0]), "r"((b)[1]))

#define CPASYNC16(saddr, gptr) \
    asm volatile("cp.async.ca.shared.global [%0], [%1], 16;" \
        :: "r"(saddr), "l"(gptr) : "memory")

__device__ __forceinline__ void pair_store2(__nv_bfloat16* P, size_t base,
                                            float a, float b) {
    __nv_bfloat16 h0 = __float2bfloat16(a), h1 = __float2bfloat16(b);
    __nv_bfloat16 l0 = __float2bfloat16(a - __bfloat162float(h0));
    __nv_bfloat16 l1 = __float2bfloat16(b - __bfloat162float(h1));
    __nv_bfloat162 hh; hh.x = h0; hh.y = h1;
    __nv_bfloat162 ll; ll.x = l0; ll.y = l1;
    *(__nv_bfloat162*)&P[base]      = hh;
    *(__nv_bfloat162*)&P[base + 64] = ll;
}
__device__ __forceinline__ void pair_store1(__nv_bfloat16* P, size_t base, float v) {
    __nv_bfloat16 h = __float2bfloat16(v);
    __nv_bfloat16 l = __float2bfloat16(v - __bfloat162float(h));
    P[base] = h;
    P[base + 64] = l;
}

// ---------------- FUSED PROLOGUE (unchanged from R16) -------------------------
#define PRO_GRID 717

struct PArgs {
    const float* x;
    const int*   ei;
    const float* et;
    const float* memin;
    const float* Whh;
    const float* timeW;
    const float* timeB;
    const float* w[11];
};

__global__ void __launch_bounds__(256) prologue(PArgs a) {
    const int b = blockIdx.x, tid = threadIdx.x;

    if (b == 0) {
        extern __shared__ unsigned long long key[];
        const int n = EE;
        for (int i = tid; i < n; i += 256) {
            unsigned long long tbits = (unsigned long long)__float_as_uint(a.et[i]);
            unsigned long long d = (unsigned long long)(unsigned)a.ei[EE + i];
            key[i] = (d << 45) | (tbits << 13) | (unsigned long long)i;
        }
        __syncthreads();
        for (int k = 2; k <= n; k <<= 1)
            for (int j = k >> 1; j > 0; j >>= 1) {
                for (int t = tid; t < n; t += 256) {
                    int ixj = t ^ j;
                    if (ixj > t) {
                        unsigned long long u = key[t], v = key[ixj];
                        bool up = ((t & k) == 0);
                        if ((u > v) == up) { key[t] = v; key[ixj] = u; }
                    }
                }
                __syncthreads();
            }
        for (int i = tid; i < n; i += 256) {
            unsigned long long kv = key[i];
            g_chain_edge[i] = (int)(kv & 0x1FFFULL);
            g_chain_dst[i]  = (int)(kv >> 45);
        }
        __syncthreads();
        for (int i = tid; i < n; i += 256)
            g_is_head[i] = (i == 0) || (g_chain_dst[i] != g_chain_dst[i - 1]);
        return;
    }
    if (b < 161) {
        const int* src = a.ei;
        const long long total = (long long)EE * KPADM;
        for (long long i = (long long)(b - 1) * 256 + tid; i < total; i += 160LL * 256) {
            int e = (int)(i / KPADM), c = (int)(i - (long long)e * KPADM);
            float v = 0.0f;
            if (c < INDIM) v = a.x[(size_t)src[e] * INDIM + c];
            else if (c < MSGD) {
                int cc = c - INDIM;
                v = fmaxf(fmaf(a.et[e], a.timeW[cc], a.timeB[cc]), 0.0f);
            }
            pair_store1(g_mpair, (size_t)e * (2 * KPADM) + ((c >> 6) << 7) + (c & 63), v);
        }
        return;
    }
    if (b < 417) {
        const long long total = (long long)NN * 256;
        for (long long i = (long long)(b - 161) * 256 + tid; i < total; i += 256LL * 256) {
            int r = (int)(i >> 8), c = (int)(i & 255);
            pair_store1(g_xpair, (size_t)r * 512 + ((c >> 6) << 7) + (c & 63),
                        a.x[(size_t)r * 256 + c]);
        }
        return;
    }
    if (b < 673) {
        const long long total = (long long)NN * 256;
        for (long long i = (long long)(b - 417) * 256 + tid; i < total; i += 256LL * 256) {
            float v = a.memin[i];
            g_mem[i] = v;
            int r = (int)(i >> 8), c = (int)(i & 255);
            pair_store1(g_apair, (size_t)r * 1024 + ((4 + (c >> 6)) << 7) + (c & 63), v);
        }
        return;
    }
    if (b < 681) {
        for (int i = (b - 673) * 256 + tid; i < G3H * HIDD; i += 8 * 256) {
            int j = i / HIDD, k = i % HIDD;
            g_WhhT[k * G3H + j] = a.Whh[i];
        }
        return;
    }
    if (b < 713) {
        const int   Kw[11]    = {320,256,512,512,512,512,256,256,256,256,256};
        const int   incol[11] = {288,256,512,512,512,512,256,256,256,256,256};
        const int   ntot[11]  = {768,256,1536,1536,1536,256,1536,1536,1536,256,64};
        const int   roff[11]  = {0,0,0,512,1024,0,0,512,1024,0,0};
        const unsigned ao[11] = {OFF_WIH,OFF_FEAT,OFF_QKV0,OFF_QKV0,OFF_QKV0,OFF_S0,
                                 OFF_QKV1,OFF_QKV1,OFF_QKV1,OFF_S1,OFF_CLS};
        const int pre[12] = {0,245760,311296,573440,835584,1097728,1228800,
                             1359872,1490944,1622016,1687552,1703936};
        for (int i = (b - 681) * 256 + tid; i < 1703936; i += 32 * 256) {
            int w = 0;
            #pragma unroll
            for (int q = 0; q < 10; q++) if (i >= pre[q + 1]) w = q + 1;
            int rel = i - pre[w];
            int K = Kw[w];
            int r = rel / K, k = rel - r * K;
            float v = (k < incol[w]) ? a.w[w][(size_t)r * incol[w] + k] : 0.0f;
            __nv_bfloat16 h = __float2bfloat16(v);
            __nv_bfloat16 l = __float2bfloat16(v - __bfloat162float(h));
            int n = roff[w] + r;
            int kk = k >> 6, pos = k & 63, j = pos >> 3, bb = pos & 7;
            size_t base = (size_t)ao[w] + ((size_t)kk * ntot[w] + n) * 128;
            g_wpair[base + ((j ^ (n & 7)) << 3) + bb] = h;
            g_wpair[base + (((j + 8) ^ (n & 7)) << 3) + bb] = l;
        }
        return;
    }
    {
        for (int i = (b - 713) * 256 + tid; i < NN * 2; i += 4 * 256) {
            g_m[0][i] = __int_as_float(0xff800000);
            g_m[1][i] = __int_as_float(0xff800000);
            g_denom[0][i] = 0.0f;
            g_denom[1][i] = 0.0f;
        }
    }
}

// fused relu + pair-conversion
__global__ void relu_cvt(const float* __restrict__ in, __nv_bfloat16* __restrict__ out) {
    int i = blockIdx.x * 256 + threadIdx.x;
    if (i >= NN * 256) return;
    int r = i >> 8, c = i & 255;
    float v = fmaxf(in[i], 0.0f);
    pair_store1(out, (size_t)r * 512 + ((c >> 6) << 7) + (c & 63), v);
}

// ---------------- HMMA split-bf16 GEMM (64-row M-tiles, 2 CTAs/SM) ----------
// 256 threads / 8 warps; MTILE x NTILE CTA tile; smem = 2*(MTILE+NTILE)*256 B.
template<int MTILE, int NTILE, int ACT, int OUT>
__global__ void __launch_bounds__(256, 2)
mma_gemm(const __nv_bfloat16* __restrict__ A, int K2, const int* __restrict__ gather,
         int M, const __nv_bfloat16* __restrict__ W, int wstride,
         const float* __restrict__ bias, void* __restrict__ Cv, int ldc, int K)
{
    constexpr int NWN = (NTILE >= 128) ? 4 : 2;
    constexpr int WN  = NTILE / NWN;
    constexpr int NF  = WN / 8;
    constexpr int NWM = 8 / NWN;
    constexpr int WM  = MTILE / NWM;
    constexpr int MF  = WM / 16;
    constexpr int ASZ = MTILE * 256;
    constexpr int WSZ = NTILE * 256;
    constexpr int STAGE = ASZ + WSZ;

    extern __shared__ char dsm[];
    __shared__ int s_grow[MTILE];
    __shared__ unsigned long long s_barw[2];
    char* tb = (char*)(((uintptr_t)dsm + 1023) & ~(uintptr_t)1023);
    const uint32_t sbase = smem_u32(tb);
    const uint32_t bw0 = smem_u32(&s_barw[0]), bw1 = smem_u32(&s_barw[1]);
    const int tid = threadIdx.x, wid = tid >> 5, lane = tid & 31;
    const int wm = (wid / NWN) * WM, wn = (wid % NWN) * WN;
    const int wrow0 = blockIdx.x * NTILE;

    if (tid == 0) {
        mbar_init(bw0, 1); mbar_init(bw1, 1);
        asm volatile("fence.proxy.async.shared::cta;" ::: "memory");
    }
    if (tid < MTILE) {
        int r = blockIdx.y * MTILE + tid;
        if (r >= M) r = M - 1;
        s_grow[tid] = (gather ? gather[r] : r) * K2;
    }
    __syncthreads();

    float cacc[MF][NF][4];
    #pragma unroll
    for (int mf = 0; mf < MF; mf++)
        #pragma unroll
        for (int nf = 0; nf < NF; nf++)
            #pragma unroll
            for (int q = 0; q < 4; q++) cacc[mf][nf][q] = 0.0f;

    const int nch = K / 64;
    uint32_t phw0 = 0, phw1 = 0;

    #define LOAD_STAGE(s_, kk_) do { \
        uint32_t sa_ = sbase + (s_) * STAGE; \
        int coff_ = (kk_) * 128; \
        _Pragma("unroll") \
        for (int v = tid; v < MTILE * 16; v += 256) { \
            int row = v >> 4, j = v & 15; \
            const __nv_bfloat16* g = A + s_grow[row] + coff_ + j * 8; \
            uint32_t ad = sa_ + row * 256 + ((j ^ (row & 7)) << 4); \
            CPASYNC16(ad, g); \
        } \
        asm volatile("cp.async.commit_group;" ::: "memory"); \
        if (tid == 0) { \
            uint32_t mb_ = (s_) ? bw1 : bw0; \
            asm volatile("mbarrier.arrive.expect_tx.shared.b64 _, [%0], %1;" \
                :: "r"(mb_), "r"((uint32_t)WSZ) : "memory"); \
            const void* gs_ = (const char*)W + (size_t)(kk_) * wstride + (size_t)wrow0 * 256; \
            asm volatile("cp.async.bulk.shared::cluster.global.mbarrier::complete_tx::bytes " \
                "[%0], [%1], %2, [%3];" \
                :: "r"(sa_ + (uint32_t)ASZ), "l"(gs_), "r"((uint32_t)WSZ), "r"(mb_) : "memory"); \
        } \
    } while (0)

    LOAD_STAGE(0, 0);

    for (int c = 0; c < nch; c++) {
        int s = c & 1;
        if (c + 1 < nch) {
            LOAD_STAGE(s ^ 1, c + 1);
            asm volatile("cp.async.wait_group 1;" ::: "memory");
        } else {
            asm volatile("cp.async.wait_group 0;" ::: "memory");
        }
        if (s == 0) { mbar_wait(bw0, phw0); phw0 ^= 1; }
        else        { mbar_wait(bw1, phw1); phw1 ^= 1; }
        __syncthreads();

        uint32_t sa = sbase + s * STAGE, sw = sa + ASZ;
        const int arow = lane & 15;
        const int brow = (lane & 7) + ((lane >> 4) << 3);
        #pragma unroll
        for (int ks = 0; ks < 4; ks++) {
            uint32_t ah[MF][4], al[MF][4];
            #pragma unroll
            for (int mf = 0; mf < MF; mf++) {
                int row = wm + mf * 16 + arow;
                int sl = ks * 2 + (lane >> 4);
                LDM4(ah[mf], sa + row * 256 + ((sl ^ (row & 7)) << 4));
                LDM4(al[mf], sa + row * 256 + (((sl + 8) ^ (row & 7)) << 4));
            }
            uint32_t bb[NF * 2];
            #pragma unroll
            for (int p = 0; p < NF / 2; p++) {
                int row = wn + p * 16 + brow;
                int sl = ks * 2 + ((lane >> 3) & 1);
                LDM4(&bb[p * 4], sw + row * 256 + ((sl ^ (row & 7)) << 4));
            }
            #pragma unroll
            for (int mf = 0; mf < MF; mf++)
                #pragma unroll
                for (int nf = 0; nf < NF; nf++) {
                    MMA16816(cacc[mf][nf], ah[mf], &bb[nf * 2]);
                    MMA16816(cacc[mf][nf], al[mf], &bb[nf * 2]);
                }
            #pragma unroll
            for (int p = 0; p < NF / 2; p++) {
                int row = wn + p * 16 + brow;
                int sl = 8 + ks * 2 + ((lane >> 3) & 1);
                LDM4(&bb[p * 4], sw + row * 256 + ((sl ^ (row & 7)) << 4));
            }
            #pragma unroll
            for (int mf = 0; mf < MF; mf++)
                #pragma unroll
                for (int nf = 0; nf < NF; nf++)
                    MMA16816(cacc[mf][nf], ah[mf], &bb[nf * 2]);
        }
        __syncthreads();
    }

    #pragma unroll
    for (int mf = 0; mf < MF; mf++) {
        int r0 = blockIdx.y * MTILE + wm + mf * 16 + (lane >> 2);
        #pragma unroll
        for (int nf = 0; nf < NF; nf++) {
            int col = wrow0 + wn + nf * 8 + (lane & 3) * 2;
            float b0 = bias[col], b1 = bias[col + 1];
            float v0 = cacc[mf][nf][0] + b0, v1 = cacc[mf][nf][1] + b1;
            float v2 = cacc[mf][nf][2] + b0, v3 = cacc[mf][nf][3] + b1;
            if (ACT) {
                v0 = fmaxf(v0, 0.f); v1 = fmaxf(v1, 0.f);
                v2 = fmaxf(v2, 0.f); v3 = fmaxf(v3, 0.f);
            }
            if (OUT == 0) {
                float* C = (float*)Cv;
                if (r0 < M)     *(float2*)&C[(size_t)r0 * ldc + col]       = make_float2(v0, v1);
                if (r0 + 8 < M) *(float2*)&C[(size_t)(r0 + 8) * ldc + col] = make_float2(v2, v3);
            } else {
                __nv_bfloat16* P = (__nv_bfloat16*)Cv;
                size_t rs = 2 * (size_t)ldc;
                size_t g = (size_t)((col >> 6) << 7) + (col & 63);
                if (r0 < M)     pair_store2(P, (size_t)r0 * rs + g, v0, v1);
                if (r0 + 8 < M) pair_store2(P, (size_t)(r0 + 8) * rs + g, v2, v3);
            }
        }
    }
    #undef LOAD_STAGE
}

// ---------------- merged Q/K/V edge GEMM (64x128 tiles) ----------------------
// W arena ntot=1536 (Q|K|V); 4 x-blocks per matrix: which = bx>>2.
__global__ void __launch_bounds__(256, 2)
qkv_gemm(const __nv_bfloat16* __restrict__ A, int K2,
         const int* __restrict__ dstg, const int* __restrict__ srcg,
         const __nv_bfloat16* __restrict__ W, int wstride,
         const float* __restrict__ qb, const float* __restrict__ kb,
         const float* __restrict__ vb,
         float* __restrict__ qo, float* __restrict__ ko, float* __restrict__ vo,
         int K)
{
    constexpr int MTILE = 64, NTILE = 128;
    constexpr int WN = 32, NF = 4, WM = 32, MF = 2;
    constexpr int ASZ = MTILE * 256, WSZ = NTILE * 256, STAGE = ASZ + WSZ;

    extern __shared__ char dsm[];
    __shared__ int s_grow[MTILE];
    __shared__ unsigned long long s_barw[2];
    char* tb = (char*)(((uintptr_t)dsm + 1023) & ~(uintptr_t)1023);
    const uint32_t sbase = smem_u32(tb);
    const uint32_t bw0 = smem_u32(&s_barw[0]), bw1 = smem_u32(&s_barw[1]);
    const int tid = threadIdx.x, wid = tid >> 5, lane = tid & 31;
    const int wm = (wid / 4) * WM, wn = (wid % 4) * WN;
    const int which = blockIdx.x >> 2;
    const int wrow0 = blockIdx.x * NTILE;

    if (tid == 0) {
        mbar_init(bw0, 1); mbar_init(bw1, 1);
        asm volatile("fence.proxy.async.shared::cta;" ::: "memory");
    }
    if (tid < MTILE) {
        int r = blockIdx.y * MTILE + tid;
        const int* gv = (which == 0) ? dstg : srcg;
        s_grow[tid] = gv[r] * K2;
    }
    __syncthreads();

    float cacc[MF][NF][4];
    #pragma unroll
    for (int mf = 0; mf < MF; mf++)
        #pragma unroll
        for (int nf = 0; nf < NF; nf++)
            #pragma unroll
            for (int q = 0; q < 4; q++) cacc[mf][nf][q] = 0.0f;

    const int nch = K / 64;
    uint32_t phw0 = 0, phw1 = 0;

    #define LOAD_STAGE_Q(s_, kk_) do { \
        uint32_t sa_ = sbase + (s_) * STAGE; \
        int coff_ = (kk_) * 128; \
        _Pragma("unroll") \
        for (int v = tid; v < MTILE * 16; v += 256) { \
            int row = v >> 4, j = v & 15; \
            const __nv_bfloat16* g = A + s_grow[row] + coff_ + j * 8; \
            uint32_t ad = sa_ + row * 256 + ((j ^ (row & 7)) << 4); \
            CPASYNC16(ad, g); \
        } \
        asm volatile("cp.async.commit_group;" ::: "memory"); \
        if (tid == 0) { \
            uint32_t mb_ = (s_) ? bw1 : bw0; \
            asm volatile("mbarrier.arrive.expect_tx.shared.b64 _, [%0], %1;" \
                :: "r"(mb_), "r"((uint32_t)WSZ) : "memory"); \
            const void* gs_ = (const char*)W + (size_t)(kk_) * wstride + (size_t)wrow0 * 256; \
            asm volatile("cp.async.bulk.shared::cluster.global.mbarrier::complete_tx::bytes " \
                "[%0], [%1], %2, [%3];" \
                :: "r"(sa_ + (uint32_t)ASZ), "l"(gs_), "r"((uint32_t)WSZ), "r"(mb_) : "memory"); \
        } \
    } while (0)

    LOAD_STAGE_Q(0, 0);
    for (int c = 0; c < nch; c++) {
        int s = c & 1;
        if (c + 1 < nch) {
            LOAD_STAGE_Q(s ^ 1, c + 1);
            asm volatile("cp.async.wait_group 1;" ::: "memory");
        } else {
            asm volatile("cp.async.wait_group 0;" ::: "memory");
        }
        if (s == 0) { mbar_wait(bw0, phw0); phw0 ^= 1; }
        else        { mbar_wait(bw1, phw1); phw1 ^= 1; }
        __syncthreads();

        uint32_t sa = sbase + s * STAGE, sw = sa + ASZ;
        const int arow = lane & 15;
        const int brow = (lane & 7) + ((lane >> 4) << 3);
        #pragma unroll
        for (int ks = 0; ks < 4; ks++) {
            uint32_t ah[MF][4], al[MF][4];
            #pragma unroll
            for (int mf = 0; mf < MF; mf++) {
                int row = wm + mf * 16 + arow;
                int sl = ks * 2 + (lane >> 4);
                LDM4(ah[mf], sa + row * 256 + ((sl ^ (row & 7)) << 4));
                LDM4(al[mf], sa + row * 256 + (((sl + 8) ^ (row & 7)) << 4));
            }
            uint32_t bb[NF * 2];
            #pragma unroll
            for (int p = 0; p < NF / 2; p++) {
                int row = wn + p * 16 + brow;
                int sl = ks * 2 + ((lane >> 3) & 1);
                LDM4(&bb[p * 4], sw + row * 256 + ((sl ^ (row & 7)) << 4));
            }
            #pragma unroll
            for (int mf = 0; mf < MF; mf++)
                #pragma unroll
                for (int nf = 0; nf < NF; nf++) {
                    MMA16816(cacc[mf][nf], ah[mf], &bb[nf * 2]);
                    MMA16816(cacc[mf][nf], al[mf], &bb[nf * 2]);
                }
            #pragma unroll
            for (int p = 0; p < NF / 2; p++) {
                int row = wn + p * 16 + brow;
                int sl = 8 + ks * 2 + ((lane >> 3) & 1);
                LDM4(&bb[p * 4], sw + row * 256 + ((sl ^ (row & 7)) << 4));
            }
            #pragma unroll
            for (int mf = 0; mf < MF; mf++)
                #pragma unroll
                for (int nf = 0; nf < NF; nf++)
                    MMA16816(cacc[mf][nf], ah[mf], &bb[nf * 2]);
        }
        __syncthreads();
    }

    const float* bias = (which == 0) ? qb : (which == 1) ? kb : vb;
    float* C = (which == 0) ? qo : (which == 1) ? ko : vo;
    const int cb0 = (blockIdx.x & 3) * NTILE;
    #pragma unroll
    for (int mf = 0; mf < MF; mf++) {
        int r0 = blockIdx.y * MTILE + wm + mf * 16 + (lane >> 2);
        #pragma unroll
        for (int nf = 0; nf < NF; nf++) {
            int col = cb0 + wn + nf * 8 + (lane & 3) * 2;
            float b0 = bias[col], b1 = bias[col + 1];
            *(float2*)&C[(size_t)r0 * 512 + col] =
                make_float2(cacc[mf][nf][0] + b0, cacc[mf][nf][1] + b1);
            *(float2*)&C[(size_t)(r0 + 8) * 512 + col] =
                make_float2(cacc[mf][nf][2] + b0, cacc[mf][nf][3] + b1);
        }
    }
    #undef LOAD_STAGE_Q
}

// ---------------- GRU chains (writes pair directly into emb arena) -----------
__global__ void __launch_bounds__(HIDD) gru_chain_kernel(const float* __restrict__ bhh) {
    int i0 = blockIdx.x;
    if (!g_is_head[i0]) return;
    int t = threadIdx.x;
    int d = g_chain_dst[i0];
    __shared__ float sh[HIDD];
    float h = g_mem[d * HIDD + t];
    sh[t] = h;
    int nz = __syncthreads_or(h != 0.0f);
    float b0 = bhh[t], b1 = bhh[HIDD + t], b2 = bhh[2 * HIDD + t];
    for (int i = i0; i < EE && g_chain_dst[i] == d; ++i) {
        int e = g_chain_edge[i];
        float gh0 = b0, gh1 = b1, gh2 = b2;
        if (nz) {
            #pragma unroll 4
            for (int kk = 0; kk < HIDD; ++kk) {
                float v = sh[kk];
                const float* wp = &g_WhhT[kk * G3H + t];
                gh0 += v * wp[0];
                gh1 += v * wp[HIDD];
                gh2 += v * wp[2 * HIDD];
            }
        }
        const float* gi = &g_gi[(size_t)e * G3H];
        float r  = 1.0f / (1.0f + expf(-(gi[t] + gh0)));
        float z  = 1.0f / (1.0f + expf(-(gi[HIDD + t] + gh1)));
        float nv = tanhf(gi[2 * HIDD + t] + r * gh2);
        float hn = (1.0f - z) * nv + z * h;
        __syncthreads();
        sh[t] = hn;
        h = hn;
        nz = __syncthreads_or(hn != 0.0f);
    }
    pair_store1(g_apair, (size_t)d * 1024 + ((4 + (t >> 6)) << 7) + (t & 63), h);
}

// ---------------- attention pieces ------------------------------------------
__device__ __forceinline__ void atomicMaxF(float* addr, float val) {
    int old = __float_as_int(*addr);
    while (__int_as_float(old) < val) {
        int assumed = old;
        old = atomicCAS((int*)addr, assumed, __float_as_int(val));
        if (old == assumed) break;
    }
}

__global__ void alpha_kernel(const float* __restrict__ qe, const float* __restrict__ ke,
                             const int* __restrict__ dst, int li) {
    int e = blockIdx.x * 8 + (threadIdx.x >> 5);
    int lane = threadIdx.x & 31;
    const float* q = qe + (size_t)e * 512;
    const float* k = ke + (size_t)e * 512;
    float s0 = 0.f, s1 = 0.f;
    #pragma unroll
    for (int c = lane; c < 256; c += 32) {
        s0 = fmaf(q[c], k[c], s0);
        s1 = fmaf(q[256 + c], k[256 + c], s1);
    }
    #pragma unroll
    for (int o = 16; o > 0; o >>= 1) {
        s0 += __shfl_xor_sync(0xffffffffu, s0, o);
        s1 += __shfl_xor_sync(0xffffffffu, s1, o);
    }
    if (lane == 0) {
        const float scale = 0.0625f;
        float a0 = s0 * scale, a1 = s1 * scale;
        int d = dst[e];
        g_alpha[e * 2] = a0; g_alpha[e * 2 + 1] = a1;
        atomicMaxF(&g_m[li][d * 2], a0);
        atomicMaxF(&g_m[li][d * 2 + 1], a1);
    }
}

__global__ void ex_kernel(const int* __restrict__ dst, int li) {
    int idx = blockIdx.x * 256 + threadIdx.x;
    if (idx < EE * 2) {
        int e = idx >> 1, h = idx & 1;
        int d = dst[e];
        float v = expf(g_alpha[idx] - g_m[li][d * 2 + h]);
        g_ex[idx] = v;
        atomicAdd(&g_denom[li][d * 2 + h], v);
    }
}

__global__ void scatter_kernel(const float* __restrict__ ve, const int* __restrict__ dst,
                               float* __restrict__ C, int li) {
    int e = blockIdx.x, c = threadIdx.x;
    int d = dst[e];
    float w0 = g_ex[e * 2]     / g_denom[li][d * 2]     * 0.5f;
    float w1 = g_ex[e * 2 + 1] / g_denom[li][d * 2 + 1] * 0.5f;
    atomicAdd(&C[(size_t)d * HIDD + c],
              w0 * ve[(size_t)e * 512 + c] + w1 * ve[(size_t)e * 512 + 256 + c]);
}

// ---------------- host ------------------------------------------------------
#define SM_MAIN 99328    // 1024 slack + 2 * (16KB A + 32KB W)  -> 2 CTAs/SM
#define SM_CLS  66560    // 1024 slack + 2 * (16KB A + 16KB W)

extern "C" void kernel_launch(void* const* d_in, const int* in_sizes, int n_in,
                              void* d_out, int out_size) {
    (void)in_sizes; (void)n_in; (void)out_size;
    const float* x     = (const float*)d_in[0];
    const int*   ei    = (const int*)  d_in[1];
    const float* et    = (const float*)d_in[2];
    const float* bih   = (const float*)d_in[6];
    const float* bhh   = (const float*)d_in[7];
    const float* featB = (const float*)d_in[11];
    const float* c0_qb = (const float*)d_in[13];
    const float* c0_kb = (const float*)d_in[15];
    const float* c0_vb = (const float*)d_in[17];
    const float* c0_sb = (const float*)d_in[19];
    const float* c1_qb = (const float*)d_in[21];
    const float* c1_kb = (const float*)d_in[23];
    const float* c1_vb = (const float*)d_in[25];
    const float* c1_sb = (const float*)d_in[27];
    const float* clsB  = (const float*)d_in[29];
    float* out = (float*)d_out;

    const int* src = ei;
    const int* dst = ei + EE;

    float *p_gi, *p_buf0, *p_buf1, *p_qe, *p_ke, *p_ve;
    __nv_bfloat16 *p_ap, *p_xp, *p_mp, *p_wp;
    cudaGetSymbolAddress((void**)&p_gi,   g_gi);
    cudaGetSymbolAddress((void**)&p_buf0, g_buf0);
    cudaGetSymbolAddress((void**)&p_buf1, g_buf1);
    cudaGetSymbolAddress((void**)&p_qe,   g_qe);
    cudaGetSymbolAddress((void**)&p_ke,   g_ke);
    cudaGetSymbolAddress((void**)&p_ve,   g_ve);
    cudaGetSymbolAddress((void**)&p_ap,   g_apair);
    cudaGetSymbolAddress((void**)&p_xp,   g_xpair);
    cudaGetSymbolAddress((void**)&p_mp,   g_mpair);
    cudaGetSymbolAddress((void**)&p_wp,   g_wpair);

    cudaFuncSetAttribute(prologue, cudaFuncAttributeMaxDynamicSharedMemorySize, 65536);
    cudaFuncSetAttribute(mma_gemm<64, 128, 0, 0>, cudaFuncAttributeMaxDynamicSharedMemorySize, SM_MAIN);
    cudaFuncSetAttribute(mma_gemm<64, 128, 1, 1>, cudaFuncAttributeMaxDynamicSharedMemorySize, SM_MAIN);
    cudaFuncSetAttribute(mma_gemm<64, 64, 0, 0>,  cudaFuncAttributeMaxDynamicSharedMemorySize, SM_CLS);
    cudaFuncSetAttribute(qkv_gemm, cudaFuncAttributeMaxDynamicSharedMemorySize, SM_MAIN);

    // 0) fused prologue
    PArgs pa;
    pa.x = x; pa.ei = ei; pa.et = et;
    pa.memin = (const float*)d_in[3];
    pa.Whh   = (const float*)d_in[5];
    pa.timeW = (const float*)d_in[8];
    pa.timeB = (const float*)d_in[9];
    pa.w[0]  = (const float*)d_in[4];
    pa.w[1]  = (const float*)d_in[10];
    pa.w[2]  = (const float*)d_in[12];
    pa.w[3]  = (const float*)d_in[14];
    pa.w[4]  = (const float*)d_in[16];
    pa.w[5]  = (const float*)d_in[18];
    pa.w[6]  = (const float*)d_in[20];
    pa.w[7]  = (const float*)d_in[22];
    pa.w[8]  = (const float*)d_in[24];
    pa.w[9]  = (const float*)d_in[26];
    pa.w[10] = (const float*)d_in[28];
    prologue<<<PRO_GRID, 256, 65536>>>(pa);

    const int NY = (NN + 63) / 64;   // 782

    // 1) gi = msg @ Wih^T + bih
    mma_gemm<64, 128, 0, 0><<<dim3(6, EE / 64), 256, SM_MAIN>>>(
        p_mp, 2 * KPADM, nullptr, EE, p_wp + OFF_WIH, 768 * 256, bih, p_gi, G3H, KPADM);

    // 2) GRU memory update; final h pair-written into emb upper half
    gru_chain_kernel<<<EE, HIDD>>>(bhh);

    // 3) feat GEMM writes relu'd pair into emb lower half
    mma_gemm<64, 128, 1, 1><<<dim3(2, NY), 256, SM_MAIN>>>(
        p_xp, 512, nullptr, NN, p_wp + OFF_FEAT, 256 * 256, featB, (void*)p_ap, 512, 256);

    // 4) layer 0
    qkv_gemm<<<dim3(12, EE / 64), 256, SM_MAIN>>>(
        p_ap, 1024, dst, src, p_wp + OFF_QKV0, 1536 * 256, c0_qb, c0_kb, c0_vb,
        p_qe, p_ke, p_ve, 512);
    mma_gemm<64, 128, 0, 0><<<dim3(2, NY), 256, SM_MAIN>>>(
        p_ap, 1024, nullptr, NN, p_wp + OFF_S0, 256 * 256, c0_sb, p_buf0, HIDD, 512);
    alpha_kernel<<<EE / 8, 256>>>(p_qe, p_ke, dst, 0);
    ex_kernel<<<(EE * 2 + 255) / 256, 256>>>(dst, 0);
    scatter_kernel<<<EE, HIDD>>>(p_ve, dst, p_buf0, 0);
    relu_cvt<<<(NN * 256 + 255) / 256, 256>>>(p_buf0, p_ap);

    // 5) layer 1
    qkv_gemm<<<dim3(12, EE / 64), 256, SM_MAIN>>>(
        p_ap, 512, dst, src, p_wp + OFF_QKV1, 1536 * 256, c1_qb, c1_kb, c1_vb,
        p_qe, p_ke, p_ve, 256);
    mma_gemm<64, 128, 0, 0><<<dim3(2, NY), 256, SM_MAIN>>>(
        p_ap, 512, nullptr, NN, p_wp + OFF_S1, 256 * 256, c1_sb, p_buf1, HIDD, 256);
    alpha_kernel<<<EE / 8, 256>>>(p_qe, p_ke, dst, 1);
    ex_kernel<<<(EE * 2 + 255) / 256, 256>>>(dst, 1);
    scatter_kernel<<<EE, HIDD>>>(p_ve, dst, p_buf1, 1);
    relu_cvt<<<(NN * 256 + 255) / 256, 256>>>(p_buf1, p_ap);

    // 6) classifier
    mma_gemm<64, 64, 0, 0><<<dim3(1, NY), 256, SM_CLS>>>(
        p_ap, 512, nullptr, NN, p_wp + OFF_CLS, 64 * 256, clsB, out, 64, 256);
}